// round 1
// baseline (speedup 1.0000x reference)
#include <cuda_runtime.h>
#include <math.h>

#define NNODE 4096
#define LL 500
#define LP 512
#define FEAT 800

// ---------------- scratch (device globals; no allocation) ----------------
__device__ float g_P1[NNODE * 2880];          // conv1+pool out [N,20,12,12]
__device__ float g_F[NNODE * FEAT];           // conv2+pool out [N,800]
__device__ float g_H[NNODE * LP];             // fc+relu features [N,500] (LD=512)
__device__ float g_sq[NNODE];                 // row norms of H
__device__ float g_D2[(size_t)NNODE * NNODE]; // pairwise squared distances
__device__ unsigned int g_hist[64];           // distance histogram
__device__ float g_thr2;                      // chosen threshold^2
__device__ float g_invS[NNODE];               // 1/max(deg,1)
__device__ float g_invC[NNODE];               // 1/(deg+1)
__device__ float g_AH[NNODE * LP];            // A @ H
__device__ float g_Zp[NNODE * LP];            // SAGE pre-act -> Z (in place)
__device__ float g_S[NNODE * 8];              // soft assignment [N,5]
__device__ float g_T[NNODE * 8];              // A @ S
__device__ float g_coar[5 * LP];              // S^T @ Z
__device__ float g_Ac[25];                    // S^T A S

// ---------------- small utility kernels ----------------
__global__ void k_zero() {
    if (threadIdx.x < 64) g_hist[threadIdx.x] = 0u;
}

// ---------------- conv1 (1->20, 5x5) + relu + maxpool2 ----------------
__global__ void __launch_bounds__(256) k_conv1(const float* __restrict__ x,
                                               const float* __restrict__ w,
                                               const float* __restrict__ b) {
    int n = blockIdx.x;
    __shared__ float simg[784];
    __shared__ float sw[500];
    __shared__ float sb[20];
    const float* xi = x + (size_t)n * 784;
    for (int i = threadIdx.x; i < 784; i += 256) simg[i] = xi[i];
    for (int i = threadIdx.x; i < 500; i += 256) sw[i] = w[i];
    if (threadIdx.x < 20) sb[threadIdx.x] = b[threadIdx.x];
    __syncthreads();
    for (int o = threadIdx.x; o < 20 * 144; o += 256) {
        int c = o / 144, p = o % 144, py = p / 12, px = p % 12;
        float mx = -1e30f;
        const float* wc = sw + c * 25;
#pragma unroll
        for (int dy = 0; dy < 2; dy++)
#pragma unroll
            for (int dx = 0; dx < 2; dx++) {
                int y = 2 * py + dy, xx = 2 * px + dx;
                float acc = sb[c];
#pragma unroll
                for (int ky = 0; ky < 5; ky++)
#pragma unroll
                    for (int kx = 0; kx < 5; kx++)
                        acc += simg[(y + ky) * 28 + xx + kx] * wc[ky * 5 + kx];
                mx = fmaxf(mx, acc);
            }
        g_P1[(size_t)n * 2880 + o] = fmaxf(mx, 0.f);
    }
}

// ---------------- conv2 (20->50, 5x5) + relu + maxpool2 ----------------
__global__ void __launch_bounds__(256) k_conv2(const float* __restrict__ w,
                                               const float* __restrict__ b) {
    int n = blockIdx.x;
    __shared__ float sin[2880];
    for (int i = threadIdx.x; i < 2880; i += 256) sin[i] = g_P1[(size_t)n * 2880 + i];
    __syncthreads();
    for (int o = threadIdx.x; o < 800; o += 256) {
        int c = o / 16, p = o % 16, py = p / 4, px = p % 4;
        float mx = -1e30f;
        const float* wc = w + c * 500;
        float bc = b[c];
        for (int dy = 0; dy < 2; dy++)
            for (int dx = 0; dx < 2; dx++) {
                int y = 2 * py + dy, xx = 2 * px + dx;
                float acc = bc;
                for (int ic = 0; ic < 20; ic++) {
                    const float* wci = wc + ic * 25;
                    const float* si = sin + ic * 144 + y * 12 + xx;
#pragma unroll
                    for (int ky = 0; ky < 5; ky++)
#pragma unroll
                        for (int kx = 0; kx < 5; kx++)
                            acc += si[ky * 12 + kx] * __ldg(wci + ky * 5 + kx);
                }
                mx = fmaxf(mx, acc);
            }
        g_F[(size_t)n * 800 + o] = fmaxf(mx, 0.f);
    }
}

// ---------------- generic NT SGEMM: C = act(rowscale(A) @ B^T + bias [+ C]) ----------------
// A: MxK row-major (lda), B: NcxK row-major (ldb), C: MxNc (ldc)
__global__ void __launch_bounds__(256) k_gemm_nt(
    const float* __restrict__ A, int lda, const float* __restrict__ B, int ldb,
    float* __restrict__ C, int ldc, int M, int Nc, int K,
    const float* __restrict__ bias, const float* __restrict__ rowscale,
    int act, int beta) {
    __shared__ float As[8][128];
    __shared__ float Bs[8][128];
    int tid = threadIdx.x;
    int tx = tid & 15, ty = tid >> 4;
    int brow = blockIdx.y * 128, bcol = blockIdx.x * 128;
    int arow = tid >> 1, apos = (tid & 1) * 4;
    int gr = brow + arow, gc = bcol + arow;
    float rs = 1.f;
    if (rowscale && gr < M) rs = rowscale[gr];
    float acc[8][8];
#pragma unroll
    for (int i = 0; i < 8; i++)
#pragma unroll
        for (int j = 0; j < 8; j++) acc[i][j] = 0.f;
    for (int kt = 0; kt < K; kt += 8) {
#pragma unroll
        for (int j = 0; j < 4; j++) {
            int k = kt + apos + j;
            As[apos + j][arow] = (gr < M && k < K) ? A[(size_t)gr * lda + k] * rs : 0.f;
            Bs[apos + j][arow] = (gc < Nc && k < K) ? B[(size_t)gc * ldb + k] : 0.f;
        }
        __syncthreads();
#pragma unroll
        for (int kk = 0; kk < 8; kk++) {
            float ra[8], rb[8];
#pragma unroll
            for (int i = 0; i < 8; i++) ra[i] = As[kk][ty + 16 * i];
#pragma unroll
            for (int j = 0; j < 8; j++) rb[j] = Bs[kk][tx + 16 * j];
#pragma unroll
            for (int i = 0; i < 8; i++)
#pragma unroll
                for (int j = 0; j < 8; j++) acc[i][j] += ra[i] * rb[j];
        }
        __syncthreads();
    }
#pragma unroll
    for (int i = 0; i < 8; i++)
#pragma unroll
        for (int j = 0; j < 8; j++) {
            int r = brow + ty + 16 * i, c = bcol + tx + 16 * j;
            if (r < M && c < Nc) {
                float v = acc[i][j];
                if (beta) v += C[(size_t)r * ldc + c];
                if (bias) v += bias[c];
                if (act == 1) v = fmaxf(v, 0.f);
                else if (act == 2) v = (v >= 0.f) ? v : 0.01f * v;
                C[(size_t)r * ldc + c] = v;
            }
        }
}

// ---------------- row squared norms of H ----------------
__global__ void k_rownorm() {
    int i = blockIdx.x;
    __shared__ float red[128];
    float s = 0.f;
    for (int k = threadIdx.x; k < LL; k += 128) {
        float v = g_H[(size_t)i * LP + k];
        s += v * v;
    }
    red[threadIdx.x] = s;
    __syncthreads();
    for (int o = 64; o > 0; o >>= 1) {
        if (threadIdx.x < o) red[threadIdx.x] += red[threadIdx.x + o];
        __syncthreads();
    }
    if (threadIdx.x == 0) g_sq[i] = red[0];
}

// ---------------- Gram -> D2 + histogram ----------------
__global__ void __launch_bounds__(256) k_gram() {
    __shared__ float As[8][128];
    __shared__ float Bs[8][128];
    __shared__ unsigned int shist[64];
    int tid = threadIdx.x;
    if (tid < 64) shist[tid] = 0u;
    int tx = tid & 15, ty = tid >> 4;
    int brow = blockIdx.y * 128, bcol = blockIdx.x * 128;
    int arow = tid >> 1, apos = (tid & 1) * 4;
    int gr = brow + arow, gc = bcol + arow;
    float acc[8][8];
#pragma unroll
    for (int i = 0; i < 8; i++)
#pragma unroll
        for (int j = 0; j < 8; j++) acc[i][j] = 0.f;
    for (int kt = 0; kt < LL; kt += 8) {
#pragma unroll
        for (int j = 0; j < 4; j++) {
            int k = kt + apos + j;
            As[apos + j][arow] = (k < LL) ? g_H[(size_t)gr * LP + k] : 0.f;
            Bs[apos + j][arow] = (k < LL) ? g_H[(size_t)gc * LP + k] : 0.f;
        }
        __syncthreads();
#pragma unroll
        for (int kk = 0; kk < 8; kk++) {
            float ra[8], rb[8];
#pragma unroll
            for (int i = 0; i < 8; i++) ra[i] = As[kk][ty + 16 * i];
#pragma unroll
            for (int j = 0; j < 8; j++) rb[j] = Bs[kk][tx + 16 * j];
#pragma unroll
            for (int i = 0; i < 8; i++)
#pragma unroll
                for (int j = 0; j < 8; j++) acc[i][j] += ra[i] * rb[j];
        }
        __syncthreads();
    }
    float sqr[8], sqc[8];
#pragma unroll
    for (int i = 0; i < 8; i++) sqr[i] = g_sq[brow + ty + 16 * i];
#pragma unroll
    for (int j = 0; j < 8; j++) sqc[j] = g_sq[bcol + tx + 16 * j];
#pragma unroll
    for (int i = 0; i < 8; i++)
#pragma unroll
        for (int j = 0; j < 8; j++) {
            int r = brow + ty + 16 * i, c = bcol + tx + 16 * j;
            float d2 = fmaxf(sqr[i] - 2.f * acc[i][j] + sqc[j], 0.f);
            g_D2[(size_t)r * NNODE + c] = d2;
            int bin;
            if (r == c) bin = 64;                // excluded (diagonal)
            else if (d2 < 6.25f) bin = 0;        // below thr=2.5
            else {
                float d = sqrtf(d2);
                bin = 1 + (int)((d - 2.5f) * 2.0f);
                if (bin > 63) bin = 63;
                // exact correction vs d2 < (2.5+0.5*bin)^2 (thresholds exact in fp32)
                float t = 2.5f + 0.5f * (float)bin;
                if (!(d2 < t * t)) { bin++; if (bin > 63) bin = 63; }
                else if (bin > 1) {
                    float tm = t - 0.5f;
                    if (d2 < tm * tm) bin--;
                }
            }
            unsigned msk = __match_any_sync(0xffffffffu, bin);
            int leader = __ffs(msk) - 1;
            if ((int)(tid & 31) == leader && bin < 64)
                atomicAdd(&shist[bin], (unsigned)__popc(msk));
        }
    __syncthreads();
    if (tid < 64 && shist[tid]) atomicAdd(&g_hist[tid], shist[tid]);
}

// ---------------- pick threshold from histogram ----------------
__global__ void k_thr() {
    unsigned int cum = 0;
    int k = 0;
    for (k = 0; k < 64; k++) {
        cum += g_hist[k];
        if ((float)cum >= 409.6f) break;   // min_edges = 0.1 * 4096
    }
    if (k > 63) k = 63;
    float t = 2.5f + 0.5f * (float)k;
    g_thr2 = t * t;
}

// ---------------- per-node degree ----------------
__global__ void k_deg() {
    __shared__ int red[256];
    int i = blockIdx.x;
    float thr2 = g_thr2;
    const float* row = g_D2 + (size_t)i * NNODE;
    int cnt = 0;
    for (int j = threadIdx.x; j < NNODE; j += 256)
        cnt += (row[j] < thr2 && j != i) ? 1 : 0;
    red[threadIdx.x] = cnt;
    __syncthreads();
    for (int o = 128; o > 0; o >>= 1) {
        if (threadIdx.x < o) red[threadIdx.x] += red[threadIdx.x + o];
        __syncthreads();
    }
    if (threadIdx.x == 0) {
        float d = (float)red[0];
        g_invS[i] = 1.f / fmaxf(d, 1.f);
        g_invC[i] = 1.f / (d + 1.f);
    }
}

// ---------------- AH = mask(D2) @ H  (NN GEMM, mask on the fly) ----------------
__global__ void __launch_bounds__(256) k_ah() {
    __shared__ float As[8][128];
    __shared__ float Bs[8][128];
    int tid = threadIdx.x;
    int tx = tid & 15, ty = tid >> 4;
    int brow = blockIdx.y * 128, bcol = blockIdx.x * 128;
    int arow = tid >> 1, apos = (tid & 1) * 4;
    int gr = brow + arow;
    int lcol = (tid & 31) * 4, lkk = tid >> 5;
    int gcb = bcol + lcol;
    float thr2 = g_thr2;
    float acc[8][8];
#pragma unroll
    for (int i = 0; i < 8; i++)
#pragma unroll
        for (int j = 0; j < 8; j++) acc[i][j] = 0.f;
    for (int kt = 0; kt < NNODE; kt += 8) {
#pragma unroll
        for (int j = 0; j < 4; j++) {
            int k = kt + apos + j;
            float d2 = g_D2[(size_t)gr * NNODE + k];
            As[apos + j][arow] = (d2 < thr2 && k != gr) ? 1.f : 0.f;
        }
#pragma unroll
        for (int j = 0; j < 4; j++) {
            int c = gcb + j;
            Bs[lkk][lcol + j] = (c < LL) ? g_H[(size_t)(kt + lkk) * LP + c] : 0.f;
        }
        __syncthreads();
#pragma unroll
        for (int kk = 0; kk < 8; kk++) {
            float ra[8], rb[8];
#pragma unroll
            for (int i = 0; i < 8; i++) ra[i] = As[kk][ty + 16 * i];
#pragma unroll
            for (int j = 0; j < 8; j++) rb[j] = Bs[kk][tx + 16 * j];
#pragma unroll
            for (int i = 0; i < 8; i++)
#pragma unroll
                for (int j = 0; j < 8; j++) acc[i][j] += ra[i] * rb[j];
        }
        __syncthreads();
    }
#pragma unroll
    for (int i = 0; i < 8; i++)
#pragma unroll
        for (int j = 0; j < 8; j++) {
            int r = brow + ty + 16 * i, c = bcol + tx + 16 * j;
            if (c < LL) g_AH[(size_t)r * LP + c] = acc[i][j];
        }
}

// ---------------- BatchNorm (training stats) over N rows, in place on g_Zp ----------------
__global__ void k_bn(const float* __restrict__ gw, const float* __restrict__ gb) {
    int f = blockIdx.x;
    __shared__ float red[256];
    float s = 0.f;
    for (int i = threadIdx.x; i < NNODE; i += 256) s += g_Zp[(size_t)i * LP + f];
    red[threadIdx.x] = s;
    __syncthreads();
    for (int o = 128; o > 0; o >>= 1) {
        if (threadIdx.x < o) red[threadIdx.x] += red[threadIdx.x + o];
        __syncthreads();
    }
    float m = red[0] / (float)NNODE;
    __syncthreads();
    float s2 = 0.f;
    for (int i = threadIdx.x; i < NNODE; i += 256) {
        float d = g_Zp[(size_t)i * LP + f] - m;
        s2 += d * d;
    }
    red[threadIdx.x] = s2;
    __syncthreads();
    for (int o = 128; o > 0; o >>= 1) {
        if (threadIdx.x < o) red[threadIdx.x] += red[threadIdx.x + o];
        __syncthreads();
    }
    float var = red[0] / (float)NNODE;
    float sd = sqrtf(var + 1e-5f);
    float gf = gw[f], bf = gb[f];
    __syncthreads();
    for (int i = threadIdx.x; i < NNODE; i += 256) {
        float v = g_Zp[(size_t)i * LP + f];
        g_Zp[(size_t)i * LP + f] = (v - m) / sd * gf + bf;
    }
}

// ---------------- ClusterGCN assignment logits + softmax -> S ----------------
__global__ void k_cluster(const float* __restrict__ wout, const float* __restrict__ bout,
                          const float* __restrict__ wroot) {
    int warp = threadIdx.x >> 5, lane = threadIdx.x & 31;
    int i = blockIdx.x * 4 + warp;
    float invc = g_invC[i];
    float lg[5];
#pragma unroll
    for (int c = 0; c < 5; c++) {
        float acc = 0.f;
        for (int k = lane; k < LL; k += 32) {
            float hv = g_H[(size_t)i * LP + k];
            float ag = (g_AH[(size_t)i * LP + k] + hv) * invc;
            acc += ag * wout[c * LL + k] + hv * wroot[c * LL + k];
        }
#pragma unroll
        for (int o = 16; o > 0; o >>= 1) acc += __shfl_down_sync(0xffffffffu, acc, o);
        acc = __shfl_sync(0xffffffffu, acc, 0);
        lg[c] = acc + bout[c];
    }
    if (lane == 0) {
        float m = lg[0];
#pragma unroll
        for (int c = 1; c < 5; c++) m = fmaxf(m, lg[c]);
        float e[5], s = 0.f;
#pragma unroll
        for (int c = 0; c < 5; c++) { e[c] = expf(lg[c] - m); s += e[c]; }
#pragma unroll
        for (int c = 0; c < 5; c++) g_S[(size_t)i * 8 + c] = e[c] / s;
    }
}

// ---------------- T = mask(D2) @ S ----------------
__global__ void k_as() {
    __shared__ float red[256];
    int i = blockIdx.x;
    float thr2 = g_thr2;
    const float* row = g_D2 + (size_t)i * NNODE;
    float acc[5] = {0.f, 0.f, 0.f, 0.f, 0.f};
    for (int j = threadIdx.x; j < NNODE; j += 256) {
        if (row[j] < thr2 && j != i) {
#pragma unroll
            for (int c = 0; c < 5; c++) acc[c] += g_S[(size_t)j * 8 + c];
        }
    }
#pragma unroll
    for (int c = 0; c < 5; c++) {
        red[threadIdx.x] = acc[c];
        __syncthreads();
        for (int o = 128; o > 0; o >>= 1) {
            if (threadIdx.x < o) red[threadIdx.x] += red[threadIdx.x + o];
            __syncthreads();
        }
        if (threadIdx.x == 0) g_T[(size_t)i * 8 + c] = red[0];
        __syncthreads();
    }
}

// ---------------- coar = S^T @ Z ----------------
__global__ void k_coar() {
    int f = blockIdx.x * 128 + threadIdx.x;
    if (f >= LL) return;
    float acc[5] = {0.f, 0.f, 0.f, 0.f, 0.f};
    for (int n = 0; n < NNODE; n++) {
        float z = g_Zp[(size_t)n * LP + f];
#pragma unroll
        for (int c = 0; c < 5; c++) acc[c] += g_S[(size_t)n * 8 + c] * z;
    }
#pragma unroll
    for (int c = 0; c < 5; c++) g_coar[c * LP + f] = acc[c];
}

// ---------------- Ac = S^T @ T ----------------
__global__ void k_ac() {
    __shared__ float red[256];
    int tid = threadIdx.x;
    float acc[25];
#pragma unroll
    for (int q = 0; q < 25; q++) acc[q] = 0.f;
    for (int n = tid; n < NNODE; n += 256) {
        float sv[5], tv[5];
#pragma unroll
        for (int c = 0; c < 5; c++) { sv[c] = g_S[(size_t)n * 8 + c]; tv[c] = g_T[(size_t)n * 8 + c]; }
#pragma unroll
        for (int a = 0; a < 5; a++)
#pragma unroll
            for (int b = 0; b < 5; b++) acc[a * 5 + b] += sv[a] * tv[b];
    }
#pragma unroll
    for (int q = 0; q < 25; q++) {
        red[tid] = acc[q];
        __syncthreads();
        for (int o = 128; o > 0; o >>= 1) {
            if (tid < o) red[tid] += red[tid + o];
            __syncthreads();
        }
        if (tid == 0) g_Ac[q] = red[0];
        __syncthreads();
    }
}

// ---------------- final: coarse SAGE + BN + pool + MLP + softmax ----------------
__global__ void __launch_bounds__(512) k_final(
    const float* __restrict__ wl, const float* __restrict__ bl, const float* __restrict__ wr,
    const float* __restrict__ bng, const float* __restrict__ bnb,
    const float* __restrict__ l1w, const float* __restrict__ l1b,
    const float* __restrict__ l2w, const float* __restrict__ l2b,
    float* __restrict__ out, int out_size) {
    __shared__ float Mc[25];
    __shared__ float invdc[5];
    __shared__ float neigh[5 * 500];   // reused for pooled
    __shared__ float pre[5 * 500];
    __shared__ float h1[5 * 250];
    __shared__ float lg[5];
    int tid = threadIdx.x;
    if (tid == 0) {
        float mean = 0.f;
        for (int q = 0; q < 25; q++) mean += g_Ac[q];
        mean *= (1.f / 25.f);
        for (int q = 0; q < 25; q++)
            Mc[q] = (g_Ac[q] >= mean && g_Ac[q] > 0.f) ? 1.f : 0.f;
        for (int i = 0; i < 5; i++) {
            float d = 0.f;
            for (int j = 0; j < 5; j++) d += Mc[i * 5 + j];
            invdc[i] = 1.f / fmaxf(d, 1.f);
        }
    }
    __syncthreads();
    // neigh = (Mc @ coar) / deg
    for (int idx = tid; idx < 2500; idx += 512) {
        int i = idx / 500, f = idx % 500;
        float a = 0.f;
#pragma unroll
        for (int j = 0; j < 5; j++) a += Mc[i * 5 + j] * g_coar[j * LP + f];
        neigh[idx] = a * invdc[i];
    }
    __syncthreads();
    // SAGE: pre = leaky(neigh@wl^T + bl + coar@wr^T)
    for (int idx = tid; idx < 2500; idx += 512) {
        int i = idx / 500, f = idx % 500;
        float acc = bl[f];
        const float* wlr = wl + f * 500;
        const float* wrr = wr + f * 500;
        for (int k = 0; k < 500; k++)
            acc += neigh[i * 500 + k] * wlr[k] + g_coar[i * LP + k] * wrr[k];
        pre[idx] = (acc >= 0.f) ? acc : 0.01f * acc;
    }
    __syncthreads();
    // BN over 5 rows per feature
    for (int f = tid; f < 500; f += 512) {
        float m = 0.f;
#pragma unroll
        for (int i = 0; i < 5; i++) m += pre[i * 500 + f];
        m *= 0.2f;
        float v = 0.f;
#pragma unroll
        for (int i = 0; i < 5; i++) { float d = pre[i * 500 + f] - m; v += d * d; }
        v *= 0.2f;
        float sd = sqrtf(v + 1e-5f);
        float gf = bng[f], bf = bnb[f];
#pragma unroll
        for (int i = 0; i < 5; i++)
            pre[i * 500 + f] = (pre[i * 500 + f] - m) / sd * gf + bf;
    }
    __syncthreads();
    // pooled = max over neighbors incl self (reuse neigh[])
    for (int idx = tid; idx < 2500; idx += 512) {
        int i = idx / 500, f = idx % 500;
        float mx = -1e30f;
#pragma unroll
        for (int j = 0; j < 5; j++)
            if (Mc[i * 5 + j] > 0.f || j == i) mx = fmaxf(mx, pre[j * 500 + f]);
        neigh[idx] = mx;
    }
    __syncthreads();
    // h1 = leaky(pooled@l1w^T + l1b)
    for (int idx = tid; idx < 1250; idx += 512) {
        int i = idx / 250, o = idx % 250;
        float acc = l1b[o];
        const float* w = l1w + o * 500;
        for (int k = 0; k < 500; k++) acc += neigh[i * 500 + k] * w[k];
        h1[idx] = (acc >= 0.f) ? acc : 0.01f * acc;
    }
    __syncthreads();
    if (tid < 5) {
        float acc = l2b[0];
        for (int k = 0; k < 250; k++) acc += h1[tid * 250 + k] * l2w[k];
        lg[tid] = (acc >= 0.f) ? acc : 0.01f * acc;
    }
    __syncthreads();
    if (tid == 0) {
        float m = lg[0];
        for (int i = 1; i < 5; i++) m = fmaxf(m, lg[i]);
        float e[5], s = 0.f;
        for (int i = 0; i < 5; i++) { e[i] = expf(lg[i] - m); s += e[i]; }
        float p = 0.f;
        for (int i = 0; i < 5; i++) p = fmaxf(p, e[i] / s);
        out[0] = p;
        if (out_size > 1) out[1] = (p >= 0.5f) ? 1.f : 0.f;
    }
}

// ---------------- host launcher ----------------
static float* symaddr(const void* sym) {
    void* p = nullptr;
    cudaGetSymbolAddress(&p, sym);
    return (float*)p;
}

extern "C" void kernel_launch(void* const* d_in, const int* in_sizes, int n_in,
                              void* d_out, int out_size) {
    const float* x    = (const float*)d_in[0];
    const float* c1w  = (const float*)d_in[1];
    const float* c1b  = (const float*)d_in[2];
    const float* c2w  = (const float*)d_in[3];
    const float* c2b  = (const float*)d_in[4];
    const float* fcw  = (const float*)d_in[5];
    const float* fcb  = (const float*)d_in[6];
    const float* swl  = (const float*)d_in[7];
    const float* sbl  = (const float*)d_in[8];
    const float* swr  = (const float*)d_in[9];
    const float* bng  = (const float*)d_in[10];
    const float* bnb  = (const float*)d_in[11];
    const float* cgwo = (const float*)d_in[12];
    const float* cgbo = (const float*)d_in[13];
    const float* cgwr = (const float*)d_in[14];
    const float* l1w  = (const float*)d_in[15];
    const float* l1b  = (const float*)d_in[16];
    const float* l2w  = (const float*)d_in[17];
    const float* l2b  = (const float*)d_in[18];
    float* out = (float*)d_out;

    float* pF  = symaddr(g_F);
    float* pH  = symaddr(g_H);
    float* pAH = symaddr(g_AH);
    float* pZp = symaddr(g_Zp);
    float* pIS = symaddr(g_invS);

    k_zero<<<1, 64>>>();
    k_conv1<<<NNODE, 256>>>(x, c1w, c1b);
    k_conv2<<<NNODE, 256>>>(c2w, c2b);
    // fc + relu: H = relu(F @ fcw^T + fcb)
    {
        dim3 g((LL + 127) / 128, NNODE / 128);
        k_gemm_nt<<<g, 256>>>(pF, FEAT, fcw, FEAT, pH, LP, NNODE, LL, FEAT,
                              fcb, nullptr, 1, 0);
    }
    k_rownorm<<<NNODE, 128>>>();
    {
        dim3 g(NNODE / 128, NNODE / 128);
        k_gram<<<g, 256>>>();
    }
    k_thr<<<1, 1>>>();
    k_deg<<<NNODE, 256>>>();
    {
        dim3 g((LL + 127) / 128, NNODE / 128);
        k_ah<<<g, 256>>>();
    }
    // SAGE: Zp = leaky( (AH/deg)@wl^T + bl + H@wr^T )
    {
        dim3 g((LL + 127) / 128, NNODE / 128);
        k_gemm_nt<<<g, 256>>>(pAH, LP, swl, LL, pZp, LP, NNODE, LL, LL,
                              sbl, pIS, 0, 0);
        k_gemm_nt<<<g, 256>>>(pH, LP, swr, LL, pZp, LP, NNODE, LL, LL,
                              nullptr, nullptr, 2, 1);
    }
    k_bn<<<LL, 256>>>(bng, bnb);
    k_cluster<<<NNODE / 4, 128>>>(cgwo, cgbo, cgwr);
    k_as<<<NNODE, 256>>>();
    k_coar<<<(LL + 127) / 128, 128>>>();
    k_ac<<<1, 256>>>();
    k_final<<<1, 512>>>(swl, sbl, swr, bng, bnb, l1w, l1b, l2w, l2b, out, out_size);
}

// round 2
// speedup vs baseline: 1.9726x; 1.9726x over previous
#include <cuda_runtime.h>
#include <math.h>

#define NNODE 4096
#define LL 500
#define LP 512
#define FEAT 800

typedef unsigned long long ull;

// ---------------- scratch (device globals; no allocation) ----------------
__device__ float g_P1[NNODE * 2880];          // conv1+pool out [N,20,12,12]
__device__ float g_F[NNODE * FEAT];           // conv2+pool out [N,800]
__device__ float g_H[NNODE * LP];             // fc+relu features [N,500] (LD=512, pads zero)
__device__ float g_sq[NNODE];                 // row norms of H
__device__ float g_D2[(size_t)NNODE * NNODE]; // pairwise squared distances
__device__ unsigned int g_hist[64];           // distance histogram
__device__ float g_thr2;                      // chosen threshold^2
__device__ float g_invS[NNODE];               // 1/max(deg,1)
__device__ float g_invC[NNODE];               // 1/(deg+1)
__device__ float g_AH[NNODE * LP];            // A @ H
__device__ float g_Zp[NNODE * LP];            // SAGE pre-act -> Z (in place)
__device__ float g_S[NNODE * 8];              // soft assignment [N,5]
__device__ float g_T[NNODE * 8];              // A @ S
__device__ float g_coar[5 * LP];              // S^T @ Z
__device__ float g_Ac[25];                    // S^T A S
__device__ float g_bnp[64 * 512];             // BN partial sums
__device__ float g_bnp2[64 * 512];
__device__ float g_bnm[512];
__device__ float g_bni[512];

__global__ void k_zero() {
    if (threadIdx.x < 64) g_hist[threadIdx.x] = 0u;
}

// ---------------- packed fp32x2 fma helpers ----------------
__device__ __forceinline__ void fma2(ull &d, ull a, ull b) {
    asm("fma.rn.f32x2 %0, %1, %2, %0;" : "+l"(d) : "l"(a), "l"(b));
}
__device__ __forceinline__ float2 up2(ull v) {
    float2 r;
    r.x = __uint_as_float((unsigned)v);
    r.y = __uint_as_float((unsigned)(v >> 32));
    return r;
}

// shared compute core: 128x128 tile, BK=16, A duplicated, acc 8 rows x 4 col-pairs
__device__ __forceinline__ void gemm_core(const float (*As)[256], const float (*Bs)[128],
                                          int tx, int ty, ull acc[8][4]) {
#pragma unroll
    for (int kk = 0; kk < 16; kk++) {
        ulonglong2 A01 = *(const ulonglong2*)&As[kk][8 * ty];
        ulonglong2 A23 = *(const ulonglong2*)&As[kk][8 * ty + 4];
        ulonglong2 A45 = *(const ulonglong2*)&As[kk][8 * ty + 128];
        ulonglong2 A67 = *(const ulonglong2*)&As[kk][8 * ty + 132];
        ulonglong2 B01 = *(const ulonglong2*)&Bs[kk][4 * tx];
        ulonglong2 B23 = *(const ulonglong2*)&Bs[kk][4 * tx + 64];
        ull av[8] = {A01.x, A01.y, A23.x, A23.y, A45.x, A45.y, A67.x, A67.y};
        ull bv[4] = {B01.x, B01.y, B23.x, B23.y};
#pragma unroll
        for (int i = 0; i < 8; i++)
#pragma unroll
            for (int j = 0; j < 4; j++) fma2(acc[i][j], av[i], bv[j]);
    }
}

// ---------------- conv1 (1->20,5x5)+relu+pool, register-blocked ----------------
__global__ void __launch_bounds__(768) k_conv1(const float* __restrict__ x,
                                               const float* __restrict__ w,
                                               const float* __restrict__ b) {
    int n = blockIdx.x;
    __shared__ float simg[784];
    __shared__ float sw[500];
    const float* xi = x + (size_t)n * 784;
    for (int i = threadIdx.x; i < 784; i += 768) simg[i] = xi[i];
    for (int i = threadIdx.x; i < 500; i += 768) sw[i] = w[i];
    __syncthreads();
    int t = threadIdx.x;
    if (t >= 720) return;
    int c = t / 36;
    int reg = t % 36;
    int ry = (reg / 6) * 2, rx = (reg % 6) * 2;   // pooled 2x2 block base in 12x12
    float wreg[25];
#pragma unroll
    for (int u = 0; u < 25; u++) wreg[u] = sw[c * 25 + u];
    float a[4][4];
#pragma unroll
    for (int i = 0; i < 4; i++)
#pragma unroll
        for (int j = 0; j < 4; j++) a[i][j] = 0.f;
#pragma unroll
    for (int rr = 0; rr < 8; rr++) {
        float row[8];
        const float* sp = simg + (2 * ry + rr) * 28 + 2 * rx;
#pragma unroll
        for (int u = 0; u < 8; u++) row[u] = sp[u];
        int iy0 = rr - 4 > 0 ? rr - 4 : 0;
        int iy1 = rr < 3 ? rr : 3;
#pragma unroll 4
        for (int iy = iy0; iy <= iy1; iy++) {
            int ky = rr - iy;
#pragma unroll
            for (int ix = 0; ix < 4; ix++)
#pragma unroll
                for (int kx = 0; kx < 5; kx++)
                    a[iy][ix] += row[ix + kx] * wreg[ky * 5 + kx];
        }
    }
    float bc = b[c];
#pragma unroll
    for (int py = 0; py < 2; py++)
#pragma unroll
        for (int px = 0; px < 2; px++) {
            float mx = fmaxf(fmaxf(a[2 * py][2 * px], a[2 * py][2 * px + 1]),
                             fmaxf(a[2 * py + 1][2 * px], a[2 * py + 1][2 * px + 1]));
            g_P1[(size_t)n * 2880 + c * 144 + (ry + py) * 12 + rx + px] = fmaxf(mx + bc, 0.f);
        }
}

// ---------------- conv2 (20->50,5x5)+relu+pool, register-blocked, 2 imgs/block ----------------
__global__ void __launch_bounds__(512) k_conv2(const float* __restrict__ w,
                                               const float* __restrict__ b) {
    int half = threadIdx.x >> 8;
    int t = threadIdx.x & 255;
    int n = blockIdx.x * 2 + half;
    __shared__ float sin[2][2880];
    for (int i = t; i < 2880; i += 256) sin[half][i] = g_P1[(size_t)n * 2880 + i];
    __syncthreads();
    if (t >= 200) return;
    int c = t >> 2, q = t & 3;
    int ry = (q >> 1) * 2, rx = (q & 1) * 2;   // pooled 2x2 block base in 4x4
    float a[4][4];
#pragma unroll
    for (int i = 0; i < 4; i++)
#pragma unroll
        for (int j = 0; j < 4; j++) a[i][j] = 0.f;
    const float* sp = sin[half];
    for (int ic = 0; ic < 20; ic++) {
        float wreg[25];
#pragma unroll
        for (int u = 0; u < 25; u++) wreg[u] = __ldg(&w[c * 500 + ic * 25 + u]);
#pragma unroll
        for (int rr = 0; rr < 8; rr++) {
            float row[8];
            const float* rp = sp + ic * 144 + (2 * ry + rr) * 12 + 2 * rx;
#pragma unroll
            for (int u = 0; u < 8; u++) row[u] = rp[u];
            int iy0 = rr - 4 > 0 ? rr - 4 : 0;
            int iy1 = rr < 3 ? rr : 3;
#pragma unroll 4
            for (int iy = iy0; iy <= iy1; iy++) {
                int ky = rr - iy;
#pragma unroll
                for (int ix = 0; ix < 4; ix++)
#pragma unroll
                    for (int kx = 0; kx < 5; kx++)
                        a[iy][ix] += row[ix + kx] * wreg[ky * 5 + kx];
            }
        }
    }
    float bc = b[c];
#pragma unroll
    for (int py = 0; py < 2; py++)
#pragma unroll
        for (int px = 0; px < 2; px++) {
            float mx = fmaxf(fmaxf(a[2 * py][2 * px], a[2 * py][2 * px + 1]),
                             fmaxf(a[2 * py + 1][2 * px], a[2 * py + 1][2 * px + 1]));
            g_F[(size_t)n * 800 + c * 16 + (ry + py) * 4 + rx + px] = fmaxf(mx + bc, 0.f);
        }
}

// ---------------- generic NT GEMM, fp32x2, 128x128x16, reg prefetch ----------------
__global__ void __launch_bounds__(256, 2) k_gemm(
    const float* __restrict__ A, int lda, const float* __restrict__ B, int ldb,
    float* __restrict__ C, int ldc, int Nc, int ncpad, int K,
    const float* __restrict__ bias, const float* __restrict__ rowscale,
    int act, int beta) {
    __shared__ float As[16][256];
    __shared__ float Bs[16][128];
    int tid = threadIdx.x, tx = tid & 15, ty = tid >> 4;
    int brow = blockIdx.y * 128, bcol = blockIdx.x * 128;
    int lrow = tid >> 1, lk = (tid & 1) * 8;
    int gr = brow + lrow, gc = bcol + lrow;
    float rs = rowscale ? rowscale[gr] : 1.f;
    int bok = (gc < Nc);
    ull acc[8][4];
#pragma unroll
    for (int i = 0; i < 8; i++)
#pragma unroll
        for (int j = 0; j < 4; j++) acc[i][j] = 0ULL;
    int ktiles = (K + 15) >> 4;
    const float4 z4 = make_float4(0.f, 0.f, 0.f, 0.f);
    float4 ra0, ra1, rb0, rb1;
    {
        int kb = lk;
        ra0 = (kb < K) ? *(const float4*)(A + (size_t)gr * lda + kb) : z4;
        ra1 = (kb + 4 < K) ? *(const float4*)(A + (size_t)gr * lda + kb + 4) : z4;
        rb0 = (bok && kb < K) ? *(const float4*)(B + (size_t)gc * ldb + kb) : z4;
        rb1 = (bok && kb + 4 < K) ? *(const float4*)(B + (size_t)gc * ldb + kb + 4) : z4;
    }
    for (int tt = 0; tt < ktiles; tt++) {
        __syncthreads();
        const float* pa0 = (const float*)&ra0;
        const float* pa1 = (const float*)&ra1;
        const float* pb0 = (const float*)&rb0;
        const float* pb1 = (const float*)&rb1;
#pragma unroll
        for (int j = 0; j < 4; j++) {
            float v0 = pa0[j] * rs, v1 = pa1[j] * rs;
            ((float2*)As[lk + j])[lrow] = make_float2(v0, v0);
            ((float2*)As[lk + 4 + j])[lrow] = make_float2(v1, v1);
            Bs[lk + j][lrow] = pb0[j];
            Bs[lk + 4 + j][lrow] = pb1[j];
        }
        __syncthreads();
        if (tt + 1 < ktiles) {
            int kb = (tt + 1) * 16 + lk;
            ra0 = (kb < K) ? *(const float4*)(A + (size_t)gr * lda + kb) : z4;
            ra1 = (kb + 4 < K) ? *(const float4*)(A + (size_t)gr * lda + kb + 4) : z4;
            rb0 = (bok && kb < K) ? *(const float4*)(B + (size_t)gc * ldb + kb) : z4;
            rb1 = (bok && kb + 4 < K) ? *(const float4*)(B + (size_t)gc * ldb + kb + 4) : z4;
        }
        gemm_core(As, Bs, tx, ty, acc);
    }
#pragma unroll
    for (int i = 0; i < 8; i++) {
        int r = brow + ty * 4 + (i & 3) + ((i >> 2) << 6);
#pragma unroll
        for (int j = 0; j < 4; j++) {
            int c = bcol + tx * 4 + ((j & 1) << 1) + ((j >> 1) << 6);
            float2 v = up2(acc[i][j]);
#pragma unroll
            for (int e = 0; e < 2; e++) {
                int cc = c + e;
                float vv = e ? v.y : v.x;
                if (cc < Nc) {
                    if (beta) vv += C[(size_t)r * ldc + cc];
                    if (bias) vv += bias[cc];
                    if (act == 1) vv = fmaxf(vv, 0.f);
                    else if (act == 2) vv = (vv >= 0.f) ? vv : 0.01f * vv;
                    C[(size_t)r * ldc + cc] = vv;
                } else if (cc < ncpad) {
                    C[(size_t)r * ldc + cc] = 0.f;
                }
            }
        }
    }
}

// ---------------- row squared norms of H ----------------
__global__ void k_rownorm() {
    int i = blockIdx.x;
    __shared__ float red[128];
    float s = 0.f;
    for (int k = threadIdx.x; k < LL; k += 128) {
        float v = g_H[(size_t)i * LP + k];
        s += v * v;
    }
    red[threadIdx.x] = s;
    __syncthreads();
    for (int o = 64; o > 0; o >>= 1) {
        if (threadIdx.x < o) red[threadIdx.x] += red[threadIdx.x + o];
        __syncthreads();
    }
    if (threadIdx.x == 0) g_sq[i] = red[0];
}

// ---------------- triangular Gram -> D2 + histogram (fp32x2 core) ----------------
__global__ void __launch_bounds__(256, 2) k_gram() {
    __shared__ float As[16][256];
    __shared__ float Bs[16][128];
    __shared__ unsigned int shist[64];
    int tid = threadIdx.x, tx = tid & 15, ty = tid >> 4;
    if (tid < 64) shist[tid] = 0u;
    int bid = blockIdx.x, by = 0, rem = bid;
    while (rem >= 32 - by) { rem -= 32 - by; by++; }
    int bx = by + rem;
    int brow = by * 128, bcol = bx * 128;
    int lrow = tid >> 1, lk = (tid & 1) * 8;
    int gr = brow + lrow, gc = bcol + lrow;
    ull acc[8][4];
#pragma unroll
    for (int i = 0; i < 8; i++)
#pragma unroll
        for (int j = 0; j < 4; j++) acc[i][j] = 0ULL;
    float4 ra0, ra1, rb0, rb1;
    ra0 = *(const float4*)(g_H + (size_t)gr * LP + lk);
    ra1 = *(const float4*)(g_H + (size_t)gr * LP + lk + 4);
    rb0 = *(const float4*)(g_H + (size_t)gc * LP + lk);
    rb1 = *(const float4*)(g_H + (size_t)gc * LP + lk + 4);
    for (int tt = 0; tt < 32; tt++) {
        __syncthreads();
        const float* pa0 = (const float*)&ra0;
        const float* pa1 = (const float*)&ra1;
        const float* pb0 = (const float*)&rb0;
        const float* pb1 = (const float*)&rb1;
#pragma unroll
        for (int j = 0; j < 4; j++) {
            ((float2*)As[lk + j])[lrow] = make_float2(pa0[j], pa0[j]);
            ((float2*)As[lk + 4 + j])[lrow] = make_float2(pa1[j], pa1[j]);
            Bs[lk + j][lrow] = pb0[j];
            Bs[lk + 4 + j][lrow] = pb1[j];
        }
        __syncthreads();
        if (tt + 1 < 32) {
            int kb = (tt + 1) * 16 + lk;
            ra0 = *(const float4*)(g_H + (size_t)gr * LP + kb);
            ra1 = *(const float4*)(g_H + (size_t)gr * LP + kb + 4);
            rb0 = *(const float4*)(g_H + (size_t)gc * LP + kb);
            rb1 = *(const float4*)(g_H + (size_t)gc * LP + kb + 4);
        }
        gemm_core(As, Bs, tx, ty, acc);
    }
    float sqr_[8], sqc_[8];
#pragma unroll
    for (int i = 0; i < 8; i++) sqr_[i] = g_sq[brow + ty * 4 + (i & 3) + ((i >> 2) << 6)];
#pragma unroll
    for (int j = 0; j < 8; j++) sqc_[j] = g_sq[bcol + tx * 4 + (j & 3) + ((j >> 2) << 6)];
    unsigned wgt = (bx == by) ? 1u : 2u;
#pragma unroll
    for (int i = 0; i < 8; i++) {
        int r = brow + ty * 4 + (i & 3) + ((i >> 2) << 6);
#pragma unroll
        for (int j = 0; j < 4; j++) {
            int cb = bcol + tx * 4 + ((j & 1) << 1) + ((j >> 1) << 6);
            float2 v = up2(acc[i][j]);
#pragma unroll
            for (int e = 0; e < 2; e++) {
                int c = cb + e;
                int ce = ((j >> 1) << 2) + ((j & 1) << 1) + e;
                float dot = e ? v.y : v.x;
                float d2 = fmaxf(sqr_[i] - 2.f * dot + sqc_[ce], 0.f);
                g_D2[(size_t)r * NNODE + c] = d2;
                if (bx != by) g_D2[(size_t)c * NNODE + r] = d2;
                int bin;
                if (r == c) bin = 64;
                else if (d2 < 6.25f) bin = 0;
                else {
                    float d = sqrtf(d2);
                    bin = 1 + (int)((d - 2.5f) * 2.0f);
                    if (bin > 63) bin = 63;
                    float t = 2.5f + 0.5f * (float)bin;
                    if (!(d2 < t * t)) { bin++; if (bin > 63) bin = 63; }
                    else if (bin > 1) {
                        float tm = t - 0.5f;
                        if (d2 < tm * tm) bin--;
                    }
                }
                unsigned msk = __match_any_sync(0xffffffffu, bin);
                int leader = __ffs(msk) - 1;
                if ((int)(tid & 31) == leader && bin < 64)
                    atomicAdd(&shist[bin], (unsigned)__popc(msk) * wgt);
            }
        }
    }
    __syncthreads();
    if (tid < 64 && shist[tid]) atomicAdd(&g_hist[tid], shist[tid]);
}

// ---------------- pick threshold ----------------
__global__ void k_thr() {
    unsigned int cum = 0;
    int k = 0;
    for (k = 0; k < 64; k++) {
        cum += g_hist[k];
        if ((float)cum >= 409.6f) break;
    }
    if (k > 63) k = 63;
    float t = 2.5f + 0.5f * (float)k;
    g_thr2 = t * t;
}

// ---------------- per-node degree ----------------
__global__ void k_deg() {
    __shared__ int red[256];
    int i = blockIdx.x;
    float thr2 = g_thr2;
    const float* row = g_D2 + (size_t)i * NNODE;
    int cnt = 0;
    for (int j = threadIdx.x; j < NNODE; j += 256)
        cnt += (row[j] < thr2 && j != i) ? 1 : 0;
    red[threadIdx.x] = cnt;
    __syncthreads();
    for (int o = 128; o > 0; o >>= 1) {
        if (threadIdx.x < o) red[threadIdx.x] += red[threadIdx.x + o];
        __syncthreads();
    }
    if (threadIdx.x == 0) {
        float d = (float)red[0];
        g_invS[i] = 1.f / fmaxf(d, 1.f);
        g_invC[i] = 1.f / (d + 1.f);
    }
}

// ---------------- AH = mask(D2) @ H  (NN, mask on the fly, fp32x2) ----------------
__global__ void __launch_bounds__(256, 2) k_ah() {
    __shared__ float As[16][256];
    __shared__ float Bs[16][128];
    int tid = threadIdx.x, tx = tid & 15, ty = tid >> 4;
    int brow = blockIdx.y * 128, bcol = blockIdx.x * 128;
    int lrow = tid >> 1, lk = (tid & 1) * 8;
    int gr = brow + lrow;
    int bk = tid >> 5, c4 = tid & 31;
    float thr2 = g_thr2;
    ull acc[8][4];
#pragma unroll
    for (int i = 0; i < 8; i++)
#pragma unroll
        for (int j = 0; j < 4; j++) acc[i][j] = 0ULL;
    float4 ra0, ra1, rb0, rb1;
    ra0 = *(const float4*)(g_D2 + (size_t)gr * NNODE + lk);
    ra1 = *(const float4*)(g_D2 + (size_t)gr * NNODE + lk + 4);
    rb0 = *(const float4*)(g_H + (size_t)bk * LP + bcol + c4 * 4);
    rb1 = *(const float4*)(g_H + (size_t)(bk + 8) * LP + bcol + c4 * 4);
    for (int tt = 0; tt < 256; tt++) {
        int kb = tt * 16;
        __syncthreads();
        const float* pa0 = (const float*)&ra0;
        const float* pa1 = (const float*)&ra1;
#pragma unroll
        for (int j = 0; j < 4; j++) {
            float m0 = (pa0[j] < thr2 && (kb + lk + j) != gr) ? 1.f : 0.f;
            float m1 = (pa1[j] < thr2 && (kb + lk + 4 + j) != gr) ? 1.f : 0.f;
            ((float2*)As[lk + j])[lrow] = make_float2(m0, m0);
            ((float2*)As[lk + 4 + j])[lrow] = make_float2(m1, m1);
        }
        *(float4*)&Bs[bk][c4 * 4] = rb0;
        *(float4*)&Bs[bk + 8][c4 * 4] = rb1;
        __syncthreads();
        if (tt + 1 < 256) {
            int kn = (tt + 1) * 16;
            ra0 = *(const float4*)(g_D2 + (size_t)gr * NNODE + kn + lk);
            ra1 = *(const float4*)(g_D2 + (size_t)gr * NNODE + kn + lk + 4);
            rb0 = *(const float4*)(g_H + (size_t)(kn + bk) * LP + bcol + c4 * 4);
            rb1 = *(const float4*)(g_H + (size_t)(kn + bk + 8) * LP + bcol + c4 * 4);
        }
        gemm_core(As, Bs, tx, ty, acc);
    }
#pragma unroll
    for (int i = 0; i < 8; i++) {
        int r = brow + ty * 4 + (i & 3) + ((i >> 2) << 6);
#pragma unroll
        for (int j = 0; j < 4; j++) {
            int c = bcol + tx * 4 + ((j & 1) << 1) + ((j >> 1) << 6);
            float2 v = up2(acc[i][j]);
            g_AH[(size_t)r * LP + c] = v.x;
            g_AH[(size_t)r * LP + c + 1] = v.y;
        }
    }
}

// ---------------- BatchNorm: coalesced partials -> finalize -> apply ----------------
__global__ void k_bnsum() {
    int f = threadIdx.x, b = blockIdx.x;
    float s = 0.f, s2 = 0.f;
    for (int n = b; n < NNODE; n += 64) {
        float v = g_Zp[(size_t)n * LP + f];
        s += v;
        s2 += v * v;
    }
    g_bnp[b * 512 + f] = s;
    g_bnp2[b * 512 + f] = s2;
}
__global__ void k_bnfin() {
    int f = threadIdx.x;
    float s = 0.f, s2 = 0.f;
    for (int b = 0; b < 64; b++) { s += g_bnp[b * 512 + f]; s2 += g_bnp2[b * 512 + f]; }
    float m = s / (float)NNODE;
    float var = fmaxf(s2 / (float)NNODE - m * m, 0.f);
    g_bnm[f] = m;
    g_bni[f] = 1.f / sqrtf(var + 1e-5f);
}
__global__ void k_bnapply(const float* __restrict__ gw, const float* __restrict__ gb) {
    int f = threadIdx.x, b = blockIdx.x;
    if (f >= LL) return;
    float m = g_bnm[f], inv = g_bni[f], gf = gw[f], bf = gb[f];
    for (int n = b; n < NNODE; n += 64) {
        float v = g_Zp[(size_t)n * LP + f];
        g_Zp[(size_t)n * LP + f] = (v - m) * inv * gf + bf;
    }
}

// ---------------- ClusterGCN assignment logits + softmax -> S ----------------
__global__ void k_cluster(const float* __restrict__ wout, const float* __restrict__ bout,
                          const float* __restrict__ wroot) {
    int warp = threadIdx.x >> 5, lane = threadIdx.x & 31;
    int i = blockIdx.x * 4 + warp;
    float invc = g_invC[i];
    float lg[5];
#pragma unroll
    for (int c = 0; c < 5; c++) {
        float acc = 0.f;
        for (int k = lane; k < LL; k += 32) {
            float hv = g_H[(size_t)i * LP + k];
            float ag = (g_AH[(size_t)i * LP + k] + hv) * invc;
            acc += ag * wout[c * LL + k] + hv * wroot[c * LL + k];
        }
#pragma unroll
        for (int o = 16; o > 0; o >>= 1) acc += __shfl_down_sync(0xffffffffu, acc, o);
        acc = __shfl_sync(0xffffffffu, acc, 0);
        lg[c] = acc + bout[c];
    }
    if (lane == 0) {
        float m = lg[0];
#pragma unroll
        for (int c = 1; c < 5; c++) m = fmaxf(m, lg[c]);
        float e[5], s = 0.f;
#pragma unroll
        for (int c = 0; c < 5; c++) { e[c] = expf(lg[c] - m); s += e[c]; }
#pragma unroll
        for (int c = 0; c < 5; c++) g_S[(size_t)i * 8 + c] = e[c] / s;
    }
}

// ---------------- T = mask(D2) @ S ----------------
__global__ void k_as() {
    int i = blockIdx.x;
    int tid = threadIdx.x, lane = tid & 31, warp = tid >> 5;
    float thr2 = g_thr2;
    const float* row = g_D2 + (size_t)i * NNODE;
    float acc[5] = {0.f, 0.f, 0.f, 0.f, 0.f};
    for (int j = tid; j < NNODE; j += 256) {
        if (row[j] < thr2 && j != i) {
            const float* s = g_S + (size_t)j * 8;
#pragma unroll
            for (int c = 0; c < 5; c++) acc[c] += s[c];
        }
    }
#pragma unroll
    for (int c = 0; c < 5; c++)
#pragma unroll
        for (int o = 16; o > 0; o >>= 1) acc[c] += __shfl_down_sync(0xffffffffu, acc[c], o);
    __shared__ float red[8][5];
    if (lane == 0)
#pragma unroll
        for (int c = 0; c < 5; c++) red[warp][c] = acc[c];
    __syncthreads();
    if (tid < 5) {
        float s = 0.f;
#pragma unroll
        for (int w = 0; w < 8; w++) s += red[w][tid];
        g_T[(size_t)i * 8 + tid] = s;
    }
}

// ---------------- coar = S^T @ Z (coalesced) ----------------
__global__ void k_coar() {
    int fx = threadIdx.x & 63, ny = threadIdx.x >> 6;
    int f = blockIdx.x * 64 + fx;
    float acc[5] = {0.f, 0.f, 0.f, 0.f, 0.f};
    for (int n = ny; n < NNODE; n += 4) {
        float z = g_Zp[(size_t)n * LP + f];
        const float* s = g_S + (size_t)n * 8;
#pragma unroll
        for (int c = 0; c < 5; c++) acc[c] += s[c] * z;
    }
    __shared__ float red[4][64][5];
#pragma unroll
    for (int c = 0; c < 5; c++) red[ny][fx][c] = acc[c];
    __syncthreads();
    if (ny == 0) {
#pragma unroll
        for (int c = 0; c < 5; c++) {
            float s = red[0][fx][c] + red[1][fx][c] + red[2][fx][c] + red[3][fx][c];
            g_coar[c * LP + f] = s;
        }
    }
}

// ---------------- Ac = S^T @ T ----------------
__global__ void k_ac() {
    __shared__ float red[256];
    int tid = threadIdx.x;
    float acc[25];
#pragma unroll
    for (int q = 0; q < 25; q++) acc[q] = 0.f;
    for (int n = tid; n < NNODE; n += 256) {
        float sv[5], tv[5];
#pragma unroll
        for (int c = 0; c < 5; c++) { sv[c] = g_S[(size_t)n * 8 + c]; tv[c] = g_T[(size_t)n * 8 + c]; }
#pragma unroll
        for (int a = 0; a < 5; a++)
#pragma unroll
            for (int b = 0; b < 5; b++) acc[a * 5 + b] += sv[a] * tv[b];
    }
#pragma unroll
    for (int q = 0; q < 25; q++) {
        red[tid] = acc[q];
        __syncthreads();
        for (int o = 128; o > 0; o >>= 1) {
            if (tid < o) red[tid] += red[tid + o];
            __syncthreads();
        }
        if (tid == 0) g_Ac[q] = red[0];
        __syncthreads();
    }
}

// ---------------- final: coarse SAGE + BN + pool + MLP + softmax ----------------
__global__ void __launch_bounds__(512) k_final(
    const float* __restrict__ wl, const float* __restrict__ bl, const float* __restrict__ wr,
    const float* __restrict__ bng, const float* __restrict__ bnb,
    const float* __restrict__ l1w, const float* __restrict__ l1b,
    const float* __restrict__ l2w, const float* __restrict__ l2b,
    float* __restrict__ out, int out_size) {
    __shared__ float Mc[25];
    __shared__ float invdc[5];
    __shared__ float neigh[5 * 500];
    __shared__ float pre[5 * 500];
    __shared__ float h1[5 * 250];
    __shared__ float lg[5];
    int tid = threadIdx.x;
    if (tid == 0) {
        float mean = 0.f;
        for (int q = 0; q < 25; q++) mean += g_Ac[q];
        mean *= (1.f / 25.f);
        for (int q = 0; q < 25; q++)
            Mc[q] = (g_Ac[q] >= mean && g_Ac[q] > 0.f) ? 1.f : 0.f;
        for (int i = 0; i < 5; i++) {
            float d = 0.f;
            for (int j = 0; j < 5; j++) d += Mc[i * 5 + j];
            invdc[i] = 1.f / fmaxf(d, 1.f);
        }
    }
    __syncthreads();
    for (int idx = tid; idx < 2500; idx += 512) {
        int i = idx / 500, f = idx % 500;
        float a = 0.f;
#pragma unroll
        for (int j = 0; j < 5; j++) a += Mc[i * 5 + j] * g_coar[j * LP + f];
        neigh[idx] = a * invdc[i];
    }
    __syncthreads();
    for (int idx = tid; idx < 2500; idx += 512) {
        int i = idx / 500, f = idx % 500;
        float acc = bl[f];
        const float* wlr = wl + f * 500;
        const float* wrr = wr + f * 500;
        for (int k = 0; k < 500; k++)
            acc += neigh[i * 500 + k] * wlr[k] + g_coar[i * LP + k] * wrr[k];
        pre[idx] = (acc >= 0.f) ? acc : 0.01f * acc;
    }
    __syncthreads();
    for (int f = tid; f < 500; f += 512) {
        float m = 0.f;
#pragma unroll
        for (int i = 0; i < 5; i++) m += pre[i * 500 + f];
        m *= 0.2f;
        float v = 0.f;
#pragma unroll
        for (int i = 0; i < 5; i++) { float d = pre[i * 500 + f] - m; v += d * d; }
        v *= 0.2f;
        float sd = sqrtf(v + 1e-5f);
        float gf = bng[f], bf = bnb[f];
#pragma unroll
        for (int i = 0; i < 5; i++)
            pre[i * 500 + f] = (pre[i * 500 + f] - m) / sd * gf + bf;
    }
    __syncthreads();
    for (int idx = tid; idx < 2500; idx += 512) {
        int i = idx / 500, f = idx % 500;
        float mx = -1e30f;
#pragma unroll
        for (int j = 0; j < 5; j++)
            if (Mc[i * 5 + j] > 0.f || j == i) mx = fmaxf(mx, pre[j * 500 + f]);
        neigh[idx] = mx;
    }
    __syncthreads();
    for (int idx = tid; idx < 1250; idx += 512) {
        int i = idx / 250, o = idx % 250;
        float acc = l1b[o];
        const float* w = l1w + o * 500;
        for (int k = 0; k < 500; k++) acc += neigh[i * 500 + k] * w[k];
        h1[idx] = (acc >= 0.f) ? acc : 0.01f * acc;
    }
    __syncthreads();
    if (tid < 5) {
        float acc = l2b[0];
        for (int k = 0; k < 250; k++) acc += h1[tid * 250 + k] * l2w[k];
        lg[tid] = (acc >= 0.f) ? acc : 0.01f * acc;
    }
    __syncthreads();
    if (tid == 0) {
        float m = lg[0];
        for (int i = 1; i < 5; i++) m = fmaxf(m, lg[i]);
        float e[5], s = 0.f;
        for (int i = 0; i < 5; i++) { e[i] = expf(lg[i] - m); s += e[i]; }
        float p = 0.f;
        for (int i = 0; i < 5; i++) p = fmaxf(p, e[i] / s);
        out[0] = p;
        if (out_size > 1) out[1] = (p >= 0.5f) ? 1.f : 0.f;
    }
}

// ---------------- host launcher ----------------
static float* symaddr(const void* sym) {
    void* p = nullptr;
    cudaGetSymbolAddress(&p, sym);
    return (float*)p;
}

extern "C" void kernel_launch(void* const* d_in, const int* in_sizes, int n_in,
                              void* d_out, int out_size) {
    const float* x    = (const float*)d_in[0];
    const float* c1w  = (const float*)d_in[1];
    const float* c1b  = (const float*)d_in[2];
    const float* c2w  = (const float*)d_in[3];
    const float* c2b  = (const float*)d_in[4];
    const float* fcw  = (const float*)d_in[5];
    const float* fcb  = (const float*)d_in[6];
    const float* swl  = (const float*)d_in[7];
    const float* sbl  = (const float*)d_in[8];
    const float* swr  = (const float*)d_in[9];
    const float* bng  = (const float*)d_in[10];
    const float* bnb  = (const float*)d_in[11];
    const float* cgwo = (const float*)d_in[12];
    const float* cgbo = (const float*)d_in[13];
    const float* cgwr = (const float*)d_in[14];
    const float* l1w  = (const float*)d_in[15];
    const float* l1b  = (const float*)d_in[16];
    const float* l2w  = (const float*)d_in[17];
    const float* l2b  = (const float*)d_in[18];
    float* out = (float*)d_out;

    float* pF  = symaddr(g_F);
    float* pH  = symaddr(g_H);
    float* pAH = symaddr(g_AH);
    float* pZp = symaddr(g_Zp);
    float* pIS = symaddr(g_invS);

    k_zero<<<1, 64>>>();
    k_conv1<<<NNODE, 768>>>(x, c1w, c1b);
    k_conv2<<<NNODE / 2, 512>>>(c2w, c2b);
    {   // H = relu(F @ fcw^T + fcb), pads zeroed
        dim3 g(4, 32);
        k_gemm<<<g, 256>>>(pF, FEAT, fcw, FEAT, pH, LP, LL, LP, FEAT,
                           fcb, nullptr, 1, 0);
    }
    k_rownorm<<<NNODE, 128>>>();
    k_gram<<<528, 256>>>();
    k_thr<<<1, 1>>>();
    k_deg<<<NNODE, 256>>>();
    {
        dim3 g(4, 32);
        k_ah<<<g, 256>>>();
    }
    {   // Zp = leaky((AH/deg)@wl^T + bl + H@wr^T)
        dim3 g(4, 32);
        k_gemm<<<g, 256>>>(pAH, LP, swl, LL, pZp, LP, LL, LP, LL,
                           sbl, pIS, 0, 0);
        k_gemm<<<g, 256>>>(pH, LP, swr, LL, pZp, LP, LL, LP, LL,
                           nullptr, nullptr, 2, 1);
    }
    k_bnsum<<<64, 512>>>();
    k_bnfin<<<1, 512>>>();
    k_bnapply<<<64, 512>>>(bng, bnb);
    k_cluster<<<NNODE / 4, 128>>>(cgwo, cgbo, cgwr);
    k_as<<<NNODE, 256>>>();
    k_coar<<<8, 256>>>();
    k_ac<<<1, 256>>>();
    k_final<<<1, 512>>>(swl, sbl, swr, bng, bnb, l1w, l1b, l2w, l2b, out, out_size);
}

// round 3
// speedup vs baseline: 2.4773x; 1.2558x over previous
#include <cuda_runtime.h>
#include <math.h>

#define NNODE 4096
#define LL 500
#define LP 512
#define FEAT 800

typedef unsigned long long ull;

// ---------------- scratch (device globals; no allocation) ----------------
__device__ float g_P1[NNODE * 2880];          // conv1+pool out [N,20,12,12]
__device__ float g_F[NNODE * FEAT];           // conv2+pool out [N,800]
__device__ float g_H[NNODE * LP];             // fc+relu features [N,500] (LD=512, pads zero)
__device__ float g_sq[NNODE];                 // row norms of H
__device__ float g_D2[(size_t)NNODE * NNODE]; // pairwise squared distances
__device__ unsigned int g_hist[64];           // distance histogram
__device__ float g_thr2;                      // chosen threshold^2
__device__ int   g_adj[(size_t)NNODE * NNODE];// adjacency lists (worst case)
__device__ int   g_deg[NNODE];
__device__ float g_invS[NNODE];               // 1/max(deg,1)
__device__ float g_invC[NNODE];               // 1/(deg+1)
__device__ float g_AH[NNODE * LP];            // A @ H (raw)
__device__ float g_AHn[NNODE * LP];           // (A @ H)/deg
__device__ float g_W[512 * 1024];             // packed [wl | wr]
__device__ float g_part0[(size_t)NNODE * LP]; // split-gemm partials
__device__ float g_part1[(size_t)NNODE * LP];
__device__ float g_Zp[NNODE * LP];            // SAGE out -> Z (in place)
__device__ float g_S[NNODE * 8];              // soft assignment [N,5]
__device__ float g_T[NNODE * 8];              // A @ S
__device__ float g_coar[5 * LP];              // S^T @ Z
__device__ float g_Ac[25];                    // S^T A S
__device__ float g_bnp[64 * 512];             // BN partial sums
__device__ float g_bnp2[64 * 512];
__device__ float g_bnm[512];
__device__ float g_bni[512];

__global__ void k_zero() {
    if (threadIdx.x < 64) g_hist[threadIdx.x] = 0u;
}

// ---------------- packed fp32x2 helpers ----------------
__device__ __forceinline__ void fma2(ull &d, ull a, ull b) {
    asm("fma.rn.f32x2 %0, %1, %2, %0;" : "+l"(d) : "l"(a), "l"(b));
}
__device__ __forceinline__ ull pk2(float a, float b) {
    ull r;
    asm("mov.b64 %0, {%1, %2};" : "=l"(r) : "f"(a), "f"(b));
    return r;
}
__device__ __forceinline__ float2 up2(ull v) {
    float2 r;
    r.x = __uint_as_float((unsigned)v);
    r.y = __uint_as_float((unsigned)(v >> 32));
    return r;
}

// shared compute core: 128x128 tile, BK=16, A duplicated, acc 8 rows x 4 col-pairs
__device__ __forceinline__ void gemm_core(const float (*As)[256], const float (*Bs)[128],
                                          int tx, int ty, ull acc[8][4]) {
#pragma unroll
    for (int kk = 0; kk < 16; kk++) {
        ulonglong2 A01 = *(const ulonglong2*)&As[kk][8 * ty];
        ulonglong2 A23 = *(const ulonglong2*)&As[kk][8 * ty + 4];
        ulonglong2 A45 = *(const ulonglong2*)&As[kk][8 * ty + 128];
        ulonglong2 A67 = *(const ulonglong2*)&As[kk][8 * ty + 132];
        ulonglong2 B01 = *(const ulonglong2*)&Bs[kk][4 * tx];
        ulonglong2 B23 = *(const ulonglong2*)&Bs[kk][4 * tx + 64];
        ull av[8] = {A01.x, A01.y, A23.x, A23.y, A45.x, A45.y, A67.x, A67.y};
        ull bv[4] = {B01.x, B01.y, B23.x, B23.y};
#pragma unroll
        for (int i = 0; i < 8; i++)
#pragma unroll
            for (int j = 0; j < 4; j++) fma2(acc[i][j], av[i], bv[j]);
    }
}

// ---------------- conv1 (1->20,5x5)+relu+pool, register-blocked ----------------
__global__ void __launch_bounds__(768) k_conv1(const float* __restrict__ x,
                                               const float* __restrict__ w,
                                               const float* __restrict__ b) {
    int n = blockIdx.x;
    __shared__ float simg[784];
    __shared__ float sw[500];
    const float* xi = x + (size_t)n * 784;
    for (int i = threadIdx.x; i < 784; i += 768) simg[i] = xi[i];
    for (int i = threadIdx.x; i < 500; i += 768) sw[i] = w[i];
    __syncthreads();
    int t = threadIdx.x;
    if (t >= 720) return;
    int c = t / 36;
    int reg = t % 36;
    int ry = (reg / 6) * 2, rx = (reg % 6) * 2;
    float wreg[25];
#pragma unroll
    for (int u = 0; u < 25; u++) wreg[u] = sw[c * 25 + u];
    float a[4][4];
#pragma unroll
    for (int i = 0; i < 4; i++)
#pragma unroll
        for (int j = 0; j < 4; j++) a[i][j] = 0.f;
#pragma unroll
    for (int rr = 0; rr < 8; rr++) {
        float row[8];
        const float* sp = simg + (2 * ry + rr) * 28 + 2 * rx;
#pragma unroll
        for (int u = 0; u < 8; u++) row[u] = sp[u];
        int iy0 = rr - 4 > 0 ? rr - 4 : 0;
        int iy1 = rr < 3 ? rr : 3;
#pragma unroll 4
        for (int iy = iy0; iy <= iy1; iy++) {
            int ky = rr - iy;
#pragma unroll
            for (int ix = 0; ix < 4; ix++)
#pragma unroll
                for (int kx = 0; kx < 5; kx++)
                    a[iy][ix] += row[ix + kx] * wreg[ky * 5 + kx];
        }
    }
    float bc = b[c];
#pragma unroll
    for (int py = 0; py < 2; py++)
#pragma unroll
        for (int px = 0; px < 2; px++) {
            float mx = fmaxf(fmaxf(a[2 * py][2 * px], a[2 * py][2 * px + 1]),
                             fmaxf(a[2 * py + 1][2 * px], a[2 * py + 1][2 * px + 1]));
            g_P1[(size_t)n * 2880 + c * 144 + (ry + py) * 12 + rx + px] = fmaxf(mx + bc, 0.f);
        }
}

// ---------------- conv2 (20->50,5x5)+relu+pool, channel-paired f32x2 ----------------
__global__ void __launch_bounds__(256, 2) k_conv2(const float* __restrict__ w,
                                                  const float* __restrict__ b) {
    __shared__ float2 sd[2][2880];   // duplicated {v,v} image
    int n0 = blockIdx.x * 2;
    for (int i = threadIdx.x; i < 2880; i += 256) {
        float v0 = g_P1[(size_t)n0 * 2880 + i];
        float v1 = g_P1[(size_t)(n0 + 1) * 2880 + i];
        sd[0][i] = make_float2(v0, v0);
        sd[1][i] = make_float2(v1, v1);
    }
    __syncthreads();
    int half = threadIdx.x >> 7, t = threadIdx.x & 127;
    if (t >= 100) return;
    int n = n0 + half;
    int cp = t >> 2, q = t & 3;
    int c0 = cp * 2;
    int ry = (q >> 1) * 2, rx = (q & 1) * 2;
    ull a2[4][4];
#pragma unroll
    for (int i = 0; i < 4; i++)
#pragma unroll
        for (int j = 0; j < 4; j++) a2[i][j] = 0ULL;
    const float2* sp = sd[half];
    for (int ic = 0; ic < 20; ic++) {
        ull wp[25];
        const float* w0 = w + c0 * 500 + ic * 25;
#pragma unroll
        for (int u = 0; u < 25; u++) wp[u] = pk2(__ldg(w0 + u), __ldg(w0 + 500 + u));
#pragma unroll
        for (int rr = 0; rr < 8; rr++) {
            const float2* rp = sp + ic * 144 + (2 * ry + rr) * 12 + 2 * rx;
            ull rd[8];
#pragma unroll
            for (int u = 0; u < 8; u++) rd[u] = *(const ull*)(rp + u);
            int iy0 = rr - 4 > 0 ? rr - 4 : 0;
            int iy1 = rr < 3 ? rr : 3;
#pragma unroll 4
            for (int iy = iy0; iy <= iy1; iy++) {
                int ky = rr - iy;
#pragma unroll
                for (int ix = 0; ix < 4; ix++)
#pragma unroll
                    for (int kx = 0; kx < 5; kx++)
                        fma2(a2[iy][ix], rd[ix + kx], wp[ky * 5 + kx]);
            }
        }
    }
    float b0 = b[c0], b1 = b[c0 + 1];
#pragma unroll
    for (int py = 0; py < 2; py++)
#pragma unroll
        for (int px = 0; px < 2; px++) {
            float2 v00 = up2(a2[2 * py][2 * px]), v01 = up2(a2[2 * py][2 * px + 1]);
            float2 v10 = up2(a2[2 * py + 1][2 * px]), v11 = up2(a2[2 * py + 1][2 * px + 1]);
            float m0 = fmaxf(fmaxf(v00.x, v01.x), fmaxf(v10.x, v11.x));
            float m1 = fmaxf(fmaxf(v00.y, v01.y), fmaxf(v10.y, v11.y));
            g_F[(size_t)n * 800 + c0 * 16 + (ry + py) * 4 + rx + px] = fmaxf(m0 + b0, 0.f);
            g_F[(size_t)n * 800 + (c0 + 1) * 16 + (ry + py) * 4 + rx + px] = fmaxf(m1 + b1, 0.f);
        }
}

// ---------------- split NT GEMM: z slot picks (A,B) pair, raw partial out ----------------
__global__ void __launch_bounds__(256, 2) k_gemm_sk(
    const float* __restrict__ A0, const float* __restrict__ A1, int lda,
    const float* __restrict__ B0, const float* __restrict__ B1, int ldb,
    int K, int Nc) {
    __shared__ float As[16][256];
    __shared__ float Bs[16][128];
    int tid = threadIdx.x, tx = tid & 15, ty = tid >> 4;
    int zz = blockIdx.z;
    const float* A = zz ? A1 : A0;
    const float* B = zz ? B1 : B0;
    float* Cp = zz ? g_part1 : g_part0;
    int brow = blockIdx.y * 128, bcol = blockIdx.x * 128;
    int lrow = tid >> 1, lk = (tid & 1) * 8;
    int gr = brow + lrow, gc = bcol + lrow;
    int bok = (gc < Nc);
    ull acc[8][4];
#pragma unroll
    for (int i = 0; i < 8; i++)
#pragma unroll
        for (int j = 0; j < 4; j++) acc[i][j] = 0ULL;
    const float4 z4 = make_float4(0.f, 0.f, 0.f, 0.f);
    float4 ra0, ra1, rb0, rb1;
    ra0 = *(const float4*)(A + (size_t)gr * lda + lk);
    ra1 = *(const float4*)(A + (size_t)gr * lda + lk + 4);
    rb0 = bok ? *(const float4*)(B + (size_t)gc * ldb + lk) : z4;
    rb1 = bok ? *(const float4*)(B + (size_t)gc * ldb + lk + 4) : z4;
    int ktiles = K >> 4;
    for (int tt = 0; tt < ktiles; tt++) {
        __syncthreads();
        const float* pa0 = (const float*)&ra0;
        const float* pa1 = (const float*)&ra1;
        const float* pb0 = (const float*)&rb0;
        const float* pb1 = (const float*)&rb1;
#pragma unroll
        for (int j = 0; j < 4; j++) {
            ((float2*)As[lk + j])[lrow] = make_float2(pa0[j], pa0[j]);
            ((float2*)As[lk + 4 + j])[lrow] = make_float2(pa1[j], pa1[j]);
            Bs[lk + j][lrow] = pb0[j];
            Bs[lk + 4 + j][lrow] = pb1[j];
        }
        __syncthreads();
        if (tt + 1 < ktiles) {
            int kb = (tt + 1) * 16 + lk;
            ra0 = *(const float4*)(A + (size_t)gr * lda + kb);
            ra1 = *(const float4*)(A + (size_t)gr * lda + kb + 4);
            rb0 = bok ? *(const float4*)(B + (size_t)gc * ldb + kb) : z4;
            rb1 = bok ? *(const float4*)(B + (size_t)gc * ldb + kb + 4) : z4;
        }
        gemm_core(As, Bs, tx, ty, acc);
    }
#pragma unroll
    for (int i = 0; i < 8; i++) {
        int r = brow + ty * 4 + (i & 3) + ((i >> 2) << 6);
#pragma unroll
        for (int j = 0; j < 4; j++) {
            int c = bcol + tx * 4 + ((j & 1) << 1) + ((j >> 1) << 6);
            float2 v = up2(acc[i][j]);
            Cp[(size_t)r * LP + c] = v.x;
            Cp[(size_t)r * LP + c + 1] = v.y;
        }
    }
}

// ---------------- combine split parts + bias + act ----------------
__global__ void k_comb(const float* __restrict__ bias, float* __restrict__ dst, int act) {
    int i = blockIdx.x;
    int c = threadIdx.x * 4;
    float4 o = make_float4(0.f, 0.f, 0.f, 0.f);
    if (c < LL) {
        float4 v0 = *(const float4*)&g_part0[(size_t)i * LP + c];
        float4 v1 = *(const float4*)&g_part1[(size_t)i * LP + c];
        o.x = v0.x + v1.x + bias[c];
        o.y = v0.y + v1.y + bias[c + 1];
        o.z = v0.z + v1.z + bias[c + 2];
        o.w = v0.w + v1.w + bias[c + 3];
        if (act == 1) {
            o.x = fmaxf(o.x, 0.f); o.y = fmaxf(o.y, 0.f);
            o.z = fmaxf(o.z, 0.f); o.w = fmaxf(o.w, 0.f);
        } else {
            o.x = o.x >= 0.f ? o.x : 0.01f * o.x;
            o.y = o.y >= 0.f ? o.y : 0.01f * o.y;
            o.z = o.z >= 0.f ? o.z : 0.01f * o.z;
            o.w = o.w >= 0.f ? o.w : 0.01f * o.w;
        }
    }
    *(float4*)&dst[(size_t)i * LP + c] = o;
}

// ---------------- pack [wl | wr] into g_W [512][1024] ----------------
__global__ void k_packw(const float* __restrict__ wl, const float* __restrict__ wr) {
    int n = blockIdx.x;
    for (int k = threadIdx.x; k < 1024; k += 256) {
        float v = 0.f;
        if (n < LL) {
            if (k < LL) v = wl[n * LL + k];
            else if (k >= 512 && k < 512 + LL) v = wr[n * LL + (k - 512)];
        }
        g_W[n * 1024 + k] = v;
    }
}

// ---------------- row squared norms of H ----------------
__global__ void k_rownorm() {
    int i = blockIdx.x;
    __shared__ float red[128];
    float s = 0.f;
    for (int k = threadIdx.x; k < LL; k += 128) {
        float v = g_H[(size_t)i * LP + k];
        s += v * v;
    }
    red[threadIdx.x] = s;
    __syncthreads();
    for (int o = 64; o > 0; o >>= 1) {
        if (threadIdx.x < o) red[threadIdx.x] += red[threadIdx.x + o];
        __syncthreads();
    }
    if (threadIdx.x == 0) g_sq[i] = red[0];
}

// ---------------- triangular Gram -> D2 + histogram ----------------
__global__ void __launch_bounds__(256, 2) k_gram() {
    __shared__ float As[16][256];
    __shared__ float Bs[16][128];
    __shared__ unsigned int shist[64];
    int tid = threadIdx.x, tx = tid & 15, ty = tid >> 4;
    if (tid < 64) shist[tid] = 0u;
    int bid = blockIdx.x, by = 0, rem = bid;
    while (rem >= 32 - by) { rem -= 32 - by; by++; }
    int bx = by + rem;
    int brow = by * 128, bcol = bx * 128;
    int lrow = tid >> 1, lk = (tid & 1) * 8;
    int gr = brow + lrow, gc = bcol + lrow;
    ull acc[8][4];
#pragma unroll
    for (int i = 0; i < 8; i++)
#pragma unroll
        for (int j = 0; j < 4; j++) acc[i][j] = 0ULL;
    float4 ra0, ra1, rb0, rb1;
    ra0 = *(const float4*)(g_H + (size_t)gr * LP + lk);
    ra1 = *(const float4*)(g_H + (size_t)gr * LP + lk + 4);
    rb0 = *(const float4*)(g_H + (size_t)gc * LP + lk);
    rb1 = *(const float4*)(g_H + (size_t)gc * LP + lk + 4);
    for (int tt = 0; tt < 32; tt++) {
        __syncthreads();
        const float* pa0 = (const float*)&ra0;
        const float* pa1 = (const float*)&ra1;
        const float* pb0 = (const float*)&rb0;
        const float* pb1 = (const float*)&rb1;
#pragma unroll
        for (int j = 0; j < 4; j++) {
            ((float2*)As[lk + j])[lrow] = make_float2(pa0[j], pa0[j]);
            ((float2*)As[lk + 4 + j])[lrow] = make_float2(pa1[j], pa1[j]);
            Bs[lk + j][lrow] = pb0[j];
            Bs[lk + 4 + j][lrow] = pb1[j];
        }
        __syncthreads();
        if (tt + 1 < 32) {
            int kb = (tt + 1) * 16 + lk;
            ra0 = *(const float4*)(g_H + (size_t)gr * LP + kb);
            ra1 = *(const float4*)(g_H + (size_t)gr * LP + kb + 4);
            rb0 = *(const float4*)(g_H + (size_t)gc * LP + kb);
            rb1 = *(const float4*)(g_H + (size_t)gc * LP + kb + 4);
        }
        gemm_core(As, Bs, tx, ty, acc);
    }
    float sqr_[8], sqc_[8];
#pragma unroll
    for (int i = 0; i < 8; i++) sqr_[i] = g_sq[brow + ty * 4 + (i & 3) + ((i >> 2) << 6)];
#pragma unroll
    for (int j = 0; j < 8; j++) sqc_[j] = g_sq[bcol + tx * 4 + (j & 3) + ((j >> 2) << 6)];
    unsigned wgt = (bx == by) ? 1u : 2u;
#pragma unroll
    for (int i = 0; i < 8; i++) {
        int r = brow + ty * 4 + (i & 3) + ((i >> 2) << 6);
#pragma unroll
        for (int j = 0; j < 4; j++) {
            int cb = bcol + tx * 4 + ((j & 1) << 1) + ((j >> 1) << 6);
            float2 v = up2(acc[i][j]);
#pragma unroll
            for (int e = 0; e < 2; e++) {
                int c = cb + e;
                int ce = ((j >> 1) << 2) + ((j & 1) << 1) + e;
                float dot = e ? v.y : v.x;
                float d2 = fmaxf(sqr_[i] - 2.f * dot + sqc_[ce], 0.f);
                g_D2[(size_t)r * NNODE + c] = d2;
                if (bx != by) g_D2[(size_t)c * NNODE + r] = d2;
                int bin;
                if (r == c) bin = 64;
                else if (d2 < 6.25f) bin = 0;
                else {
                    float d = sqrtf(d2);
                    bin = 1 + (int)((d - 2.5f) * 2.0f);
                    if (bin > 63) bin = 63;
                    float t = 2.5f + 0.5f * (float)bin;
                    if (!(d2 < t * t)) { bin++; if (bin > 63) bin = 63; }
                    else if (bin > 1) {
                        float tm = t - 0.5f;
                        if (d2 < tm * tm) bin--;
                    }
                }
                unsigned msk = __match_any_sync(0xffffffffu, bin);
                int leader = __ffs(msk) - 1;
                if ((int)(tid & 31) == leader && bin < 64)
                    atomicAdd(&shist[bin], (unsigned)__popc(msk) * wgt);
            }
        }
    }
    __syncthreads();
    if (tid < 64 && shist[tid]) atomicAdd(&g_hist[tid], shist[tid]);
}

// ---------------- pick threshold ----------------
__global__ void k_thr() {
    unsigned int cum = 0;
    int k = 0;
    for (k = 0; k < 64; k++) {
        cum += g_hist[k];
        if ((float)cum >= 409.6f) break;
    }
    if (k > 63) k = 63;
    float t = 2.5f + 0.5f * (float)k;
    g_thr2 = t * t;
}

// ---------------- build adjacency lists (ascending j, deterministic) ----------------
__global__ void __launch_bounds__(256) k_adj() {
    int i = blockIdx.x;
    int tid = threadIdx.x, lane = tid & 31, warp = tid >> 5;
    float thr2 = g_thr2;
    const float* row = g_D2 + (size_t)i * NNODE;
    int* out = g_adj + (size_t)i * NNODE;
    __shared__ int warpcnt[8];
    __shared__ int base;
    if (tid == 0) base = 0;
    __syncthreads();
    for (int j0 = 0; j0 < NNODE; j0 += 256) {
        int j = j0 + tid;
        bool p = (row[j] < thr2) && (j != i);
        unsigned m = __ballot_sync(0xffffffffu, p);
        if (lane == 0) warpcnt[warp] = __popc(m);
        __syncthreads();
        int off = 0;
        for (int w = 0; w < warp; w++) off += warpcnt[w];
        if (p) out[base + off + __popc(m & ((1u << lane) - 1u))] = j;
        __syncthreads();
        if (tid == 0) {
            int tot = 0;
            for (int w = 0; w < 8; w++) tot += warpcnt[w];
            base += tot;
        }
        __syncthreads();
    }
    if (tid == 0) {
        float d = (float)base;
        g_deg[i] = base;
        g_invS[i] = 1.f / fmaxf(d, 1.f);
        g_invC[i] = 1.f / (d + 1.f);
    }
}

// ---------------- sparse AH gather ----------------
__global__ void __launch_bounds__(128) k_gather() {
    int i = blockIdx.x;
    int deg = g_deg[i];
    int f = threadIdx.x * 4;
    const int* adj = g_adj + (size_t)i * NNODE;
    float4 acc = make_float4(0.f, 0.f, 0.f, 0.f);
    for (int e = 0; e < deg; e++) {
        int j = adj[e];
        float4 h = *(const float4*)&g_H[(size_t)j * LP + f];
        acc.x += h.x; acc.y += h.y; acc.z += h.z; acc.w += h.w;
    }
    *(float4*)&g_AH[(size_t)i * LP + f] = acc;
    float s = g_invS[i];
    float4 an = make_float4(acc.x * s, acc.y * s, acc.z * s, acc.w * s);
    *(float4*)&g_AHn[(size_t)i * LP + f] = an;
}

// ---------------- BatchNorm: coalesced partials -> finalize -> apply ----------------
__global__ void k_bnsum() {
    int f = threadIdx.x, b = blockIdx.x;
    float s = 0.f, s2 = 0.f;
    for (int n = b; n < NNODE; n += 64) {
        float v = g_Zp[(size_t)n * LP + f];
        s += v;
        s2 += v * v;
    }
    g_bnp[b * 512 + f] = s;
    g_bnp2[b * 512 + f] = s2;
}
__global__ void k_bnfin() {
    int f = threadIdx.x;
    float s = 0.f, s2 = 0.f;
    for (int b = 0; b < 64; b++) { s += g_bnp[b * 512 + f]; s2 += g_bnp2[b * 512 + f]; }
    float m = s / (float)NNODE;
    float var = fmaxf(s2 / (float)NNODE - m * m, 0.f);
    g_bnm[f] = m;
    g_bni[f] = 1.f / sqrtf(var + 1e-5f);
}
__global__ void k_bnapply(const float* __restrict__ gw, const float* __restrict__ gb) {
    int f = threadIdx.x, b = blockIdx.x;
    if (f >= LL) return;
    float m = g_bnm[f], inv = g_bni[f], gf = gw[f], bf = gb[f];
    for (int n = b; n < NNODE; n += 64) {
        float v = g_Zp[(size_t)n * LP + f];
        g_Zp[(size_t)n * LP + f] = (v - m) * inv * gf + bf;
    }
}

// ---------------- ClusterGCN assignment logits + softmax -> S ----------------
__global__ void k_cluster(const float* __restrict__ wout, const float* __restrict__ bout,
                          const float* __restrict__ wroot) {
    int warp = threadIdx.x >> 5, lane = threadIdx.x & 31;
    int i = blockIdx.x * 4 + warp;
    float invc = g_invC[i];
    float lg[5];
#pragma unroll
    for (int c = 0; c < 5; c++) {
        float acc = 0.f;
        for (int k = lane; k < LL; k += 32) {
            float hv = g_H[(size_t)i * LP + k];
            float ag = (g_AH[(size_t)i * LP + k] + hv) * invc;
            acc += ag * wout[c * LL + k] + hv * wroot[c * LL + k];
        }
#pragma unroll
        for (int o = 16; o > 0; o >>= 1) acc += __shfl_down_sync(0xffffffffu, acc, o);
        acc = __shfl_sync(0xffffffffu, acc, 0);
        lg[c] = acc + bout[c];
    }
    if (lane == 0) {
        float m = lg[0];
#pragma unroll
        for (int c = 1; c < 5; c++) m = fmaxf(m, lg[c]);
        float e[5], s = 0.f;
#pragma unroll
        for (int c = 0; c < 5; c++) { e[c] = expf(lg[c] - m); s += e[c]; }
#pragma unroll
        for (int c = 0; c < 5; c++) g_S[(size_t)i * 8 + c] = e[c] / s;
    }
}

// ---------------- T = A @ S via adjacency ----------------
__global__ void __launch_bounds__(256) k_ts() {
    int row = blockIdx.x * 8 + (threadIdx.x >> 5);
    int lane = threadIdx.x & 31;
    int deg = g_deg[row];
    const int* adj = g_adj + (size_t)row * NNODE;
    float a0 = 0.f, a1 = 0.f, a2 = 0.f, a3 = 0.f, a4 = 0.f;
    for (int e = lane; e < deg; e += 32) {
        int j = adj[e];
        const float* s = g_S + (size_t)j * 8;
        a0 += s[0]; a1 += s[1]; a2 += s[2]; a3 += s[3]; a4 += s[4];
    }
#pragma unroll
    for (int o = 16; o > 0; o >>= 1) {
        a0 += __shfl_down_sync(0xffffffffu, a0, o);
        a1 += __shfl_down_sync(0xffffffffu, a1, o);
        a2 += __shfl_down_sync(0xffffffffu, a2, o);
        a3 += __shfl_down_sync(0xffffffffu, a3, o);
        a4 += __shfl_down_sync(0xffffffffu, a4, o);
    }
    if (lane == 0) {
        g_T[(size_t)row * 8 + 0] = a0;
        g_T[(size_t)row * 8 + 1] = a1;
        g_T[(size_t)row * 8 + 2] = a2;
        g_T[(size_t)row * 8 + 3] = a3;
        g_T[(size_t)row * 8 + 4] = a4;
    }
}

// ---------------- coar = S^T @ Z (coalesced) ----------------
__global__ void k_coar() {
    int fx = threadIdx.x & 63, ny = threadIdx.x >> 6;
    int f = blockIdx.x * 64 + fx;
    float acc[5] = {0.f, 0.f, 0.f, 0.f, 0.f};
    for (int n = ny; n < NNODE; n += 4) {
        float z = g_Zp[(size_t)n * LP + f];
        const float* s = g_S + (size_t)n * 8;
#pragma unroll
        for (int c = 0; c < 5; c++) acc[c] += s[c] * z;
    }
    __shared__ float red[4][64][5];
#pragma unroll
    for (int c = 0; c < 5; c++) red[ny][fx][c] = acc[c];
    __syncthreads();
    if (ny == 0) {
#pragma unroll
        for (int c = 0; c < 5; c++) {
            float s = red[0][fx][c] + red[1][fx][c] + red[2][fx][c] + red[3][fx][c];
            g_coar[c * LP + f] = s;
        }
    }
}

// ---------------- Ac = S^T @ T ----------------
__global__ void k_ac() {
    __shared__ float red[256];
    int tid = threadIdx.x;
    float acc[25];
#pragma unroll
    for (int q = 0; q < 25; q++) acc[q] = 0.f;
    for (int n = tid; n < NNODE; n += 256) {
        float sv[5], tv[5];
#pragma unroll
        for (int c = 0; c < 5; c++) { sv[c] = g_S[(size_t)n * 8 + c]; tv[c] = g_T[(size_t)n * 8 + c]; }
#pragma unroll
        for (int a = 0; a < 5; a++)
#pragma unroll
            for (int b = 0; b < 5; b++) acc[a * 5 + b] += sv[a] * tv[b];
    }
#pragma unroll
    for (int q = 0; q < 25; q++) {
        red[tid] = acc[q];
        __syncthreads();
        for (int o = 128; o > 0; o >>= 1) {
            if (tid < o) red[tid] += red[tid + o];
            __syncthreads();
        }
        if (tid == 0) g_Ac[q] = red[0];
        __syncthreads();
    }
}

// ---------------- final: coarse SAGE + BN + pool + MLP + softmax ----------------
__global__ void __launch_bounds__(512) k_final(
    const float* __restrict__ wl, const float* __restrict__ bl, const float* __restrict__ wr,
    const float* __restrict__ bng, const float* __restrict__ bnb,
    const float* __restrict__ l1w, const float* __restrict__ l1b,
    const float* __restrict__ l2w, const float* __restrict__ l2b,
    float* __restrict__ out, int out_size) {
    __shared__ float Mc[25];
    __shared__ float invdc[5];
    __shared__ float neigh[5 * 500];
    __shared__ float pre[5 * 500];
    __shared__ float h1[5 * 250];
    __shared__ float lg[5];
    int tid = threadIdx.x;
    if (tid == 0) {
        float mean = 0.f;
        for (int q = 0; q < 25; q++) mean += g_Ac[q];
        mean *= (1.f / 25.f);
        for (int q = 0; q < 25; q++)
            Mc[q] = (g_Ac[q] >= mean && g_Ac[q] > 0.f) ? 1.f : 0.f;
        for (int i = 0; i < 5; i++) {
            float d = 0.f;
            for (int j = 0; j < 5; j++) d += Mc[i * 5 + j];
            invdc[i] = 1.f / fmaxf(d, 1.f);
        }
    }
    __syncthreads();
    for (int idx = tid; idx < 2500; idx += 512) {
        int i = idx / 500, f = idx % 500;
        float a = 0.f;
#pragma unroll
        for (int j = 0; j < 5; j++) a += Mc[i * 5 + j] * g_coar[j * LP + f];
        neigh[idx] = a * invdc[i];
    }
    __syncthreads();
    for (int idx = tid; idx < 2500; idx += 512) {
        int i = idx / 500, f = idx % 500;
        float acc = bl[f];
        const float* wlr = wl + f * 500;
        const float* wrr = wr + f * 500;
        for (int k = 0; k < 500; k++)
            acc += neigh[i * 500 + k] * wlr[k] + g_coar[i * LP + k] * wrr[k];
        pre[idx] = (acc >= 0.f) ? acc : 0.01f * acc;
    }
    __syncthreads();
    for (int f = tid; f < 500; f += 512) {
        float m = 0.f;
#pragma unroll
        for (int i = 0; i < 5; i++) m += pre[i * 500 + f];
        m *= 0.2f;
        float v = 0.f;
#pragma unroll
        for (int i = 0; i < 5; i++) { float d = pre[i * 500 + f] - m; v += d * d; }
        v *= 0.2f;
        float sd = sqrtf(v + 1e-5f);
        float gf = bng[f], bf = bnb[f];
#pragma unroll
        for (int i = 0; i < 5; i++)
            pre[i * 500 + f] = (pre[i * 500 + f] - m) / sd * gf + bf;
    }
    __syncthreads();
    for (int idx = tid; idx < 2500; idx += 512) {
        int i = idx / 500, f = idx % 500;
        float mx = -1e30f;
#pragma unroll
        for (int j = 0; j < 5; j++)
            if (Mc[i * 5 + j] > 0.f || j == i) mx = fmaxf(mx, pre[j * 500 + f]);
        neigh[idx] = mx;
    }
    __syncthreads();
    for (int idx = tid; idx < 1250; idx += 512) {
        int i = idx / 250, o = idx % 250;
        float acc = l1b[o];
        const float* w = l1w + o * 500;
        for (int k = 0; k < 500; k++) acc += neigh[i * 500 + k] * w[k];
        h1[idx] = (acc >= 0.f) ? acc : 0.01f * acc;
    }
    __syncthreads();
    if (tid < 5) {
        float acc = l2b[0];
        for (int k = 0; k < 250; k++) acc += h1[tid * 250 + k] * l2w[k];
        lg[tid] = (acc >= 0.f) ? acc : 0.01f * acc;
    }
    __syncthreads();
    if (tid == 0) {
        float m = lg[0];
        for (int i = 1; i < 5; i++) m = fmaxf(m, lg[i]);
        float e[5], s = 0.f;
        for (int i = 0; i < 5; i++) { e[i] = expf(lg[i] - m); s += e[i]; }
        float p = 0.f;
        for (int i = 0; i < 5; i++) p = fmaxf(p, e[i] / s);
        out[0] = p;
        if (out_size > 1) out[1] = (p >= 0.5f) ? 1.f : 0.f;
    }
}

// ---------------- host launcher ----------------
static float* symaddr(const void* sym) {
    void* p = nullptr;
    cudaGetSymbolAddress(&p, sym);
    return (float*)p;
}

extern "C" void kernel_launch(void* const* d_in, const int* in_sizes, int n_in,
                              void* d_out, int out_size) {
    const float* x    = (const float*)d_in[0];
    const float* c1w  = (const float*)d_in[1];
    const float* c1b  = (const float*)d_in[2];
    const float* c2w  = (const float*)d_in[3];
    const float* c2b  = (const float*)d_in[4];
    const float* fcw  = (const float*)d_in[5];
    const float* fcb  = (const float*)d_in[6];
    const float* swl  = (const float*)d_in[7];
    const float* sbl  = (const float*)d_in[8];
    const float* swr  = (const float*)d_in[9];
    const float* bng  = (const float*)d_in[10];
    const float* bnb  = (const float*)d_in[11];
    const float* cgwo = (const float*)d_in[12];
    const float* cgbo = (const float*)d_in[13];
    const float* cgwr = (const float*)d_in[14];
    const float* l1w  = (const float*)d_in[15];
    const float* l1b  = (const float*)d_in[16];
    const float* l2w  = (const float*)d_in[17];
    const float* l2b  = (const float*)d_in[18];
    float* out = (float*)d_out;

    float* pF   = symaddr(g_F);
    float* pH   = symaddr(g_H);
    float* pAHn = symaddr(g_AHn);
    float* pZp  = symaddr(g_Zp);
    float* pW   = symaddr(g_W);

    k_zero<<<1, 64>>>();
    k_packw<<<512, 256>>>(swl, swr);
    k_conv1<<<NNODE, 768>>>(x, c1w, c1b);
    k_conv2<<<NNODE / 2, 256>>>(c2w, c2b);
    {   // fc: H = relu(F @ fcw^T + fcb), split-K 2 (400+400)
        dim3 g(4, 32, 2);
        k_gemm_sk<<<g, 256>>>(pF, pF + 400, FEAT, fcw, fcw + 400, FEAT, 400, LL);
        k_comb<<<NNODE, 128>>>(fcb, pH, 1);
    }
    k_rownorm<<<NNODE, 128>>>();
    k_gram<<<528, 256>>>();
    k_thr<<<1, 1>>>();
    k_adj<<<NNODE, 256>>>();
    k_gather<<<NNODE, 128>>>();
    {   // SAGE: Zp = leaky(AHn@wl^T + H@wr^T + bl), two slots of packed W
        dim3 g(4, 32, 2);
        k_gemm_sk<<<g, 256>>>(pAHn, pH, LP, pW, pW + 512, 1024, 512, LP);
        k_comb<<<NNODE, 128>>>(sbl, pZp, 2);
    }
    k_bnsum<<<64, 512>>>();
    k_bnfin<<<1, 512>>>();
    k_bnapply<<<64, 512>>>(bng, bnb);
    k_cluster<<<NNODE / 4, 128>>>(cgwo, cgbo, cgwr);
    k_ts<<<NNODE / 8, 256>>>();
    k_coar<<<8, 256>>>();
    k_ac<<<1, 256>>>();
    k_final<<<1, 512>>>(swl, sbl, swr, bng, bnb, l1w, l1b, l2w, l2b, out, out_size);
}

// round 4
// speedup vs baseline: 2.8352x; 1.1445x over previous
#include <cuda_runtime.h>
#include <math.h>

#define NNODE 4096
#define LL 500
#define LP 512
#define FEAT 800

typedef unsigned long long ull;

// ---------------- scratch (device globals; no allocation) ----------------
__device__ float g_P1[NNODE * 3840];          // conv1+pool out, padded [N,20,12,16]
__device__ float g_F[NNODE * FEAT];           // conv2+pool out [N,800]
__device__ float g_H[NNODE * LP];             // fc+relu features [N,500] (LD=512, pads zero)
__device__ float g_sq[NNODE];                 // row norms of H
__device__ unsigned char g_bin[(size_t)NNODE * NNODE]; // distance bin per pair
__device__ unsigned int g_hist[64];           // distance histogram
__device__ int   g_kthr;                      // chosen threshold bin
__device__ int   g_adj[(size_t)NNODE * NNODE];// adjacency lists
__device__ int   g_deg[NNODE];
__device__ float g_invS[NNODE];               // 1/max(deg,1)
__device__ float g_invC[NNODE];               // 1/(deg+1)
__device__ float g_AH[NNODE * LP];            // A @ H (raw)
__device__ float g_AHn[NNODE * LP];           // (A @ H)/deg
__device__ float g_W[512 * 1024];             // packed [wl | wr]
__device__ float g_part0[(size_t)NNODE * LP]; // split-gemm partials
__device__ float g_part1[(size_t)NNODE * LP];
__device__ float g_Zp[NNODE * LP];            // SAGE out -> Z (in place)
__device__ float g_S[NNODE * 8];              // soft assignment [N,5]
__device__ float g_T[NNODE * 8];              // A @ S
__device__ float g_cpart[8][5 * 512];         // coar partials
__device__ float g_coar[5 * LP];              // S^T @ Z
__device__ float g_Ac[25];                    // S^T A S
__device__ float g_bnp[64 * 512];             // BN partial sums
__device__ float g_bnp2[64 * 512];
__device__ float g_bnm[512];
__device__ float g_bni[512];

__global__ void k_zero() {
    if (threadIdx.x < 64) g_hist[threadIdx.x] = 0u;
}

// ---------------- packed fp32x2 helpers ----------------
__device__ __forceinline__ void fma2(ull &d, ull a, ull b) {
    asm("fma.rn.f32x2 %0, %1, %2, %0;" : "+l"(d) : "l"(a), "l"(b));
}
__device__ __forceinline__ ull pk2(float a, float b) {
    ull r;
    asm("mov.b64 %0, {%1, %2};" : "=l"(r) : "f"(a), "f"(b));
    return r;
}
__device__ __forceinline__ ull dup2(float a) { return pk2(a, a); }
__device__ __forceinline__ float2 up2(ull v) {
    float2 r;
    r.x = __uint_as_float((unsigned)v);
    r.y = __uint_as_float((unsigned)(v >> 32));
    return r;
}

// compute core: 128x128 tile, BK=16, plain A (packed after load), acc 8 rows x 4 col-pairs
__device__ __forceinline__ void gemm_core_p(const float (*As)[128], const float (*Bs)[128],
                                            int tx, int ty, ull acc[8][4]) {
#pragma unroll
    for (int kk = 0; kk < 16; kk++) {
        float4 a0 = *(const float4*)&As[kk][4 * ty];
        float4 a1 = *(const float4*)&As[kk][4 * ty + 64];
        ulonglong2 B01 = *(const ulonglong2*)&Bs[kk][4 * tx];
        ulonglong2 B23 = *(const ulonglong2*)&Bs[kk][4 * tx + 64];
        ull av[8] = {dup2(a0.x), dup2(a0.y), dup2(a0.z), dup2(a0.w),
                     dup2(a1.x), dup2(a1.y), dup2(a1.z), dup2(a1.w)};
        ull bv[4] = {B01.x, B01.y, B23.x, B23.y};
#pragma unroll
        for (int i = 0; i < 8; i++)
#pragma unroll
            for (int j = 0; j < 4; j++) fma2(acc[i][j], av[i], bv[j]);
    }
}

// ---------------- conv1 (1->20,5x5)+relu+pool, channel-paired f32x2 ----------------
__global__ void __launch_bounds__(384) k_conv1(const float* __restrict__ x,
                                               const float* __restrict__ w,
                                               const float* __restrict__ b) {
    int n = blockIdx.x;
    __shared__ __align__(16) float simg[784];
    __shared__ float sw[500];
    const float* xi = x + (size_t)n * 784;
    for (int i = threadIdx.x; i < 784; i += 384) simg[i] = xi[i];
    for (int i = threadIdx.x; i < 500; i += 384) sw[i] = w[i];
    __syncthreads();
    int t = threadIdx.x;
    if (t >= 360) return;
    int p = t / 36, reg = t % 36;
    int c0 = p * 2;
    int ry = (reg / 6) * 2, rx = (reg % 6) * 2;
    ull wp[25];
#pragma unroll
    for (int u = 0; u < 25; u++) wp[u] = pk2(sw[c0 * 25 + u], sw[c0 * 25 + 25 + u]);
    ull a2[4][4];
#pragma unroll
    for (int i = 0; i < 4; i++)
#pragma unroll
        for (int j = 0; j < 4; j++) a2[i][j] = 0ULL;
#pragma unroll
    for (int rr = 0; rr < 8; rr++) {
        const float* sp = simg + (2 * ry + rr) * 28 + 2 * rx;
        float4 q0 = *(const float4*)sp;
        float4 q1 = *(const float4*)(sp + 4);
        ull rd[8] = {dup2(q0.x), dup2(q0.y), dup2(q0.z), dup2(q0.w),
                     dup2(q1.x), dup2(q1.y), dup2(q1.z), dup2(q1.w)};
        int iy0 = rr - 4 > 0 ? rr - 4 : 0;
        int iy1 = rr < 3 ? rr : 3;
#pragma unroll 4
        for (int iy = iy0; iy <= iy1; iy++) {
            int ky = rr - iy;
#pragma unroll
            for (int ix = 0; ix < 4; ix++)
#pragma unroll
                for (int kx = 0; kx < 5; kx++)
                    fma2(a2[iy][ix], rd[ix + kx], wp[ky * 5 + kx]);
        }
    }
    float b0 = b[c0], b1 = b[c0 + 1];
#pragma unroll
    for (int py = 0; py < 2; py++)
#pragma unroll
        for (int px = 0; px < 2; px++) {
            float2 v00 = up2(a2[2 * py][2 * px]), v01 = up2(a2[2 * py][2 * px + 1]);
            float2 v10 = up2(a2[2 * py + 1][2 * px]), v11 = up2(a2[2 * py + 1][2 * px + 1]);
            float m0 = fmaxf(fmaxf(v00.x, v01.x), fmaxf(v10.x, v11.x));
            float m1 = fmaxf(fmaxf(v00.y, v01.y), fmaxf(v10.y, v11.y));
            int yy = ry + py, xx = rx + px;
            g_P1[(size_t)n * 3840 + c0 * 192 + yy * 16 + xx] = fmaxf(m0 + b0, 0.f);
            g_P1[(size_t)n * 3840 + (c0 + 1) * 192 + yy * 16 + xx] = fmaxf(m1 + b1, 0.f);
        }
}

// ---------------- conv2 (20->50,5x5)+relu+pool, channel-paired f32x2, padded smem ----------------
__global__ void __launch_bounds__(256, 2) k_conv2(const float* __restrict__ w,
                                                  const float* __restrict__ b) {
    __shared__ __align__(16) float sp2[2][3840];
    int n0 = blockIdx.x * 2;
    for (int v = threadIdx.x; v < 1920; v += 256) {
        int img = v / 960, idx = v % 960;
        ((float4*)sp2[img])[idx] = ((const float4*)(g_P1 + (size_t)(n0 + img) * 3840))[idx];
    }
    __syncthreads();
    int half = threadIdx.x >> 7, t = threadIdx.x & 127;
    if (t >= 100) return;
    int n = n0 + half;
    int cp = t >> 2, q = t & 3;
    int c0 = cp * 2;
    int ry = (q >> 1) * 2, rx = (q & 1) * 2;
    ull a2[4][4];
#pragma unroll
    for (int i = 0; i < 4; i++)
#pragma unroll
        for (int j = 0; j < 4; j++) a2[i][j] = 0ULL;
    const float* sp = sp2[half];
    for (int ic = 0; ic < 20; ic++) {
        ull wp[25];
        const float* w0 = w + c0 * 500 + ic * 25;
#pragma unroll
        for (int u = 0; u < 25; u++) wp[u] = pk2(__ldg(w0 + u), __ldg(w0 + 500 + u));
#pragma unroll
        for (int rr = 0; rr < 8; rr++) {
            const float* rp = sp + ic * 192 + (2 * ry + rr) * 16 + 2 * rx;
            float4 q0 = *(const float4*)rp;
            float4 q1 = *(const float4*)(rp + 4);
            ull rd[8] = {dup2(q0.x), dup2(q0.y), dup2(q0.z), dup2(q0.w),
                         dup2(q1.x), dup2(q1.y), dup2(q1.z), dup2(q1.w)};
            int iy0 = rr - 4 > 0 ? rr - 4 : 0;
            int iy1 = rr < 3 ? rr : 3;
#pragma unroll 4
            for (int iy = iy0; iy <= iy1; iy++) {
                int ky = rr - iy;
#pragma unroll
                for (int ix = 0; ix < 4; ix++)
#pragma unroll
                    for (int kx = 0; kx < 5; kx++)
                        fma2(a2[iy][ix], rd[ix + kx], wp[ky * 5 + kx]);
            }
        }
    }
    float b0 = b[c0], b1 = b[c0 + 1];
#pragma unroll
    for (int py = 0; py < 2; py++)
#pragma unroll
        for (int px = 0; px < 2; px++) {
            float2 v00 = up2(a2[2 * py][2 * px]), v01 = up2(a2[2 * py][2 * px + 1]);
            float2 v10 = up2(a2[2 * py + 1][2 * px]), v11 = up2(a2[2 * py + 1][2 * px + 1]);
            float m0 = fmaxf(fmaxf(v00.x, v01.x), fmaxf(v10.x, v11.x));
            float m1 = fmaxf(fmaxf(v00.y, v01.y), fmaxf(v10.y, v11.y));
            g_F[(size_t)n * 800 + c0 * 16 + (ry + py) * 4 + rx + px] = fmaxf(m0 + b0, 0.f);
            g_F[(size_t)n * 800 + (c0 + 1) * 16 + (ry + py) * 4 + rx + px] = fmaxf(m1 + b1, 0.f);
        }
}

// ---------------- split NT GEMM: z slot picks (A,B) pair, raw partial out ----------------
__global__ void __launch_bounds__(256, 2) k_gemm_sk(
    const float* __restrict__ A0, const float* __restrict__ A1, int lda,
    const float* __restrict__ B0, const float* __restrict__ B1, int ldb,
    int K, int Nc) {
    __shared__ float As[16][128];
    __shared__ float Bs[16][128];
    int tid = threadIdx.x, tx = tid & 15, ty = tid >> 4;
    int zz = blockIdx.z;
    const float* A = zz ? A1 : A0;
    const float* B = zz ? B1 : B0;
    float* Cp = zz ? g_part1 : g_part0;
    int brow = blockIdx.y * 128, bcol = blockIdx.x * 128;
    int lrow = tid >> 1, lk = (tid & 1) * 8;
    int gr = brow + lrow, gc = bcol + lrow;
    int bok = (gc < Nc);
    ull acc[8][4];
#pragma unroll
    for (int i = 0; i < 8; i++)
#pragma unroll
        for (int j = 0; j < 4; j++) acc[i][j] = 0ULL;
    const float4 z4 = make_float4(0.f, 0.f, 0.f, 0.f);
    float4 ra0, ra1, rb0, rb1;
    ra0 = *(const float4*)(A + (size_t)gr * lda + lk);
    ra1 = *(const float4*)(A + (size_t)gr * lda + lk + 4);
    rb0 = bok ? *(const float4*)(B + (size_t)gc * ldb + lk) : z4;
    rb1 = bok ? *(const float4*)(B + (size_t)gc * ldb + lk + 4) : z4;
    int ktiles = K >> 4;
    for (int tt = 0; tt < ktiles; tt++) {
        __syncthreads();
        const float* pa0 = (const float*)&ra0;
        const float* pa1 = (const float*)&ra1;
        const float* pb0 = (const float*)&rb0;
        const float* pb1 = (const float*)&rb1;
#pragma unroll
        for (int j = 0; j < 4; j++) {
            As[lk + j][lrow] = pa0[j];
            As[lk + 4 + j][lrow] = pa1[j];
            Bs[lk + j][lrow] = pb0[j];
            Bs[lk + 4 + j][lrow] = pb1[j];
        }
        __syncthreads();
        if (tt + 1 < ktiles) {
            int kb = (tt + 1) * 16 + lk;
            ra0 = *(const float4*)(A + (size_t)gr * lda + kb);
            ra1 = *(const float4*)(A + (size_t)gr * lda + kb + 4);
            rb0 = bok ? *(const float4*)(B + (size_t)gc * ldb + kb) : z4;
            rb1 = bok ? *(const float4*)(B + (size_t)gc * ldb + kb + 4) : z4;
        }
        gemm_core_p(As, Bs, tx, ty, acc);
    }
#pragma unroll
    for (int i = 0; i < 8; i++) {
        int r = brow + ty * 4 + (i & 3) + ((i >> 2) << 6);
#pragma unroll
        for (int j = 0; j < 4; j++) {
            int c = bcol + tx * 4 + ((j & 1) << 1) + ((j >> 1) << 6);
            float2 v = up2(acc[i][j]);
            Cp[(size_t)r * LP + c] = v.x;
            Cp[(size_t)r * LP + c + 1] = v.y;
        }
    }
}

// ---------------- combine split parts + bias + act ----------------
__global__ void k_comb(const float* __restrict__ bias, float* __restrict__ dst, int act) {
    int i = blockIdx.x;
    int c = threadIdx.x * 4;
    float4 o = make_float4(0.f, 0.f, 0.f, 0.f);
    if (c < LL) {
        float4 v0 = *(const float4*)&g_part0[(size_t)i * LP + c];
        float4 v1 = *(const float4*)&g_part1[(size_t)i * LP + c];
        o.x = v0.x + v1.x + bias[c];
        o.y = v0.y + v1.y + bias[c + 1];
        o.z = v0.z + v1.z + bias[c + 2];
        o.w = v0.w + v1.w + bias[c + 3];
        if (act == 1) {
            o.x = fmaxf(o.x, 0.f); o.y = fmaxf(o.y, 0.f);
            o.z = fmaxf(o.z, 0.f); o.w = fmaxf(o.w, 0.f);
        } else {
            o.x = o.x >= 0.f ? o.x : 0.01f * o.x;
            o.y = o.y >= 0.f ? o.y : 0.01f * o.y;
            o.z = o.z >= 0.f ? o.z : 0.01f * o.z;
            o.w = o.w >= 0.f ? o.w : 0.01f * o.w;
        }
    }
    *(float4*)&dst[(size_t)i * LP + c] = o;
}

// ---------------- pack [wl | wr] into g_W [512][1024] ----------------
__global__ void k_packw(const float* __restrict__ wl, const float* __restrict__ wr) {
    int n = blockIdx.x;
    for (int k = threadIdx.x; k < 1024; k += 256) {
        float v = 0.f;
        if (n < LL) {
            if (k < LL) v = wl[n * LL + k];
            else if (k >= 512 && k < 512 + LL) v = wr[n * LL + (k - 512)];
        }
        g_W[n * 1024 + k] = v;
    }
}

// ---------------- row squared norms of H ----------------
__global__ void k_rownorm() {
    int i = blockIdx.x;
    __shared__ float red[128];
    float s = 0.f;
    for (int k = threadIdx.x; k < LL; k += 128) {
        float v = g_H[(size_t)i * LP + k];
        s += v * v;
    }
    red[threadIdx.x] = s;
    __syncthreads();
    for (int o = 64; o > 0; o >>= 1) {
        if (threadIdx.x < o) red[threadIdx.x] += red[threadIdx.x + o];
        __syncthreads();
    }
    if (threadIdx.x == 0) g_sq[i] = red[0];
}

// ---------------- triangular Gram -> bins + histogram ----------------
__global__ void __launch_bounds__(256, 2) k_gram() {
    __shared__ float As[16][128];
    __shared__ float Bs[16][128];
    __shared__ unsigned int shist[64];
    int tid = threadIdx.x, tx = tid & 15, ty = tid >> 4;
    if (tid < 64) shist[tid] = 0u;
    int bid = blockIdx.x, by = 0, rem = bid;
    while (rem >= 32 - by) { rem -= 32 - by; by++; }
    int bx = by + rem;
    int brow = by * 128, bcol = bx * 128;
    int lrow = tid >> 1, lk = (tid & 1) * 8;
    int gr = brow + lrow, gc = bcol + lrow;
    ull acc[8][4];
#pragma unroll
    for (int i = 0; i < 8; i++)
#pragma unroll
        for (int j = 0; j < 4; j++) acc[i][j] = 0ULL;
    float4 ra0, ra1, rb0, rb1;
    ra0 = *(const float4*)(g_H + (size_t)gr * LP + lk);
    ra1 = *(const float4*)(g_H + (size_t)gr * LP + lk + 4);
    rb0 = *(const float4*)(g_H + (size_t)gc * LP + lk);
    rb1 = *(const float4*)(g_H + (size_t)gc * LP + lk + 4);
    for (int tt = 0; tt < 32; tt++) {
        __syncthreads();
        const float* pa0 = (const float*)&ra0;
        const float* pa1 = (const float*)&ra1;
        const float* pb0 = (const float*)&rb0;
        const float* pb1 = (const float*)&rb1;
#pragma unroll
        for (int j = 0; j < 4; j++) {
            As[lk + j][lrow] = pa0[j];
            As[lk + 4 + j][lrow] = pa1[j];
            Bs[lk + j][lrow] = pb0[j];
            Bs[lk + 4 + j][lrow] = pb1[j];
        }
        __syncthreads();
        if (tt + 1 < 32) {
            int kb = (tt + 1) * 16 + lk;
            ra0 = *(const float4*)(g_H + (size_t)gr * LP + kb);
            ra1 = *(const float4*)(g_H + (size_t)gr * LP + kb + 4);
            rb0 = *(const float4*)(g_H + (size_t)gc * LP + kb);
            rb1 = *(const float4*)(g_H + (size_t)gc * LP + kb + 4);
        }
        gemm_core_p(As, Bs, tx, ty, acc);
    }
    float sqr_[8], sqc_[8];
#pragma unroll
    for (int i = 0; i < 8; i++) sqr_[i] = g_sq[brow + ty * 4 + (i & 3) + ((i >> 2) << 6)];
#pragma unroll
    for (int j = 0; j < 8; j++) sqc_[j] = g_sq[bcol + tx * 4 + (j & 3) + ((j >> 2) << 6)];
    unsigned wgt = (bx == by) ? 1u : 2u;
#pragma unroll
    for (int i = 0; i < 8; i++) {
        int r = brow + ty * 4 + (i & 3) + ((i >> 2) << 6);
#pragma unroll
        for (int j = 0; j < 4; j++) {
            int cb = bcol + tx * 4 + ((j & 1) << 1) + ((j >> 1) << 6);
            float2 v = up2(acc[i][j]);
#pragma unroll
            for (int e = 0; e < 2; e++) {
                int c = cb + e;
                int ce = ((j >> 1) << 2) + ((j & 1) << 1) + e;
                float dot = e ? v.y : v.x;
                float d2 = fmaxf(sqr_[i] - 2.f * dot + sqc_[ce], 0.f);
                int bin;
                if (r == c) bin = 255;
                else if (d2 < 6.25f) bin = 0;
                else {
                    float d = sqrtf(d2);
                    bin = 1 + (int)((d - 2.5f) * 2.0f);
                    if (bin > 63) bin = 63;
                    float t = 2.5f + 0.5f * (float)bin;
                    if (!(d2 < t * t)) { bin++; if (bin > 63) bin = 63; }
                    else if (bin > 1) {
                        float tm = t - 0.5f;
                        if (d2 < tm * tm) bin--;
                    }
                }
                g_bin[(size_t)r * NNODE + c] = (unsigned char)bin;
                if (bx != by) g_bin[(size_t)c * NNODE + r] = (unsigned char)bin;
                unsigned msk = __match_any_sync(0xffffffffu, bin);
                int leader = __ffs(msk) - 1;
                if ((int)(tid & 31) == leader && bin < 64)
                    atomicAdd(&shist[bin], (unsigned)__popc(msk) * wgt);
            }
        }
    }
    __syncthreads();
    if (tid < 64 && shist[tid]) atomicAdd(&g_hist[tid], shist[tid]);
}

// ---------------- pick threshold bin ----------------
__global__ void k_thr() {
    unsigned int cum = 0;
    int k = 0;
    for (k = 0; k < 64; k++) {
        cum += g_hist[k];
        if ((float)cum >= 409.6f) break;
    }
    if (k > 63) k = 63;
    g_kthr = k;
}

// ---------------- adjacency build: 16 bytes/thread, 2 barriers ----------------
__global__ void __launch_bounds__(256) k_adj() {
    int i = blockIdx.x;
    int tid = threadIdx.x, lane = tid & 31, warp = tid >> 5;
    int kthr = g_kthr;
    uint4 v = ((const uint4*)(g_bin + (size_t)i * NNODE))[tid];
    unsigned words[4] = {v.x, v.y, v.z, v.w};
    int cnt = 0;
    unsigned hm = 0;
#pragma unroll
    for (int wq = 0; wq < 4; wq++)
#pragma unroll
        for (int bq = 0; bq < 4; bq++) {
            int bv = (int)((words[wq] >> (bq * 8)) & 0xffu);
            int u = wq * 4 + bq;
            bool h = (bv <= kthr);
            cnt += h ? 1 : 0;
            hm |= (h ? 1u : 0u) << u;
        }
    int sc = cnt;
#pragma unroll
    for (int o = 1; o < 32; o <<= 1) {
        int t2 = __shfl_up_sync(0xffffffffu, sc, o);
        if (lane >= o) sc += t2;
    }
    __shared__ int wtot[8], wbase[8];
    __shared__ int stot;
    if (lane == 31) wtot[warp] = sc;
    int excl = sc - cnt;
    __syncthreads();
    if (tid == 0) {
        int bse = 0;
        for (int w = 0; w < 8; w++) { wbase[w] = bse; bse += wtot[w]; }
        stot = bse;
        float d = (float)bse;
        g_deg[i] = bse;
        g_invS[i] = 1.f / fmaxf(d, 1.f);
        g_invC[i] = 1.f / (d + 1.f);
    }
    __syncthreads();
    int pos = wbase[warp] + excl;
    int* out = g_adj + (size_t)i * NNODE;
    int j0 = tid * 16;
#pragma unroll
    for (int u = 0; u < 16; u++)
        if ((hm >> u) & 1u) out[pos++] = j0 + u;
}

// ---------------- sparse AH gather ----------------
__global__ void __launch_bounds__(128) k_gather() {
    int i = blockIdx.x;
    int deg = g_deg[i];
    int f = threadIdx.x * 4;
    const int* adj = g_adj + (size_t)i * NNODE;
    float4 acc = make_float4(0.f, 0.f, 0.f, 0.f);
    for (int e = 0; e < deg; e++) {
        int j = adj[e];
        float4 h = *(const float4*)&g_H[(size_t)j * LP + f];
        acc.x += h.x; acc.y += h.y; acc.z += h.z; acc.w += h.w;
    }
    *(float4*)&g_AH[(size_t)i * LP + f] = acc;
    float s = g_invS[i];
    float4 an = make_float4(acc.x * s, acc.y * s, acc.z * s, acc.w * s);
    *(float4*)&g_AHn[(size_t)i * LP + f] = an;
}

// ---------------- BatchNorm: coalesced partials -> finalize -> apply ----------------
__global__ void k_bnsum() {
    int f = threadIdx.x, b = blockIdx.x;
    float s = 0.f, s2 = 0.f;
    for (int n = b; n < NNODE; n += 64) {
        float v = g_Zp[(size_t)n * LP + f];
        s += v;
        s2 += v * v;
    }
    g_bnp[b * 512 + f] = s;
    g_bnp2[b * 512 + f] = s2;
}
__global__ void k_bnfin() {
    int f = threadIdx.x;
    float s = 0.f, s2 = 0.f;
    for (int b = 0; b < 64; b++) { s += g_bnp[b * 512 + f]; s2 += g_bnp2[b * 512 + f]; }
    float m = s / (float)NNODE;
    float var = fmaxf(s2 / (float)NNODE - m * m, 0.f);
    g_bnm[f] = m;
    g_bni[f] = 1.f / sqrtf(var + 1e-5f);
}
__global__ void k_bnapply(const float* __restrict__ gw, const float* __restrict__ gb) {
    int f = threadIdx.x, b = blockIdx.x;
    if (f >= LL) return;
    float m = g_bnm[f], inv = g_bni[f], gf = gw[f], bf = gb[f];
    for (int n = b; n < NNODE; n += 64) {
        float v = g_Zp[(size_t)n * LP + f];
        g_Zp[(size_t)n * LP + f] = (v - m) * inv * gf + bf;
    }
}

// ---------------- ClusterGCN assignment logits + softmax -> S ----------------
__global__ void k_cluster(const float* __restrict__ wout, const float* __restrict__ bout,
                          const float* __restrict__ wroot) {
    int warp = threadIdx.x >> 5, lane = threadIdx.x & 31;
    int i = blockIdx.x * 4 + warp;
    float invc = g_invC[i];
    float lg[5];
#pragma unroll
    for (int c = 0; c < 5; c++) {
        float acc = 0.f;
        for (int k = lane; k < LL; k += 32) {
            float hv = g_H[(size_t)i * LP + k];
            float ag = (g_AH[(size_t)i * LP + k] + hv) * invc;
            acc += ag * wout[c * LL + k] + hv * wroot[c * LL + k];
        }
#pragma unroll
        for (int o = 16; o > 0; o >>= 1) acc += __shfl_down_sync(0xffffffffu, acc, o);
        acc = __shfl_sync(0xffffffffu, acc, 0);
        lg[c] = acc + bout[c];
    }
    if (lane == 0) {
        float m = lg[0];
#pragma unroll
        for (int c = 1; c < 5; c++) m = fmaxf(m, lg[c]);
        float e[5], s = 0.f;
#pragma unroll
        for (int c = 0; c < 5; c++) { e[c] = expf(lg[c] - m); s += e[c]; }
#pragma unroll
        for (int c = 0; c < 5; c++) g_S[(size_t)i * 8 + c] = e[c] / s;
    }
}

// ---------------- T = A @ S via adjacency ----------------
__global__ void __launch_bounds__(256) k_ts() {
    int row = blockIdx.x * 8 + (threadIdx.x >> 5);
    int lane = threadIdx.x & 31;
    int deg = g_deg[row];
    const int* adj = g_adj + (size_t)row * NNODE;
    float a0 = 0.f, a1 = 0.f, a2 = 0.f, a3 = 0.f, a4 = 0.f;
    for (int e = lane; e < deg; e += 32) {
        int j = adj[e];
        const float* s = g_S + (size_t)j * 8;
        a0 += s[0]; a1 += s[1]; a2 += s[2]; a3 += s[3]; a4 += s[4];
    }
#pragma unroll
    for (int o = 16; o > 0; o >>= 1) {
        a0 += __shfl_down_sync(0xffffffffu, a0, o);
        a1 += __shfl_down_sync(0xffffffffu, a1, o);
        a2 += __shfl_down_sync(0xffffffffu, a2, o);
        a3 += __shfl_down_sync(0xffffffffu, a3, o);
        a4 += __shfl_down_sync(0xffffffffu, a4, o);
    }
    if (lane == 0) {
        g_T[(size_t)row * 8 + 0] = a0;
        g_T[(size_t)row * 8 + 1] = a1;
        g_T[(size_t)row * 8 + 2] = a2;
        g_T[(size_t)row * 8 + 3] = a3;
        g_T[(size_t)row * 8 + 4] = a4;
    }
}

// ---------------- coar partials = S^T @ Z over n-chunks ----------------
__global__ void k_coar() {
    int fx = threadIdx.x & 63, ny = threadIdx.x >> 6;
    int f = blockIdx.x * 64 + fx;
    int n0 = blockIdx.y * 512;
    float acc[5] = {0.f, 0.f, 0.f, 0.f, 0.f};
    for (int n = n0 + ny; n < n0 + 512; n += 4) {
        float z = g_Zp[(size_t)n * LP + f];
        const float* s = g_S + (size_t)n * 8;
#pragma unroll
        for (int c = 0; c < 5; c++) acc[c] += s[c] * z;
    }
    __shared__ float red[4][64][5];
#pragma unroll
    for (int c = 0; c < 5; c++) red[ny][fx][c] = acc[c];
    __syncthreads();
    if (ny == 0) {
#pragma unroll
        for (int c = 0; c < 5; c++)
            g_cpart[blockIdx.y][c * 512 + f] =
                red[0][fx][c] + red[1][fx][c] + red[2][fx][c] + red[3][fx][c];
    }
}
__global__ void k_coarfin() {
    int c = blockIdx.x, f = threadIdx.x;
    float s = 0.f;
    for (int b = 0; b < 8; b++) s += g_cpart[b][c * 512 + f];
    g_coar[c * LP + f] = s;
}

// ---------------- Ac = S^T @ T ----------------
__global__ void k_ac() {
    int tid = threadIdx.x, lane = tid & 31, warp = tid >> 5;
    float acc[25];
#pragma unroll
    for (int q = 0; q < 25; q++) acc[q] = 0.f;
    for (int n = tid; n < NNODE; n += 256) {
        float sv[5], tv[5];
#pragma unroll
        for (int c = 0; c < 5; c++) { sv[c] = g_S[(size_t)n * 8 + c]; tv[c] = g_T[(size_t)n * 8 + c]; }
#pragma unroll
        for (int a = 0; a < 5; a++)
#pragma unroll
            for (int b = 0; b < 5; b++) acc[a * 5 + b] += sv[a] * tv[b];
    }
#pragma unroll
    for (int q = 0; q < 25; q++)
#pragma unroll
        for (int o = 16; o > 0; o >>= 1) acc[q] += __shfl_down_sync(0xffffffffu, acc[q], o);
    __shared__ float red[8][25];
    if (lane == 0)
#pragma unroll
        for (int q = 0; q < 25; q++) red[warp][q] = acc[q];
    __syncthreads();
    if (tid < 25) {
        float s = 0.f;
#pragma unroll
        for (int w = 0; w < 8; w++) s += red[w][tid];
        g_Ac[tid] = s;
    }
}

// ---------------- final: coarse SAGE + BN + pool + MLP + softmax ----------------
__global__ void __launch_bounds__(512) k_final(
    const float* __restrict__ wl, const float* __restrict__ bl, const float* __restrict__ wr,
    const float* __restrict__ bng, const float* __restrict__ bnb,
    const float* __restrict__ l1w, const float* __restrict__ l1b,
    const float* __restrict__ l2w, const float* __restrict__ l2b,
    float* __restrict__ out, int out_size) {
    __shared__ float Mc[25];
    __shared__ float invdc[5];
    __shared__ float neigh[5 * 500];
    __shared__ float pre[5 * 500];
    __shared__ float h1[5 * 250];
    __shared__ float lg[5];
    int tid = threadIdx.x;
    if (tid == 0) {
        float mean = 0.f;
        for (int q = 0; q < 25; q++) mean += g_Ac[q];
        mean *= (1.f / 25.f);
        for (int q = 0; q < 25; q++)
            Mc[q] = (g_Ac[q] >= mean && g_Ac[q] > 0.f) ? 1.f : 0.f;
        for (int i = 0; i < 5; i++) {
            float d = 0.f;
            for (int j = 0; j < 5; j++) d += Mc[i * 5 + j];
            invdc[i] = 1.f / fmaxf(d, 1.f);
        }
    }
    __syncthreads();
    for (int idx = tid; idx < 2500; idx += 512) {
        int i = idx / 500, f = idx % 500;
        float a = 0.f;
#pragma unroll
        for (int j = 0; j < 5; j++) a += Mc[i * 5 + j] * g_coar[j * LP + f];
        neigh[idx] = a * invdc[i];
    }
    __syncthreads();
    for (int idx = tid; idx < 2500; idx += 512) {
        int i = idx / 500, f = idx % 500;
        const float* wlr = wl + f * 500;
        const float* wrr = wr + f * 500;
        float a0 = 0.f, a1 = 0.f, a2 = 0.f, a3 = 0.f;
        for (int k = 0; k < 500; k += 4) {
            a0 += neigh[i * 500 + k] * wlr[k] + g_coar[i * LP + k] * wrr[k];
            a1 += neigh[i * 500 + k + 1] * wlr[k + 1] + g_coar[i * LP + k + 1] * wrr[k + 1];
            a2 += neigh[i * 500 + k + 2] * wlr[k + 2] + g_coar[i * LP + k + 2] * wrr[k + 2];
            a3 += neigh[i * 500 + k + 3] * wlr[k + 3] + g_coar[i * LP + k + 3] * wrr[k + 3];
        }
        float acc = bl[f] + ((a0 + a1) + (a2 + a3));
        pre[idx] = (acc >= 0.f) ? acc : 0.01f * acc;
    }
    __syncthreads();
    for (int f = tid; f < 500; f += 512) {
        float m = 0.f;
#pragma unroll
        for (int i = 0; i < 5; i++) m += pre[i * 500 + f];
        m *= 0.2f;
        float v = 0.f;
#pragma unroll
        for (int i = 0; i < 5; i++) { float d = pre[i * 500 + f] - m; v += d * d; }
        v *= 0.2f;
        float sd = sqrtf(v + 1e-5f);
        float gf = bng[f], bf = bnb[f];
#pragma unroll
        for (int i = 0; i < 5; i++)
            pre[i * 500 + f] = (pre[i * 500 + f] - m) / sd * gf + bf;
    }
    __syncthreads();
    for (int idx = tid; idx < 2500; idx += 512) {
        int i = idx / 500, f = idx % 500;
        float mx = -1e30f;
#pragma unroll
        for (int j = 0; j < 5; j++)
            if (Mc[i * 5 + j] > 0.f || j == i) mx = fmaxf(mx, pre[j * 500 + f]);
        neigh[idx] = mx;
    }
    __syncthreads();
    for (int idx = tid; idx < 1250; idx += 512) {
        int i = idx / 250, o = idx % 250;
        const float* w = l1w + o * 500;
        float a0 = 0.f, a1 = 0.f, a2 = 0.f, a3 = 0.f;
        for (int k = 0; k < 500; k += 4) {
            a0 += neigh[i * 500 + k] * w[k];
            a1 += neigh[i * 500 + k + 1] * w[k + 1];
            a2 += neigh[i * 500 + k + 2] * w[k + 2];
            a3 += neigh[i * 500 + k + 3] * w[k + 3];
        }
        float acc = l1b[o] + ((a0 + a1) + (a2 + a3));
        h1[idx] = (acc >= 0.f) ? acc : 0.01f * acc;
    }
    __syncthreads();
    if (tid < 5) {
        float acc = l2b[0];
        for (int k = 0; k < 250; k++) acc += h1[tid * 250 + k] * l2w[k];
        lg[tid] = (acc >= 0.f) ? acc : 0.01f * acc;
    }
    __syncthreads();
    if (tid == 0) {
        float m = lg[0];
        for (int i = 1; i < 5; i++) m = fmaxf(m, lg[i]);
        float e[5], s = 0.f;
        for (int i = 0; i < 5; i++) { e[i] = expf(lg[i] - m); s += e[i]; }
        float p = 0.f;
        for (int i = 0; i < 5; i++) p = fmaxf(p, e[i] / s);
        out[0] = p;
        if (out_size > 1) out[1] = (p >= 0.5f) ? 1.f : 0.f;
    }
}

// ---------------- host launcher ----------------
static float* symaddr(const void* sym) {
    void* p = nullptr;
    cudaGetSymbolAddress(&p, sym);
    return (float*)p;
}

extern "C" void kernel_launch(void* const* d_in, const int* in_sizes, int n_in,
                              void* d_out, int out_size) {
    const float* x    = (const float*)d_in[0];
    const float* c1w  = (const float*)d_in[1];
    const float* c1b  = (const float*)d_in[2];
    const float* c2w  = (const float*)d_in[3];
    const float* c2b  = (const float*)d_in[4];
    const float* fcw  = (const float*)d_in[5];
    const float* fcb  = (const float*)d_in[6];
    const float* swl  = (const float*)d_in[7];
    const float* sbl  = (const float*)d_in[8];
    const float* swr  = (const float*)d_in[9];
    const float* bng  = (const float*)d_in[10];
    const float* bnb  = (const float*)d_in[11];
    const float* cgwo = (const float*)d_in[12];
    const float* cgbo = (const float*)d_in[13];
    const float* cgwr = (const float*)d_in[14];
    const float* l1w  = (const float*)d_in[15];
    const float* l1b  = (const float*)d_in[16];
    const float* l2w  = (const float*)d_in[17];
    const float* l2b  = (const float*)d_in[18];
    float* out = (float*)d_out;

    float* pF   = symaddr(g_F);
    float* pH   = symaddr(g_H);
    float* pAHn = symaddr(g_AHn);
    float* pZp  = symaddr(g_Zp);
    float* pW   = symaddr(g_W);

    k_zero<<<1, 64>>>();
    k_packw<<<512, 256>>>(swl, swr);
    k_conv1<<<NNODE, 384>>>(x, c1w, c1b);
    k_conv2<<<NNODE / 2, 256>>>(c2w, c2b);
    {   // fc: H = relu(F @ fcw^T + fcb), split-K 2 (400+400)
        dim3 g(4, 32, 2);
        k_gemm_sk<<<g, 256>>>(pF, pF + 400, FEAT, fcw, fcw + 400, FEAT, 400, LL);
        k_comb<<<NNODE, 128>>>(fcb, pH, 1);
    }
    k_rownorm<<<NNODE, 128>>>();
    k_gram<<<528, 256>>>();
    k_thr<<<1, 1>>>();
    k_adj<<<NNODE, 256>>>();
    k_gather<<<NNODE, 128>>>();
    {   // SAGE: Zp = leaky(AHn@wl^T + H@wr^T + bl), two slots of packed W
        dim3 g(4, 32, 2);
        k_gemm_sk<<<g, 256>>>(pAHn, pH, LP, pW, pW + 512, 1024, 512, LP);
        k_comb<<<NNODE, 128>>>(sbl, pZp, 2);
    }
    k_bnsum<<<64, 512>>>();
    k_bnfin<<<1, 512>>>();
    k_bnapply<<<64, 512>>>(bng, bnb);
    k_cluster<<<NNODE / 4, 128>>>(cgwo, cgbo, cgwr);
    k_ts<<<NNODE / 8, 256>>>();
    {
        dim3 g(8, 8);
        k_coar<<<g, 256>>>();
        k_coarfin<<<5, 512>>>();
    }
    k_ac<<<1, 256>>>();
    k_final<<<1, 512>>>(swl, sbl, swr, bng, bnb, l1w, l1b, l2w, l2b, out, out_size);
}

// round 6
// speedup vs baseline: 2.9223x; 1.0307x over previous
#include <cuda_runtime.h>
#include <math.h>

#define NNODE 4096
#define LL 500
#define LP 512
#define FEAT 800

typedef unsigned long long ull;

// ---------------- scratch (device globals; no allocation) ----------------
__device__ float g_P1[NNODE * 3840];          // conv1+pool out, padded [N,20,12,16]
__device__ float g_F[NNODE * FEAT];           // conv2+pool out [N,800]
__device__ float g_H[NNODE * LP];             // fc+relu features [N,500] (LD=512, pads zero)
__device__ float g_sq[NNODE];                 // row norms of H
__device__ unsigned char g_bin[(size_t)NNODE * NNODE]; // distance bin per pair
__device__ unsigned int g_hist[64];           // distance histogram
__device__ int   g_kthr;                      // chosen threshold bin
__device__ int   g_adj[(size_t)NNODE * NNODE];// adjacency lists
__device__ int   g_deg[NNODE];
__device__ float g_invS[NNODE];               // 1/max(deg,1)
__device__ float g_invC[NNODE];               // 1/(deg+1)
__device__ float g_AH[NNODE * LP];            // A @ H (raw)
__device__ float g_AHn[NNODE * LP];           // (A @ H)/deg
__device__ float g_W[512 * 1024];             // packed [wl | wr]
__device__ float g_part0[(size_t)NNODE * LP]; // split-gemm partials
__device__ float g_part1[(size_t)NNODE * LP];
__device__ float g_Zp[NNODE * LP];            // SAGE out -> Z (in place)
__device__ float g_S[NNODE * 8];              // soft assignment [N,5]
__device__ float g_T[NNODE * 8];              // A @ S
__device__ float g_cpart[8][5 * 512];         // coar partials
__device__ float g_coar[5 * LP];              // S^T @ Z
__device__ float g_Ac[25];                    // S^T A S
__device__ float g_bnp[64 * 512];             // BN partial sums
__device__ float g_bnp2[64 * 512];
__device__ float g_bnm[512];
__device__ float g_bni[512];

__global__ void k_zero() {
    if (threadIdx.x < 64) g_hist[threadIdx.x] = 0u;
}

// ---------------- packed fp32x2 helpers ----------------
__device__ __forceinline__ void fma2(ull &d, ull a, ull b) {
    asm("fma.rn.f32x2 %0, %1, %2, %0;" : "+l"(d) : "l"(a), "l"(b));
}
__device__ __forceinline__ ull pk2(float a, float b) {
    ull r;
    asm("mov.b64 %0, {%1, %2};" : "=l"(r) : "f"(a), "f"(b));
    return r;
}
__device__ __forceinline__ ull dup2(float a) { return pk2(a, a); }
__device__ __forceinline__ float2 up2(ull v) {
    float2 r;
    r.x = __uint_as_float((unsigned)v);
    r.y = __uint_as_float((unsigned)(v >> 32));
    return r;
}

// compute core: 128x128 tile, BK=16, plain A (packed after load), acc 8 rows x 4 col-pairs
__device__ __forceinline__ void gemm_core_p(const float (*As)[128], const float (*Bs)[128],
                                            int tx, int ty, ull acc[8][4]) {
#pragma unroll
    for (int kk = 0; kk < 16; kk++) {
        float4 a0 = *(const float4*)&As[kk][4 * ty];
        float4 a1 = *(const float4*)&As[kk][4 * ty + 64];
        ulonglong2 B01 = *(const ulonglong2*)&Bs[kk][4 * tx];
        ulonglong2 B23 = *(const ulonglong2*)&Bs[kk][4 * tx + 64];
        ull av[8] = {dup2(a0.x), dup2(a0.y), dup2(a0.z), dup2(a0.w),
                     dup2(a1.x), dup2(a1.y), dup2(a1.z), dup2(a1.w)};
        ull bv[4] = {B01.x, B01.y, B23.x, B23.y};
#pragma unroll
        for (int i = 0; i < 8; i++)
#pragma unroll
            for (int j = 0; j < 4; j++) fma2(acc[i][j], av[i], bv[j]);
    }
}

// ---------------- conv1 (1->20,5x5)+relu+pool, channel-paired f32x2 ----------------
__global__ void __launch_bounds__(384) k_conv1(const float* __restrict__ x,
                                               const float* __restrict__ w,
                                               const float* __restrict__ b) {
    int n = blockIdx.x;
    __shared__ __align__(16) float simg[784];
    __shared__ float sw[500];
    const float* xi = x + (size_t)n * 784;
    for (int i = threadIdx.x; i < 784; i += 384) simg[i] = xi[i];
    for (int i = threadIdx.x; i < 500; i += 384) sw[i] = w[i];
    __syncthreads();
    int t = threadIdx.x;
    if (t >= 360) return;
    int p = t / 36, reg = t % 36;
    int c0 = p * 2;
    int ry = (reg / 6) * 2, rx = (reg % 6) * 2;
    ull wp[25];
#pragma unroll
    for (int u = 0; u < 25; u++) wp[u] = pk2(sw[c0 * 25 + u], sw[c0 * 25 + 25 + u]);
    ull a2[4][4];
#pragma unroll
    for (int i = 0; i < 4; i++)
#pragma unroll
        for (int j = 0; j < 4; j++) a2[i][j] = 0ULL;
#pragma unroll
    for (int rr = 0; rr < 8; rr++) {
        const float* sp = simg + (2 * ry + rr) * 28 + 2 * rx;
        float4 q0 = *(const float4*)sp;
        float4 q1 = *(const float4*)(sp + 4);
        ull rd[8] = {dup2(q0.x), dup2(q0.y), dup2(q0.z), dup2(q0.w),
                     dup2(q1.x), dup2(q1.y), dup2(q1.z), dup2(q1.w)};
        int iy0 = rr - 4 > 0 ? rr - 4 : 0;
        int iy1 = rr < 3 ? rr : 3;
#pragma unroll 4
        for (int iy = iy0; iy <= iy1; iy++) {
            int ky = rr - iy;
#pragma unroll
            for (int ix = 0; ix < 4; ix++)
#pragma unroll
                for (int kx = 0; kx < 5; kx++)
                    fma2(a2[iy][ix], rd[ix + kx], wp[ky * 5 + kx]);
        }
    }
    float b0 = b[c0], b1 = b[c0 + 1];
#pragma unroll
    for (int py = 0; py < 2; py++)
#pragma unroll
        for (int px = 0; px < 2; px++) {
            float2 v00 = up2(a2[2 * py][2 * px]), v01 = up2(a2[2 * py][2 * px + 1]);
            float2 v10 = up2(a2[2 * py + 1][2 * px]), v11 = up2(a2[2 * py + 1][2 * px + 1]);
            float m0 = fmaxf(fmaxf(v00.x, v01.x), fmaxf(v10.x, v11.x));
            float m1 = fmaxf(fmaxf(v00.y, v01.y), fmaxf(v10.y, v11.y));
            int yy = ry + py, xx = rx + px;
            g_P1[(size_t)n * 3840 + c0 * 192 + yy * 16 + xx] = fmaxf(m0 + b0, 0.f);
            g_P1[(size_t)n * 3840 + (c0 + 1) * 192 + yy * 16 + xx] = fmaxf(m1 + b1, 0.f);
        }
}

// ---------------- conv2: 5 images/block, 500 active lanes, channel-paired f32x2 ----------------
#define C2_IMGS 5
__global__ void __launch_bounds__(512, 1) k_conv2(const float* __restrict__ w,
                                                  const float* __restrict__ b) {
    extern __shared__ __align__(16) float sp5[];   // [5][3840]
    int n0 = blockIdx.x * C2_IMGS;
    for (int v = threadIdx.x; v < 960 * C2_IMGS; v += 512) {
        int img = v / 960, idx = v % 960;
        if (n0 + img < NNODE)
            ((float4*)(sp5 + img * 3840))[idx] =
                ((const float4*)(g_P1 + (size_t)(n0 + img) * 3840))[idx];
    }
    __syncthreads();
    int t = threadIdx.x;
    if (t >= 100 * C2_IMGS) return;
    int img = t / 100, t2 = t % 100;
    int n = n0 + img;
    if (n >= NNODE) return;
    int cp = t2 >> 2, q = t2 & 3;
    int c0 = cp * 2;
    int ry = (q >> 1) * 2, rx = (q & 1) * 2;
    ull a2[4][4];
#pragma unroll
    for (int i = 0; i < 4; i++)
#pragma unroll
        for (int j = 0; j < 4; j++) a2[i][j] = 0ULL;
    const float* sp = sp5 + img * 3840;
    for (int ic = 0; ic < 20; ic++) {
        ull wp[25];
        const float* w0 = w + c0 * 500 + ic * 25;
#pragma unroll
        for (int u = 0; u < 25; u++) wp[u] = pk2(__ldg(w0 + u), __ldg(w0 + 500 + u));
#pragma unroll
        for (int rr = 0; rr < 8; rr++) {
            const float* rp = sp + ic * 192 + (2 * ry + rr) * 16 + 2 * rx;
            float4 q0 = *(const float4*)rp;
            float4 q1 = *(const float4*)(rp + 4);
            ull rd[8] = {dup2(q0.x), dup2(q0.y), dup2(q0.z), dup2(q0.w),
                         dup2(q1.x), dup2(q1.y), dup2(q1.z), dup2(q1.w)};
            int iy0 = rr - 4 > 0 ? rr - 4 : 0;
            int iy1 = rr < 3 ? rr : 3;
#pragma unroll 4
            for (int iy = iy0; iy <= iy1; iy++) {
                int ky = rr - iy;
#pragma unroll
                for (int ix = 0; ix < 4; ix++)
#pragma unroll
                    for (int kx = 0; kx < 5; kx++)
                        fma2(a2[iy][ix], rd[ix + kx], wp[ky * 5 + kx]);
            }
        }
    }
    float b0 = b[c0], b1 = b[c0 + 1];
#pragma unroll
    for (int py = 0; py < 2; py++)
#pragma unroll
        for (int px = 0; px < 2; px++) {
            float2 v00 = up2(a2[2 * py][2 * px]), v01 = up2(a2[2 * py][2 * px + 1]);
            float2 v10 = up2(a2[2 * py + 1][2 * px]), v11 = up2(a2[2 * py + 1][2 * px + 1]);
            float m0 = fmaxf(fmaxf(v00.x, v01.x), fmaxf(v10.x, v11.x));
            float m1 = fmaxf(fmaxf(v00.y, v01.y), fmaxf(v10.y, v11.y));
            g_F[(size_t)n * 800 + c0 * 16 + (ry + py) * 4 + rx + px] = fmaxf(m0 + b0, 0.f);
            g_F[(size_t)n * 800 + (c0 + 1) * 16 + (ry + py) * 4 + rx + px] = fmaxf(m1 + b1, 0.f);
        }
}

// ---------------- split NT GEMM: z slot picks (A,B) pair, raw partial out ----------------
__global__ void __launch_bounds__(256, 2) k_gemm_sk(
    const float* __restrict__ A0, const float* __restrict__ A1, int lda,
    const float* __restrict__ B0, const float* __restrict__ B1, int ldb,
    int K, int Nc) {
    __shared__ float As[16][128];
    __shared__ float Bs[16][128];
    int tid = threadIdx.x, tx = tid & 15, ty = tid >> 4;
    int zz = blockIdx.z;
    const float* A = zz ? A1 : A0;
    const float* B = zz ? B1 : B0;
    float* Cp = zz ? g_part1 : g_part0;
    int brow = blockIdx.y * 128, bcol = blockIdx.x * 128;
    int lrow = tid >> 1, lk = (tid & 1) * 8;
    int gr = brow + lrow, gc = bcol + lrow;
    int bok = (gc < Nc);
    ull acc[8][4];
#pragma unroll
    for (int i = 0; i < 8; i++)
#pragma unroll
        for (int j = 0; j < 4; j++) acc[i][j] = 0ULL;
    const float4 z4 = make_float4(0.f, 0.f, 0.f, 0.f);
    float4 ra0, ra1, rb0, rb1;
    ra0 = *(const float4*)(A + (size_t)gr * lda + lk);
    ra1 = *(const float4*)(A + (size_t)gr * lda + lk + 4);
    rb0 = bok ? *(const float4*)(B + (size_t)gc * ldb + lk) : z4;
    rb1 = bok ? *(const float4*)(B + (size_t)gc * ldb + lk + 4) : z4;
    int ktiles = K >> 4;
    for (int tt = 0; tt < ktiles; tt++) {
        __syncthreads();
        const float* pa0 = (const float*)&ra0;
        const float* pa1 = (const float*)&ra1;
        const float* pb0 = (const float*)&rb0;
        const float* pb1 = (const float*)&rb1;
#pragma unroll
        for (int j = 0; j < 4; j++) {
            As[lk + j][lrow] = pa0[j];
            As[lk + 4 + j][lrow] = pa1[j];
            Bs[lk + j][lrow] = pb0[j];
            Bs[lk + 4 + j][lrow] = pb1[j];
        }
        __syncthreads();
        if (tt + 1 < ktiles) {
            int kb = (tt + 1) * 16 + lk;
            ra0 = *(const float4*)(A + (size_t)gr * lda + kb);
            ra1 = *(const float4*)(A + (size_t)gr * lda + kb + 4);
            rb0 = bok ? *(const float4*)(B + (size_t)gc * ldb + kb) : z4;
            rb1 = bok ? *(const float4*)(B + (size_t)gc * ldb + kb + 4) : z4;
        }
        gemm_core_p(As, Bs, tx, ty, acc);
    }
#pragma unroll
    for (int i = 0; i < 8; i++) {
        int r = brow + ty * 4 + (i & 3) + ((i >> 2) << 6);
#pragma unroll
        for (int j = 0; j < 4; j++) {
            int c = bcol + tx * 4 + ((j & 1) << 1) + ((j >> 1) << 6);
            float2 v = up2(acc[i][j]);
            Cp[(size_t)r * LP + c] = v.x;
            Cp[(size_t)r * LP + c + 1] = v.y;
        }
    }
}

// ---------------- combine split parts + bias + act (+ optional row norm) ----------------
__global__ void k_comb(const float* __restrict__ bias, float* __restrict__ dst,
                       int act, int rn) {
    int i = blockIdx.x;
    int tid = threadIdx.x;
    int c = tid * 4;
    float4 o = make_float4(0.f, 0.f, 0.f, 0.f);
    if (c < LL) {
        float4 v0 = *(const float4*)&g_part0[(size_t)i * LP + c];
        float4 v1 = *(const float4*)&g_part1[(size_t)i * LP + c];
        o.x = v0.x + v1.x + bias[c];
        o.y = v0.y + v1.y + bias[c + 1];
        o.z = v0.z + v1.z + bias[c + 2];
        o.w = v0.w + v1.w + bias[c + 3];
        if (act == 1) {
            o.x = fmaxf(o.x, 0.f); o.y = fmaxf(o.y, 0.f);
            o.z = fmaxf(o.z, 0.f); o.w = fmaxf(o.w, 0.f);
        } else {
            o.x = o.x >= 0.f ? o.x : 0.01f * o.x;
            o.y = o.y >= 0.f ? o.y : 0.01f * o.y;
            o.z = o.z >= 0.f ? o.z : 0.01f * o.z;
            o.w = o.w >= 0.f ? o.w : 0.01f * o.w;
        }
    }
    *(float4*)&dst[(size_t)i * LP + c] = o;
    if (rn) {
        float s = o.x * o.x + o.y * o.y + o.z * o.z + o.w * o.w;
        int lane = tid & 31, warp = tid >> 5;
#pragma unroll
        for (int off = 16; off > 0; off >>= 1) s += __shfl_down_sync(0xffffffffu, s, off);
        __shared__ float red[4];
        if (lane == 0) red[warp] = s;
        __syncthreads();
        if (tid == 0) g_sq[i] = red[0] + red[1] + red[2] + red[3];
    }
}

// ---------------- pack [wl | wr] into g_W [512][1024] ----------------
__global__ void k_packw(const float* __restrict__ wl, const float* __restrict__ wr) {
    int n = blockIdx.x;
    for (int k = threadIdx.x; k < 1024; k += 256) {
        float v = 0.f;
        if (n < LL) {
            if (k < LL) v = wl[n * LL + k];
            else if (k >= 512 && k < 512 + LL) v = wr[n * LL + (k - 512)];
        }
        g_W[n * 1024 + k] = v;
    }
}

// ---------------- triangular Gram -> bins (smem-staged coalesced) + histogram ----------------
__global__ void __launch_bounds__(256, 2) k_gram() {
    __shared__ float As[16][128];
    __shared__ float Bs[16][128];
    __shared__ unsigned int shist[64];
    __shared__ unsigned char sbin[128][132];   // pad 132: conflict-free column reads
    int tid = threadIdx.x, tx = tid & 15, ty = tid >> 4;
    if (tid < 64) shist[tid] = 0u;
    int bid = blockIdx.x, by = 0, rem = bid;
    while (rem >= 32 - by) { rem -= 32 - by; by++; }
    int bx = by + rem;
    int brow = by * 128, bcol = bx * 128;
    int lrow = tid >> 1, lk = (tid & 1) * 8;
    int gr = brow + lrow, gc = bcol + lrow;
    ull acc[8][4];
#pragma unroll
    for (int i = 0; i < 8; i++)
#pragma unroll
        for (int j = 0; j < 4; j++) acc[i][j] = 0ULL;
    float4 ra0, ra1, rb0, rb1;
    ra0 = *(const float4*)(g_H + (size_t)gr * LP + lk);
    ra1 = *(const float4*)(g_H + (size_t)gr * LP + lk + 4);
    rb0 = *(const float4*)(g_H + (size_t)gc * LP + lk);
    rb1 = *(const float4*)(g_H + (size_t)gc * LP + lk + 4);
    for (int tt = 0; tt < 32; tt++) {
        __syncthreads();
        const float* pa0 = (const float*)&ra0;
        const float* pa1 = (const float*)&ra1;
        const float* pb0 = (const float*)&rb0;
        const float* pb1 = (const float*)&rb1;
#pragma unroll
        for (int j = 0; j < 4; j++) {
            As[lk + j][lrow] = pa0[j];
            As[lk + 4 + j][lrow] = pa1[j];
            Bs[lk + j][lrow] = pb0[j];
            Bs[lk + 4 + j][lrow] = pb1[j];
        }
        __syncthreads();
        if (tt + 1 < 32) {
            int kb = (tt + 1) * 16 + lk;
            ra0 = *(const float4*)(g_H + (size_t)gr * LP + kb);
            ra1 = *(const float4*)(g_H + (size_t)gr * LP + kb + 4);
            rb0 = *(const float4*)(g_H + (size_t)gc * LP + kb);
            rb1 = *(const float4*)(g_H + (size_t)gc * LP + kb + 4);
        }
        gemm_core_p(As, Bs, tx, ty, acc);
    }
    float sqr_[8], sqc_[8];
#pragma unroll
    for (int i = 0; i < 8; i++) sqr_[i] = g_sq[brow + ty * 4 + (i & 3) + ((i >> 2) << 6)];
#pragma unroll
    for (int j = 0; j < 8; j++) sqc_[j] = g_sq[bcol + tx * 4 + (j & 3) + ((j >> 2) << 6)];
    unsigned wgt = (bx == by) ? 1u : 2u;
#pragma unroll
    for (int i = 0; i < 8; i++) {
        int lr = ty * 4 + (i & 3) + ((i >> 2) << 6);
        int r = brow + lr;
#pragma unroll
        for (int j = 0; j < 4; j++) {
            int lcb = tx * 4 + ((j & 1) << 1) + ((j >> 1) << 6);
            float2 v = up2(acc[i][j]);
#pragma unroll
            for (int e = 0; e < 2; e++) {
                int lc = lcb + e;
                int c = bcol + lc;
                int ce = ((j >> 1) << 2) + ((j & 1) << 1) + e;
                float dot = e ? v.y : v.x;
                float d2 = fmaxf(sqr_[i] - 2.f * dot + sqc_[ce], 0.f);
                int bin;
                if (r == c) bin = 255;
                else if (d2 < 6.25f) bin = 0;
                else {
                    float d = sqrtf(d2);
                    bin = 1 + (int)((d - 2.5f) * 2.0f);
                    if (bin > 63) bin = 63;
                    float t = 2.5f + 0.5f * (float)bin;
                    if (!(d2 < t * t)) { bin++; if (bin > 63) bin = 63; }
                    else if (bin > 1) {
                        float tm = t - 0.5f;
                        if (d2 < tm * tm) bin--;
                    }
                }
                sbin[lr][lc] = (unsigned char)bin;
                unsigned msk = __match_any_sync(0xffffffffu, bin);
                int leader = __ffs(msk) - 1;
                if ((int)(tid & 31) == leader && bin < 64)
                    atomicAdd(&shist[bin], (unsigned)__popc(msk) * wgt);
            }
        }
    }
    __syncthreads();
    if (tid < 64 && shist[tid]) atomicAdd(&g_hist[tid], shist[tid]);
    // coalesced writes: normal tile (and mirrored tile if off-diagonal)
    for (int idx = tid; idx < 1024; idx += 256) {
        int row = idx >> 3, cq = (idx & 7) * 16;
        union { unsigned char b[16]; uint4 v; } u;
#pragma unroll
        for (int k = 0; k < 16; k++) u.b[k] = sbin[row][cq + k];
        *(uint4*)&g_bin[(size_t)(brow + row) * NNODE + bcol + cq] = u.v;
    }
    if (bx != by) {
        for (int idx = tid; idx < 1024; idx += 256) {
            int row = idx >> 3, cq = (idx & 7) * 16;
            union { unsigned char b[16]; uint4 v; } u;
#pragma unroll
            for (int k = 0; k < 16; k++) u.b[k] = sbin[cq + k][row];
            *(uint4*)&g_bin[(size_t)(bcol + row) * NNODE + brow + cq] = u.v;
        }
    }
}

// ---------------- pick threshold bin ----------------
__global__ void k_thr() {
    unsigned int cum = 0;
    int k = 0;
    for (k = 0; k < 64; k++) {
        cum += g_hist[k];
        if ((float)cum >= 409.6f) break;
    }
    if (k > 63) k = 63;
    g_kthr = k;
}

// ---------------- adjacency build: 16 bytes/thread, 2 barriers ----------------
__global__ void __launch_bounds__(256) k_adj() {
    int i = blockIdx.x;
    int tid = threadIdx.x, lane = tid & 31, warp = tid >> 5;
    int kthr = g_kthr;
    uint4 v = ((const uint4*)(g_bin + (size_t)i * NNODE))[tid];
    unsigned words[4] = {v.x, v.y, v.z, v.w};
    int cnt = 0;
    unsigned hm = 0;
#pragma unroll
    for (int wq = 0; wq < 4; wq++)
#pragma unroll
        for (int bq = 0; bq < 4; bq++) {
            int bv = (int)((words[wq] >> (bq * 8)) & 0xffu);
            int u = wq * 4 + bq;
            bool h = (bv <= kthr);
            cnt += h ? 1 : 0;
            hm |= (h ? 1u : 0u) << u;
        }
    int sc = cnt;
#pragma unroll
    for (int o = 1; o < 32; o <<= 1) {
        int t2 = __shfl_up_sync(0xffffffffu, sc, o);
        if (lane >= o) sc += t2;
    }
    __shared__ int wtot[8], wbase[8];
    if (lane == 31) wtot[warp] = sc;
    int excl = sc - cnt;
    __syncthreads();
    if (tid == 0) {
        int bse = 0;
        for (int w = 0; w < 8; w++) { wbase[w] = bse; bse += wtot[w]; }
        float d = (float)bse;
        g_deg[i] = bse;
        g_invS[i] = 1.f / fmaxf(d, 1.f);
        g_invC[i] = 1.f / (d + 1.f);
    }
    __syncthreads();
    int pos = wbase[warp] + excl;
    int* out = g_adj + (size_t)i * NNODE;
    int j0 = tid * 16;
#pragma unroll
    for (int u = 0; u < 16; u++)
        if ((hm >> u) & 1u) out[pos++] = j0 + u;
}

// ---------------- sparse AH gather ----------------
__global__ void __launch_bounds__(128) k_gather() {
    int i = blockIdx.x;
    int deg = g_deg[i];
    int f = threadIdx.x * 4;
    const int* adj = g_adj + (size_t)i * NNODE;
    float4 acc = make_float4(0.f, 0.f, 0.f, 0.f);
    for (int e = 0; e < deg; e++) {
        int j = adj[e];
        float4 h = *(const float4*)&g_H[(size_t)j * LP + f];
        acc.x += h.x; acc.y += h.y; acc.z += h.z; acc.w += h.w;
    }
    *(float4*)&g_AH[(size_t)i * LP + f] = acc;
    float s = g_invS[i];
    float4 an = make_float4(acc.x * s, acc.y * s, acc.z * s, acc.w * s);
    *(float4*)&g_AHn[(size_t)i * LP + f] = an;
}

// ---------------- BatchNorm: coalesced partials -> finalize -> apply ----------------
__global__ void k_bnsum() {
    int f = threadIdx.x, b = blockIdx.x;
    float s = 0.f, s2 = 0.f;
    for (int n = b; n < NNODE; n += 64) {
        float v = g_Zp[(size_t)n * LP + f];
        s += v;
        s2 += v * v;
    }
    g_bnp[b * 512 + f] = s;
    g_bnp2[b * 512 + f] = s2;
}
__global__ void k_bnfin() {
    int f = threadIdx.x;
    float s = 0.f, s2 = 0.f;
    for (int b = 0; b < 64; b++) { s += g_bnp[b * 512 + f]; s2 += g_bnp2[b * 512 + f]; }
    float m = s / (float)NNODE;
    float var = fmaxf(s2 / (float)NNODE - m * m, 0.f);
    g_bnm[f] = m;
    g_bni[f] = 1.f / sqrtf(var + 1e-5f);
}
__global__ void k_bnapply(const float* __restrict__ gw, const float* __restrict__ gb) {
    int f = threadIdx.x, b = blockIdx.x;
    if (f >= LL) return;
    float m = g_bnm[f], inv = g_bni[f], gf = gw[f], bf = gb[f];
    for (int n = b; n < NNODE; n += 64) {
        float v = g_Zp[(size_t)n * LP + f];
        g_Zp[(size_t)n * LP + f] = (v - m) * inv * gf + bf;
    }
}

// ---------------- ClusterGCN assignment (register-cached rows) ----------------
__global__ void k_cluster(const float* __restrict__ wout, const float* __restrict__ bout,
                          const float* __restrict__ wroot) {
    int warp = threadIdx.x >> 5, lane = threadIdx.x & 31;
    int i = blockIdx.x * 4 + warp;
    float invc = g_invC[i];
    float hv[16], ag[16];
#pragma unroll
    for (int u = 0; u < 16; u++) {
        int k = lane + 32 * u;
        float h = g_H[(size_t)i * LP + k];        // pads are zero
        float a = g_AH[(size_t)i * LP + k];
        hv[u] = h;
        ag[u] = (a + h) * invc;
    }
    float lg[5];
#pragma unroll
    for (int c = 0; c < 5; c++) {
        float acc = 0.f;
#pragma unroll
        for (int u = 0; u < 16; u++) {
            int k = lane + 32 * u;
            if (k < LL)
                acc += ag[u] * __ldg(&wout[c * LL + k]) + hv[u] * __ldg(&wroot[c * LL + k]);
        }
#pragma unroll
        for (int o = 16; o > 0; o >>= 1) acc += __shfl_down_sync(0xffffffffu, acc, o);
        acc = __shfl_sync(0xffffffffu, acc, 0);
        lg[c] = acc + bout[c];
    }
    if (lane == 0) {
        float m = lg[0];
#pragma unroll
        for (int c = 1; c < 5; c++) m = fmaxf(m, lg[c]);
        float e[5], s = 0.f;
#pragma unroll
        for (int c = 0; c < 5; c++) { e[c] = expf(lg[c] - m); s += e[c]; }
#pragma unroll
        for (int c = 0; c < 5; c++) g_S[(size_t)i * 8 + c] = e[c] / s;
    }
}

// ---------------- T = A @ S via adjacency ----------------
__global__ void __launch_bounds__(256) k_ts() {
    int row = blockIdx.x * 8 + (threadIdx.x >> 5);
    int lane = threadIdx.x & 31;
    int deg = g_deg[row];
    const int* adj = g_adj + (size_t)row * NNODE;
    float a0 = 0.f, a1 = 0.f, a2 = 0.f, a3 = 0.f, a4 = 0.f;
    for (int e = lane; e < deg; e += 32) {
        int j = adj[e];
        const float* s = g_S + (size_t)j * 8;
        a0 += s[0]; a1 += s[1]; a2 += s[2]; a3 += s[3]; a4 += s[4];
    }
#pragma unroll
    for (int o = 16; o > 0; o >>= 1) {
        a0 += __shfl_down_sync(0xffffffffu, a0, o);
        a1 += __shfl_down_sync(0xffffffffu, a1, o);
        a2 += __shfl_down_sync(0xffffffffu, a2, o);
        a3 += __shfl_down_sync(0xffffffffu, a3, o);
        a4 += __shfl_down_sync(0xffffffffu, a4, o);
    }
    if (lane == 0) {
        g_T[(size_t)row * 8 + 0] = a0;
        g_T[(size_t)row * 8 + 1] = a1;
        g_T[(size_t)row * 8 + 2] = a2;
        g_T[(size_t)row * 8 + 3] = a3;
        g_T[(size_t)row * 8 + 4] = a4;
    }
}

// ---------------- coar partials = S^T @ Z over n-chunks ----------------
__global__ void k_coar() {
    int fx = threadIdx.x & 63, ny = threadIdx.x >> 6;
    int f = blockIdx.x * 64 + fx;
    int n0 = blockIdx.y * 512;
    float acc[5] = {0.f, 0.f, 0.f, 0.f, 0.f};
    for (int n = n0 + ny; n < n0 + 512; n += 4) {
        float z = g_Zp[(size_t)n * LP + f];
        const float* s = g_S + (size_t)n * 8;
#pragma unroll
        for (int c = 0; c < 5; c++) acc[c] += s[c] * z;
    }
    __shared__ float red[4][64][5];
#pragma unroll
    for (int c = 0; c < 5; c++) red[ny][fx][c] = acc[c];
    __syncthreads();
    if (ny == 0) {
#pragma unroll
        for (int c = 0; c < 5; c++)
            g_cpart[blockIdx.y][c * 512 + f] =
                red[0][fx][c] + red[1][fx][c] + red[2][fx][c] + red[3][fx][c];
    }
}
__global__ void k_coarfin() {
    int c = blockIdx.x, f = threadIdx.x;
    float s = 0.f;
    for (int b = 0; b < 8; b++) s += g_cpart[b][c * 512 + f];
    g_coar[c * LP + f] = s;
}

// ---------------- Ac = S^T @ T ----------------
__global__ void k_ac() {
    int tid = threadIdx.x, lane = tid & 31, warp = tid >> 5;
    float acc[25];
#pragma unroll
    for (int q = 0; q < 25; q++) acc[q] = 0.f;
    for (int n = tid; n < NNODE; n += 256) {
        float sv[5], tv[5];
#pragma unroll
        for (int c = 0; c < 5; c++) { sv[c] = g_S[(size_t)n * 8 + c]; tv[c] = g_T[(size_t)n * 8 + c]; }
#pragma unroll
        for (int a = 0; a < 5; a++)
#pragma unroll
            for (int b = 0; b < 5; b++) acc[a * 5 + b] += sv[a] * tv[b];
    }
#pragma unroll
    for (int q = 0; q < 25; q++)
#pragma unroll
        for (int o = 16; o > 0; o >>= 1) acc[q] += __shfl_down_sync(0xffffffffu, acc[q], o);
    __shared__ float red[8][25];
    if (lane == 0)
#pragma unroll
        for (int q = 0; q < 25; q++) red[warp][q] = acc[q];
    __syncthreads();
    if (tid < 25) {
        float s = 0.f;
#pragma unroll
        for (int w = 0; w < 8; w++) s += red[w][tid];
        g_Ac[tid] = s;
    }
}

// ---------------- final: coarse SAGE + BN + pool + MLP + softmax ----------------
__global__ void __launch_bounds__(512) k_final(
    const float* __restrict__ wl, const float* __restrict__ bl, const float* __restrict__ wr,
    const float* __restrict__ bng, const float* __restrict__ bnb,
    const float* __restrict__ l1w, const float* __restrict__ l1b,
    const float* __restrict__ l2w, const float* __restrict__ l2b,
    float* __restrict__ out, int out_size) {
    __shared__ float Mc[25];
    __shared__ float invdc[5];
    __shared__ float neigh[5 * 500];
    __shared__ float pre[5 * 500];
    __shared__ float h1[5 * 250];
    __shared__ float lg[5];
    int tid = threadIdx.x;
    if (tid == 0) {
        float mean = 0.f;
        for (int q = 0; q < 25; q++) mean += g_Ac[q];
        mean *= (1.f / 25.f);
        for (int q = 0; q < 25; q++)
            Mc[q] = (g_Ac[q] >= mean && g_Ac[q] > 0.f) ? 1.f : 0.f;
        for (int i = 0; i < 5; i++) {
            float d = 0.f;
            for (int j = 0; j < 5; j++) d += Mc[i * 5 + j];
            invdc[i] = 1.f / fmaxf(d, 1.f);
        }
    }
    __syncthreads();
    for (int idx = tid; idx < 2500; idx += 512) {
        int i = idx / 500, f = idx % 500;
        float a = 0.f;
#pragma unroll
        for (int j = 0; j < 5; j++) a += Mc[i * 5 + j] * g_coar[j * LP + f];
        neigh[idx] = a * invdc[i];
    }
    __syncthreads();
    for (int idx = tid; idx < 2500; idx += 512) {
        int i = idx / 500, f = idx % 500;
        const float* wlr = wl + f * 500;
        const float* wrr = wr + f * 500;
        float a0 = 0.f, a1 = 0.f, a2 = 0.f, a3 = 0.f;
        for (int k = 0; k < 500; k += 4) {
            a0 += neigh[i * 500 + k] * wlr[k] + g_coar[i * LP + k] * wrr[k];
            a1 += neigh[i * 500 + k + 1] * wlr[k + 1] + g_coar[i * LP + k + 1] * wrr[k + 1];
            a2 += neigh[i * 500 + k + 2] * wlr[k + 2] + g_coar[i * LP + k + 2] * wrr[k + 2];
            a3 += neigh[i * 500 + k + 3] * wlr[k + 3] + g_coar[i * LP + k + 3] * wrr[k + 3];
        }
        float acc = bl[f] + ((a0 + a1) + (a2 + a3));
        pre[idx] = (acc >= 0.f) ? acc : 0.01f * acc;
    }
    __syncthreads();
    for (int f = tid; f < 500; f += 512) {
        float m = 0.f;
#pragma unroll
        for (int i = 0; i < 5; i++) m += pre[i * 500 + f];
        m *= 0.2f;
        float v = 0.f;
#pragma unroll
        for (int i = 0; i < 5; i++) { float d = pre[i * 500 + f] - m; v += d * d; }
        v *= 0.2f;
        float sd = sqrtf(v + 1e-5f);
        float gf = bng[f], bf = bnb[f];
#pragma unroll
        for (int i = 0; i < 5; i++)
            pre[i * 500 + f] = (pre[i * 500 + f] - m) / sd * gf + bf;
    }
    __syncthreads();
    for (int idx = tid; idx < 2500; idx += 512) {
        int i = idx / 500, f = idx % 500;
        float mx = -1e30f;
#pragma unroll
        for (int j = 0; j < 5; j++)
            if (Mc[i * 5 + j] > 0.f || j == i) mx = fmaxf(mx, pre[j * 500 + f]);
        neigh[idx] = mx;
    }
    __syncthreads();
    for (int idx = tid; idx < 1250; idx += 512) {
        int i = idx / 250, o = idx % 250;
        const float* w = l1w + o * 500;
        float a0 = 0.f, a1 = 0.f, a2 = 0.f, a3 = 0.f;
        for (int k = 0; k < 500; k += 4) {
            a0 += neigh[i * 500 + k] * w[k];
            a1 += neigh[i * 500 + k + 1] * w[k + 1];
            a2 += neigh[i * 500 + k + 2] * w[k + 2];
            a3 += neigh[i * 500 + k + 3] * w[k + 3];
        }
        float acc = l1b[o] + ((a0 + a1) + (a2 + a3));
        h1[idx] = (acc >= 0.f) ? acc : 0.01f * acc;
    }
    __syncthreads();
    if (tid < 5) {
        float acc = l2b[0];
        for (int k = 0; k < 250; k++) acc += h1[tid * 250 + k] * l2w[k];
        lg[tid] = (acc >= 0.f) ? acc : 0.01f * acc;
    }
    __syncthreads();
    if (tid == 0) {
        float m = lg[0];
        for (int i = 1; i < 5; i++) m = fmaxf(m, lg[i]);
        float e[5], s = 0.f;
        for (int i = 0; i < 5; i++) { e[i] = expf(lg[i] - m); s += e[i]; }
        float p = 0.f;
        for (int i = 0; i < 5; i++) p = fmaxf(p, e[i] / s);
        out[0] = p;
        if (out_size > 1) out[1] = (p >= 0.5f) ? 1.f : 0.f;
    }
}

// ---------------- host launcher ----------------
static float* symaddr(const void* sym) {
    void* p = nullptr;
    cudaGetSymbolAddress(&p, sym);
    return (float*)p;
}

extern "C" void kernel_launch(void* const* d_in, const int* in_sizes, int n_in,
                              void* d_out, int out_size) {
    const float* x    = (const float*)d_in[0];
    const float* c1w  = (const float*)d_in[1];
    const float* c1b  = (const float*)d_in[2];
    const float* c2w  = (const float*)d_in[3];
    const float* c2b  = (const float*)d_in[4];
    const float* fcw  = (const float*)d_in[5];
    const float* fcb  = (const float*)d_in[6];
    const float* swl  = (const float*)d_in[7];
    const float* sbl  = (const float*)d_in[8];
    const float* swr  = (const float*)d_in[9];
    const float* bng  = (const float*)d_in[10];
    const float* bnb  = (const float*)d_in[11];
    const float* cgwo = (const float*)d_in[12];
    const float* cgbo = (const float*)d_in[13];
    const float* cgwr = (const float*)d_in[14];
    const float* l1w  = (const float*)d_in[15];
    const float* l1b  = (const float*)d_in[16];
    const float* l2w  = (const float*)d_in[17];
    const float* l2b  = (const float*)d_in[18];
    float* out = (float*)d_out;

    float* pF   = symaddr(g_F);
    float* pH   = symaddr(g_H);
    float* pAHn = symaddr(g_AHn);
    float* pZp  = symaddr(g_Zp);
    float* pW   = symaddr(g_W);

    const int c2_smem = C2_IMGS * 3840 * (int)sizeof(float);
    cudaFuncSetAttribute(k_conv2, cudaFuncAttributeMaxDynamicSharedMemorySize, c2_smem);

    k_zero<<<1, 64>>>();
    k_packw<<<512, 256>>>(swl, swr);
    k_conv1<<<NNODE, 384>>>(x, c1w, c1b);
    k_conv2<<<(NNODE + C2_IMGS - 1) / C2_IMGS, 512, c2_smem>>>(c2w, c2b);
    {   // fc: H = relu(F @ fcw^T + fcb), split-K 2 (400+400); fused row norms
        dim3 g(4, 32, 2);
        k_gemm_sk<<<g, 256>>>(pF, pF + 400, FEAT, fcw, fcw + 400, FEAT, 400, LL);
        k_comb<<<NNODE, 128>>>(fcb, pH, 1, 1);
    }
    k_gram<<<528, 256>>>();
    k_thr<<<1, 1>>>();
    k_adj<<<NNODE, 256>>>();
    k_gather<<<NNODE, 128>>>();
    {   // SAGE: Zp = leaky(AHn@wl^T + H@wr^T + bl), two slots of packed W
        dim3 g(4, 32, 2);
        k_gemm_sk<<<g, 256>>>(pAHn, pH, LP, pW, pW + 512, 1024, 512, LP);
        k_comb<<<NNODE, 128>>>(sbl, pZp, 2, 0);
    }
    k_bnsum<<<64, 512>>>();
    k_bnfin<<<1, 512>>>();
    k_bnapply<<<64, 512>>>(bng, bnb);
    k_cluster<<<NNODE / 4, 128>>>(cgwo, cgbo, cgwr);
    k_ts<<<NNODE / 8, 256>>>();
    {
        dim3 g(8, 8);
        k_coar<<<g, 256>>>();
        k_coarfin<<<5, 512>>>();
    }
    k_ac<<<1, 256>>>();
    k_final<<<1, 512>>>(swl, sbl, swr, bng, bnb, l1w, l1b, l2w, l2b, out, out_size);
}

// round 7
// speedup vs baseline: 2.9305x; 1.0028x over previous
#include <cuda_runtime.h>
#include <math.h>

#define NNODE 4096
#define LL 500
#define LP 512
#define FEAT 800

typedef unsigned long long ull;

// ---------------- scratch (device globals; no allocation) ----------------
__device__ float g_P1[NNODE * 3840];          // conv1+pool out, padded [N,20,12,16]
__device__ float g_F[NNODE * FEAT];           // conv2+pool out [N,800]
__device__ float g_H[NNODE * LP];             // fc+relu features [N,500] (LD=512, pads zero)
__device__ float g_sq[NNODE];                 // row norms of H
__device__ unsigned char g_bin[(size_t)NNODE * NNODE]; // distance bin per pair
__device__ unsigned int g_hist[64];           // distance histogram
__device__ int   g_kthr;                      // chosen threshold bin
__device__ int   g_adj[(size_t)NNODE * NNODE];// adjacency lists
__device__ int   g_deg[NNODE];
__device__ float g_invS[NNODE];               // 1/max(deg,1)
__device__ float g_invC[NNODE];               // 1/(deg+1)
__device__ float g_AH[NNODE * LP];            // A @ H (raw)
__device__ float g_AHn[NNODE * LP];           // (A @ H)/deg
__device__ float g_W[512 * 1024];             // packed [wl | wr]
__device__ float g_part0[(size_t)NNODE * LP]; // split-gemm partials
__device__ float g_part1[(size_t)NNODE * LP];
__device__ float g_Zp[NNODE * LP];            // SAGE out -> Z (in place)
__device__ float g_S[NNODE * 8];              // soft assignment [N,5]
__device__ float g_T[NNODE * 8];              // A @ S
__device__ float g_cpart[8][5 * 512];         // coar partials
__device__ float g_coar[5 * LP];              // S^T @ Z
__device__ float g_Ac[25];                    // S^T A S
__device__ float g_bnp[64 * 512];             // BN partial sums
__device__ float g_bnp2[64 * 512];
__device__ float g_bnm[512];
__device__ float g_bni[512];

__global__ void k_zero() {
    if (threadIdx.x < 64) g_hist[threadIdx.x] = 0u;
}

// ---------------- packed fp32x2 helpers ----------------
__device__ __forceinline__ void fma2(ull &d, ull a, ull b) {
    asm("fma.rn.f32x2 %0, %1, %2, %0;" : "+l"(d) : "l"(a), "l"(b));
}
__device__ __forceinline__ ull pk2(float a, float b) {
    ull r;
    asm("mov.b64 %0, {%1, %2};" : "=l"(r) : "f"(a), "f"(b));
    return r;
}
__device__ __forceinline__ ull dup2(float a) { return pk2(a, a); }
__device__ __forceinline__ float2 up2(ull v) {
    float2 r;
    r.x = __uint_as_float((unsigned)v);
    r.y = __uint_as_float((unsigned)(v >> 32));
    return r;
}

// compute core: 128x128 tile, BK=16, plain A (packed after load), acc 8 rows x 4 col-pairs
__device__ __forceinline__ void gemm_core_p(const float (*As)[128], const float (*Bs)[128],
                                            int tx, int ty, ull acc[8][4]) {
#pragma unroll
    for (int kk = 0; kk < 16; kk++) {
        float4 a0 = *(const float4*)&As[kk][4 * ty];
        float4 a1 = *(const float4*)&As[kk][4 * ty + 64];
        ulonglong2 B01 = *(const ulonglong2*)&Bs[kk][4 * tx];
        ulonglong2 B23 = *(const ulonglong2*)&Bs[kk][4 * tx + 64];
        ull av[8] = {dup2(a0.x), dup2(a0.y), dup2(a0.z), dup2(a0.w),
                     dup2(a1.x), dup2(a1.y), dup2(a1.z), dup2(a1.w)};
        ull bv[4] = {B01.x, B01.y, B23.x, B23.y};
#pragma unroll
        for (int i = 0; i < 8; i++)
#pragma unroll
            for (int j = 0; j < 4; j++) fma2(acc[i][j], av[i], bv[j]);
    }
}

// ---------------- conv1 (1->20,5x5)+relu+pool, channel-paired f32x2 ----------------
__global__ void __launch_bounds__(384) k_conv1(const float* __restrict__ x,
                                               const float* __restrict__ w,
                                               const float* __restrict__ b) {
    int n = blockIdx.x;
    __shared__ __align__(16) float simg[784];
    __shared__ float sw[500];
    const float* xi = x + (size_t)n * 784;
    for (int i = threadIdx.x; i < 784; i += 384) simg[i] = xi[i];
    for (int i = threadIdx.x; i < 500; i += 384) sw[i] = w[i];
    __syncthreads();
    int t = threadIdx.x;
    if (t >= 360) return;
    int p = t / 36, reg = t % 36;
    int c0 = p * 2;
    int ry = (reg / 6) * 2, rx = (reg % 6) * 2;
    ull wp[25];
#pragma unroll
    for (int u = 0; u < 25; u++) wp[u] = pk2(sw[c0 * 25 + u], sw[c0 * 25 + 25 + u]);
    ull a2[4][4];
#pragma unroll
    for (int i = 0; i < 4; i++)
#pragma unroll
        for (int j = 0; j < 4; j++) a2[i][j] = 0ULL;
#pragma unroll
    for (int rr = 0; rr < 8; rr++) {
        const float* sp = simg + (2 * ry + rr) * 28 + 2 * rx;
        float4 q0 = *(const float4*)sp;
        float4 q1 = *(const float4*)(sp + 4);
        ull rd[8] = {dup2(q0.x), dup2(q0.y), dup2(q0.z), dup2(q0.w),
                     dup2(q1.x), dup2(q1.y), dup2(q1.z), dup2(q1.w)};
        int iy0 = rr - 4 > 0 ? rr - 4 : 0;
        int iy1 = rr < 3 ? rr : 3;
#pragma unroll 4
        for (int iy = iy0; iy <= iy1; iy++) {
            int ky = rr - iy;
#pragma unroll
            for (int ix = 0; ix < 4; ix++)
#pragma unroll
                for (int kx = 0; kx < 5; kx++)
                    fma2(a2[iy][ix], rd[ix + kx], wp[ky * 5 + kx]);
        }
    }
    float b0 = b[c0], b1 = b[c0 + 1];
#pragma unroll
    for (int py = 0; py < 2; py++)
#pragma unroll
        for (int px = 0; px < 2; px++) {
            float2 v00 = up2(a2[2 * py][2 * px]), v01 = up2(a2[2 * py][2 * px + 1]);
            float2 v10 = up2(a2[2 * py + 1][2 * px]), v11 = up2(a2[2 * py + 1][2 * px + 1]);
            float m0 = fmaxf(fmaxf(v00.x, v01.x), fmaxf(v10.x, v11.x));
            float m1 = fmaxf(fmaxf(v00.y, v01.y), fmaxf(v10.y, v11.y));
            int yy = ry + py, xx = rx + px;
            g_P1[(size_t)n * 3840 + c0 * 192 + yy * 16 + xx] = fmaxf(m0 + b0, 0.f);
            g_P1[(size_t)n * 3840 + (c0 + 1) * 192 + yy * 16 + xx] = fmaxf(m1 + b1, 0.f);
        }
}

// ---------------- conv2: 5 images/block, 500 active lanes, channel-paired f32x2 ----------------
#define C2_IMGS 5
__global__ void __launch_bounds__(512, 1) k_conv2(const float* __restrict__ w,
                                                  const float* __restrict__ b) {
    extern __shared__ __align__(16) float sp5[];   // [5][3840]
    int n0 = blockIdx.x * C2_IMGS;
    for (int v = threadIdx.x; v < 960 * C2_IMGS; v += 512) {
        int img = v / 960, idx = v % 960;
        if (n0 + img < NNODE)
            ((float4*)(sp5 + img * 3840))[idx] =
                ((const float4*)(g_P1 + (size_t)(n0 + img) * 3840))[idx];
    }
    __syncthreads();
    int t = threadIdx.x;
    if (t >= 100 * C2_IMGS) return;
    int img = t / 100, t2 = t % 100;
    int n = n0 + img;
    if (n >= NNODE) return;
    int cp = t2 >> 2, q = t2 & 3;
    int c0 = cp * 2;
    int ry = (q >> 1) * 2, rx = (q & 1) * 2;
    ull a2[4][4];
#pragma unroll
    for (int i = 0; i < 4; i++)
#pragma unroll
        for (int j = 0; j < 4; j++) a2[i][j] = 0ULL;
    const float* sp = sp5 + img * 3840;
    for (int ic = 0; ic < 20; ic++) {
        ull wp[25];
        const float* w0 = w + c0 * 500 + ic * 25;
#pragma unroll
        for (int u = 0; u < 25; u++) wp[u] = pk2(__ldg(w0 + u), __ldg(w0 + 500 + u));
#pragma unroll
        for (int rr = 0; rr < 8; rr++) {
            const float* rp = sp + ic * 192 + (2 * ry + rr) * 16 + 2 * rx;
            float4 q0 = *(const float4*)rp;
            float4 q1 = *(const float4*)(rp + 4);
            ull rd[8] = {dup2(q0.x), dup2(q0.y), dup2(q0.z), dup2(q0.w),
                         dup2(q1.x), dup2(q1.y), dup2(q1.z), dup2(q1.w)};
            int iy0 = rr - 4 > 0 ? rr - 4 : 0;
            int iy1 = rr < 3 ? rr : 3;
#pragma unroll 4
            for (int iy = iy0; iy <= iy1; iy++) {
                int ky = rr - iy;
#pragma unroll
                for (int ix = 0; ix < 4; ix++)
#pragma unroll
                    for (int kx = 0; kx < 5; kx++)
                        fma2(a2[iy][ix], rd[ix + kx], wp[ky * 5 + kx]);
            }
        }
    }
    float b0 = b[c0], b1 = b[c0 + 1];
#pragma unroll
    for (int py = 0; py < 2; py++)
#pragma unroll
        for (int px = 0; px < 2; px++) {
            float2 v00 = up2(a2[2 * py][2 * px]), v01 = up2(a2[2 * py][2 * px + 1]);
            float2 v10 = up2(a2[2 * py + 1][2 * px]), v11 = up2(a2[2 * py + 1][2 * px + 1]);
            float m0 = fmaxf(fmaxf(v00.x, v01.x), fmaxf(v10.x, v11.x));
            float m1 = fmaxf(fmaxf(v00.y, v01.y), fmaxf(v10.y, v11.y));
            g_F[(size_t)n * 800 + c0 * 16 + (ry + py) * 4 + rx + px] = fmaxf(m0 + b0, 0.f);
            g_F[(size_t)n * 800 + (c0 + 1) * 16 + (ry + py) * 4 + rx + px] = fmaxf(m1 + b1, 0.f);
        }
}

// ---------------- split NT GEMM: z slot picks (A,B) pair, raw partial out ----------------
__global__ void __launch_bounds__(256, 2) k_gemm_sk(
    const float* __restrict__ A0, const float* __restrict__ A1, int lda,
    const float* __restrict__ B0, const float* __restrict__ B1, int ldb,
    int K, int Nc) {
    __shared__ float As[16][128];
    __shared__ float Bs[16][128];
    int tid = threadIdx.x, tx = tid & 15, ty = tid >> 4;
    int zz = blockIdx.z;
    const float* A = zz ? A1 : A0;
    const float* B = zz ? B1 : B0;
    float* Cp = zz ? g_part1 : g_part0;
    int brow = blockIdx.y * 128, bcol = blockIdx.x * 128;
    int lrow = tid >> 1, lk = (tid & 1) * 8;
    int gr = brow + lrow, gc = bcol + lrow;
    int bok = (gc < Nc);
    ull acc[8][4];
#pragma unroll
    for (int i = 0; i < 8; i++)
#pragma unroll
        for (int j = 0; j < 4; j++) acc[i][j] = 0ULL;
    const float4 z4 = make_float4(0.f, 0.f, 0.f, 0.f);
    float4 ra0, ra1, rb0, rb1;
    ra0 = *(const float4*)(A + (size_t)gr * lda + lk);
    ra1 = *(const float4*)(A + (size_t)gr * lda + lk + 4);
    rb0 = bok ? *(const float4*)(B + (size_t)gc * ldb + lk) : z4;
    rb1 = bok ? *(const float4*)(B + (size_t)gc * ldb + lk + 4) : z4;
    int ktiles = K >> 4;
    for (int tt = 0; tt < ktiles; tt++) {
        __syncthreads();
        const float* pa0 = (const float*)&ra0;
        const float* pa1 = (const float*)&ra1;
        const float* pb0 = (const float*)&rb0;
        const float* pb1 = (const float*)&rb1;
#pragma unroll
        for (int j = 0; j < 4; j++) {
            As[lk + j][lrow] = pa0[j];
            As[lk + 4 + j][lrow] = pa1[j];
            Bs[lk + j][lrow] = pb0[j];
            Bs[lk + 4 + j][lrow] = pb1[j];
        }
        __syncthreads();
        if (tt + 1 < ktiles) {
            int kb = (tt + 1) * 16 + lk;
            ra0 = *(const float4*)(A + (size_t)gr * lda + kb);
            ra1 = *(const float4*)(A + (size_t)gr * lda + kb + 4);
            rb0 = bok ? *(const float4*)(B + (size_t)gc * ldb + kb) : z4;
            rb1 = bok ? *(const float4*)(B + (size_t)gc * ldb + kb + 4) : z4;
        }
        gemm_core_p(As, Bs, tx, ty, acc);
    }
#pragma unroll
    for (int i = 0; i < 8; i++) {
        int r = brow + ty * 4 + (i & 3) + ((i >> 2) << 6);
#pragma unroll
        for (int j = 0; j < 4; j++) {
            int c = bcol + tx * 4 + ((j & 1) << 1) + ((j >> 1) << 6);
            float2 v = up2(acc[i][j]);
            Cp[(size_t)r * LP + c] = v.x;
            Cp[(size_t)r * LP + c + 1] = v.y;
        }
    }
}

// ---------------- combine split parts + bias + act (+ optional row norm) ----------------
__global__ void k_comb(const float* __restrict__ bias, float* __restrict__ dst,
                       int act, int rn) {
    int i = blockIdx.x;
    int tid = threadIdx.x;
    int c = tid * 4;
    float4 o = make_float4(0.f, 0.f, 0.f, 0.f);
    if (c < LL) {
        float4 v0 = *(const float4*)&g_part0[(size_t)i * LP + c];
        float4 v1 = *(const float4*)&g_part1[(size_t)i * LP + c];
        o.x = v0.x + v1.x + bias[c];
        o.y = v0.y + v1.y + bias[c + 1];
        o.z = v0.z + v1.z + bias[c + 2];
        o.w = v0.w + v1.w + bias[c + 3];
        if (act == 1) {
            o.x = fmaxf(o.x, 0.f); o.y = fmaxf(o.y, 0.f);
            o.z = fmaxf(o.z, 0.f); o.w = fmaxf(o.w, 0.f);
        } else {
            o.x = o.x >= 0.f ? o.x : 0.01f * o.x;
            o.y = o.y >= 0.f ? o.y : 0.01f * o.y;
            o.z = o.z >= 0.f ? o.z : 0.01f * o.z;
            o.w = o.w >= 0.f ? o.w : 0.01f * o.w;
        }
    }
    *(float4*)&dst[(size_t)i * LP + c] = o;
    if (rn) {
        float s = o.x * o.x + o.y * o.y + o.z * o.z + o.w * o.w;
        int lane = tid & 31, warp = tid >> 5;
#pragma unroll
        for (int off = 16; off > 0; off >>= 1) s += __shfl_down_sync(0xffffffffu, s, off);
        __shared__ float red[4];
        if (lane == 0) red[warp] = s;
        __syncthreads();
        if (tid == 0) g_sq[i] = red[0] + red[1] + red[2] + red[3];
    }
}

// ---------------- pack [wl | wr] into g_W [512][1024] ----------------
__global__ void k_packw(const float* __restrict__ wl, const float* __restrict__ wr) {
    int n = blockIdx.x;
    for (int k = threadIdx.x; k < 1024; k += 256) {
        float v = 0.f;
        if (n < LL) {
            if (k < LL) v = wl[n * LL + k];
            else if (k >= 512 && k < 512 + LL) v = wr[n * LL + (k - 512)];
        }
        g_W[n * 1024 + k] = v;
    }
}

// ---------------- triangular Gram -> bins (smem-staged coalesced) + histogram ----------------
__global__ void __launch_bounds__(256, 2) k_gram() {
    __shared__ float As[16][128];
    __shared__ float Bs[16][128];
    __shared__ unsigned int shist[64];
    __shared__ unsigned char sbin[128][132];   // pad 132: conflict-free column reads
    int tid = threadIdx.x, tx = tid & 15, ty = tid >> 4;
    if (tid < 64) shist[tid] = 0u;
    int bid = blockIdx.x, by = 0, rem = bid;
    while (rem >= 32 - by) { rem -= 32 - by; by++; }
    int bx = by + rem;
    int brow = by * 128, bcol = bx * 128;
    int lrow = tid >> 1, lk = (tid & 1) * 8;
    int gr = brow + lrow, gc = bcol + lrow;
    ull acc[8][4];
#pragma unroll
    for (int i = 0; i < 8; i++)
#pragma unroll
        for (int j = 0; j < 4; j++) acc[i][j] = 0ULL;
    float4 ra0, ra1, rb0, rb1;
    ra0 = *(const float4*)(g_H + (size_t)gr * LP + lk);
    ra1 = *(const float4*)(g_H + (size_t)gr * LP + lk + 4);
    rb0 = *(const float4*)(g_H + (size_t)gc * LP + lk);
    rb1 = *(const float4*)(g_H + (size_t)gc * LP + lk + 4);
    for (int tt = 0; tt < 32; tt++) {
        __syncthreads();
        const float* pa0 = (const float*)&ra0;
        const float* pa1 = (const float*)&ra1;
        const float* pb0 = (const float*)&rb0;
        const float* pb1 = (const float*)&rb1;
#pragma unroll
        for (int j = 0; j < 4; j++) {
            As[lk + j][lrow] = pa0[j];
            As[lk + 4 + j][lrow] = pa1[j];
            Bs[lk + j][lrow] = pb0[j];
            Bs[lk + 4 + j][lrow] = pb1[j];
        }
        __syncthreads();
        if (tt + 1 < 32) {
            int kb = (tt + 1) * 16 + lk;
            ra0 = *(const float4*)(g_H + (size_t)gr * LP + kb);
            ra1 = *(const float4*)(g_H + (size_t)gr * LP + kb + 4);
            rb0 = *(const float4*)(g_H + (size_t)gc * LP + kb);
            rb1 = *(const float4*)(g_H + (size_t)gc * LP + kb + 4);
        }
        gemm_core_p(As, Bs, tx, ty, acc);
    }
    float sqr_[8], sqc_[8];
#pragma unroll
    for (int i = 0; i < 8; i++) sqr_[i] = g_sq[brow + ty * 4 + (i & 3) + ((i >> 2) << 6)];
#pragma unroll
    for (int j = 0; j < 8; j++) sqc_[j] = g_sq[bcol + tx * 4 + (j & 3) + ((j >> 2) << 6)];
    unsigned wgt = (bx == by) ? 1u : 2u;
#pragma unroll
    for (int i = 0; i < 8; i++) {
        int lr = ty * 4 + (i & 3) + ((i >> 2) << 6);
        int r = brow + lr;
#pragma unroll
        for (int j = 0; j < 4; j++) {
            int lcb = tx * 4 + ((j & 1) << 1) + ((j >> 1) << 6);
            float2 v = up2(acc[i][j]);
#pragma unroll
            for (int e = 0; e < 2; e++) {
                int lc = lcb + e;
                int c = bcol + lc;
                int ce = ((j >> 1) << 2) + ((j & 1) << 1) + e;
                float dot = e ? v.y : v.x;
                float d2 = fmaxf(sqr_[i] - 2.f * dot + sqc_[ce], 0.f);
                int bin;
                if (r == c) bin = 255;
                else if (d2 < 6.25f) bin = 0;
                else {
                    float d = sqrtf(d2);
                    bin = 1 + (int)((d - 2.5f) * 2.0f);
                    if (bin > 63) bin = 63;
                    float t = 2.5f + 0.5f * (float)bin;
                    if (!(d2 < t * t)) { bin++; if (bin > 63) bin = 63; }
                    else if (bin > 1) {
                        float tm = t - 0.5f;
                        if (d2 < tm * tm) bin--;
                    }
                }
                sbin[lr][lc] = (unsigned char)bin;
                unsigned msk = __match_any_sync(0xffffffffu, bin);
                int leader = __ffs(msk) - 1;
                if ((int)(tid & 31) == leader && bin < 64)
                    atomicAdd(&shist[bin], (unsigned)__popc(msk) * wgt);
            }
        }
    }
    __syncthreads();
    if (tid < 64 && shist[tid]) atomicAdd(&g_hist[tid], shist[tid]);
    // coalesced writes: normal tile (and mirrored tile if off-diagonal)
    for (int idx = tid; idx < 1024; idx += 256) {
        int row = idx >> 3, cq = (idx & 7) * 16;
        union { unsigned char b[16]; uint4 v; } u;
#pragma unroll
        for (int k = 0; k < 16; k++) u.b[k] = sbin[row][cq + k];
        *(uint4*)&g_bin[(size_t)(brow + row) * NNODE + bcol + cq] = u.v;
    }
    if (bx != by) {
        for (int idx = tid; idx < 1024; idx += 256) {
            int row = idx >> 3, cq = (idx & 7) * 16;
            union { unsigned char b[16]; uint4 v; } u;
#pragma unroll
            for (int k = 0; k < 16; k++) u.b[k] = sbin[cq + k][row];
            *(uint4*)&g_bin[(size_t)(bcol + row) * NNODE + brow + cq] = u.v;
        }
    }
}

// ---------------- pick threshold bin ----------------
__global__ void k_thr() {
    unsigned int cum = 0;
    int k = 0;
    for (k = 0; k < 64; k++) {
        cum += g_hist[k];
        if ((float)cum >= 409.6f) break;
    }
    if (k > 63) k = 63;
    g_kthr = k;
}

// ---------------- adjacency build: 16 bytes/thread, 2 barriers ----------------
__global__ void __launch_bounds__(256) k_adj() {
    int i = blockIdx.x;
    int tid = threadIdx.x, lane = tid & 31, warp = tid >> 5;
    int kthr = g_kthr;
    uint4 v = ((const uint4*)(g_bin + (size_t)i * NNODE))[tid];
    unsigned words[4] = {v.x, v.y, v.z, v.w};
    int cnt = 0;
    unsigned hm = 0;
#pragma unroll
    for (int wq = 0; wq < 4; wq++)
#pragma unroll
        for (int bq = 0; bq < 4; bq++) {
            int bv = (int)((words[wq] >> (bq * 8)) & 0xffu);
            int u = wq * 4 + bq;
            bool h = (bv <= kthr);
            cnt += h ? 1 : 0;
            hm |= (h ? 1u : 0u) << u;
        }
    int sc = cnt;
#pragma unroll
    for (int o = 1; o < 32; o <<= 1) {
        int t2 = __shfl_up_sync(0xffffffffu, sc, o);
        if (lane >= o) sc += t2;
    }
    __shared__ int wtot[8], wbase[8];
    if (lane == 31) wtot[warp] = sc;
    int excl = sc - cnt;
    __syncthreads();
    if (tid == 0) {
        int bse = 0;
        for (int w = 0; w < 8; w++) { wbase[w] = bse; bse += wtot[w]; }
        float d = (float)bse;
        g_deg[i] = bse;
        g_invS[i] = 1.f / fmaxf(d, 1.f);
        g_invC[i] = 1.f / (d + 1.f);
    }
    __syncthreads();
    int pos = wbase[warp] + excl;
    int* out = g_adj + (size_t)i * NNODE;
    int j0 = tid * 16;
#pragma unroll
    for (int u = 0; u < 16; u++)
        if ((hm >> u) & 1u) out[pos++] = j0 + u;
}

// ---------------- sparse AH gather ----------------
__global__ void __launch_bounds__(128) k_gather() {
    int i = blockIdx.x;
    int deg = g_deg[i];
    int f = threadIdx.x * 4;
    const int* adj = g_adj + (size_t)i * NNODE;
    float4 acc = make_float4(0.f, 0.f, 0.f, 0.f);
    for (int e = 0; e < deg; e++) {
        int j = adj[e];
        float4 h = *(const float4*)&g_H[(size_t)j * LP + f];
        acc.x += h.x; acc.y += h.y; acc.z += h.z; acc.w += h.w;
    }
    *(float4*)&g_AH[(size_t)i * LP + f] = acc;
    float s = g_invS[i];
    float4 an = make_float4(acc.x * s, acc.y * s, acc.z * s, acc.w * s);
    *(float4*)&g_AHn[(size_t)i * LP + f] = an;
}

// ---------------- BatchNorm: coalesced partials -> finalize -> apply ----------------
__global__ void k_bnsum() {
    int f = threadIdx.x, b = blockIdx.x;
    float s = 0.f, s2 = 0.f;
    for (int n = b; n < NNODE; n += 64) {
        float v = g_Zp[(size_t)n * LP + f];
        s += v;
        s2 += v * v;
    }
    g_bnp[b * 512 + f] = s;
    g_bnp2[b * 512 + f] = s2;
}
__global__ void k_bnfin() {
    int f = threadIdx.x;
    float s = 0.f, s2 = 0.f;
    for (int b = 0; b < 64; b++) { s += g_bnp[b * 512 + f]; s2 += g_bnp2[b * 512 + f]; }
    float m = s / (float)NNODE;
    float var = fmaxf(s2 / (float)NNODE - m * m, 0.f);
    g_bnm[f] = m;
    g_bni[f] = 1.f / sqrtf(var + 1e-5f);
}
__global__ void k_bnapply(const float* __restrict__ gw, const float* __restrict__ gb) {
    int f = threadIdx.x, b = blockIdx.x;
    if (f >= LL) return;
    float m = g_bnm[f], inv = g_bni[f], gf = gw[f], bf = gb[f];
    for (int n = b; n < NNODE; n += 64) {
        float v = g_Zp[(size_t)n * LP + f];
        g_Zp[(size_t)n * LP + f] = (v - m) * inv * gf + bf;
    }
}

// ---------------- ClusterGCN assignment (register-cached rows) ----------------
__global__ void k_cluster(const float* __restrict__ wout, const float* __restrict__ bout,
                          const float* __restrict__ wroot) {
    int warp = threadIdx.x >> 5, lane = threadIdx.x & 31;
    int i = blockIdx.x * 4 + warp;
    float invc = g_invC[i];
    float hv[16], ag[16];
#pragma unroll
    for (int u = 0; u < 16; u++) {
        int k = lane + 32 * u;
        float h = g_H[(size_t)i * LP + k];        // pads are zero
        float a = g_AH[(size_t)i * LP + k];
        hv[u] = h;
        ag[u] = (a + h) * invc;
    }
    float lg[5];
#pragma unroll
    for (int c = 0; c < 5; c++) {
        float acc = 0.f;
#pragma unroll
        for (int u = 0; u < 16; u++) {
            int k = lane + 32 * u;
            if (k < LL)
                acc += ag[u] * __ldg(&wout[c * LL + k]) + hv[u] * __ldg(&wroot[c * LL + k]);
        }
#pragma unroll
        for (int o = 16; o > 0; o >>= 1) acc += __shfl_down_sync(0xffffffffu, acc, o);
        acc = __shfl_sync(0xffffffffu, acc, 0);
        lg[c] = acc + bout[c];
    }
    if (lane == 0) {
        float m = lg[0];
#pragma unroll
        for (int c = 1; c < 5; c++) m = fmaxf(m, lg[c]);
        float e[5], s = 0.f;
#pragma unroll
        for (int c = 0; c < 5; c++) { e[c] = expf(lg[c] - m); s += e[c]; }
#pragma unroll
        for (int c = 0; c < 5; c++) g_S[(size_t)i * 8 + c] = e[c] / s;
    }
}

// ---------------- T = A @ S via adjacency ----------------
__global__ void __launch_bounds__(256) k_ts() {
    int row = blockIdx.x * 8 + (threadIdx.x >> 5);
    int lane = threadIdx.x & 31;
    int deg = g_deg[row];
    const int* adj = g_adj + (size_t)row * NNODE;
    float a0 = 0.f, a1 = 0.f, a2 = 0.f, a3 = 0.f, a4 = 0.f;
    for (int e = lane; e < deg; e += 32) {
        int j = adj[e];
        const float* s = g_S + (size_t)j * 8;
        a0 += s[0]; a1 += s[1]; a2 += s[2]; a3 += s[3]; a4 += s[4];
    }
#pragma unroll
    for (int o = 16; o > 0; o >>= 1) {
        a0 += __shfl_down_sync(0xffffffffu, a0, o);
        a1 += __shfl_down_sync(0xffffffffu, a1, o);
        a2 += __shfl_down_sync(0xffffffffu, a2, o);
        a3 += __shfl_down_sync(0xffffffffu, a3, o);
        a4 += __shfl_down_sync(0xffffffffu, a4, o);
    }
    if (lane == 0) {
        g_T[(size_t)row * 8 + 0] = a0;
        g_T[(size_t)row * 8 + 1] = a1;
        g_T[(size_t)row * 8 + 2] = a2;
        g_T[(size_t)row * 8 + 3] = a3;
        g_T[(size_t)row * 8 + 4] = a4;
    }
}

// ---------------- coar partials = S^T @ Z over n-chunks ----------------
__global__ void k_coar() {
    int fx = threadIdx.x & 63, ny = threadIdx.x >> 6;
    int f = blockIdx.x * 64 + fx;
    int n0 = blockIdx.y * 512;
    float acc[5] = {0.f, 0.f, 0.f, 0.f, 0.f};
    for (int n = n0 + ny; n < n0 + 512; n += 4) {
        float z = g_Zp[(size_t)n * LP + f];
        const float* s = g_S + (size_t)n * 8;
#pragma unroll
        for (int c = 0; c < 5; c++) acc[c] += s[c] * z;
    }
    __shared__ float red[4][64][5];
#pragma unroll
    for (int c = 0; c < 5; c++) red[ny][fx][c] = acc[c];
    __syncthreads();
    if (ny == 0) {
#pragma unroll
        for (int c = 0; c < 5; c++)
            g_cpart[blockIdx.y][c * 512 + f] =
                red[0][fx][c] + red[1][fx][c] + red[2][fx][c] + red[3][fx][c];
    }
}
__global__ void k_coarfin() {
    int c = blockIdx.x, f = threadIdx.x;
    float s = 0.f;
    for (int b = 0; b < 8; b++) s += g_cpart[b][c * 512 + f];
    g_coar[c * LP + f] = s;
}

// ---------------- Ac = S^T @ T ----------------
__global__ void k_ac() {
    int tid = threadIdx.x, lane = tid & 31, warp = tid >> 5;
    float acc[25];
#pragma unroll
    for (int q = 0; q < 25; q++) acc[q] = 0.f;
    for (int n = tid; n < NNODE; n += 256) {
        float sv[5], tv[5];
#pragma unroll
        for (int c = 0; c < 5; c++) { sv[c] = g_S[(size_t)n * 8 + c]; tv[c] = g_T[(size_t)n * 8 + c]; }
#pragma unroll
        for (int a = 0; a < 5; a++)
#pragma unroll
            for (int b = 0; b < 5; b++) acc[a * 5 + b] += sv[a] * tv[b];
    }
#pragma unroll
    for (int q = 0; q < 25; q++)
#pragma unroll
        for (int o = 16; o > 0; o >>= 1) acc[q] += __shfl_down_sync(0xffffffffu, acc[q], o);
    __shared__ float red[8][25];
    if (lane == 0)
#pragma unroll
        for (int q = 0; q < 25; q++) red[warp][q] = acc[q];
    __syncthreads();
    if (tid < 25) {
        float s = 0.f;
#pragma unroll
        for (int w = 0; w < 8; w++) s += red[w][tid];
        g_Ac[tid] = s;
    }
}

// ---------------- final: coarse SAGE + BN + pool + MLP + softmax ----------------
__global__ void __launch_bounds__(512) k_final(
    const float* __restrict__ wl, const float* __restrict__ bl, const float* __restrict__ wr,
    const float* __restrict__ bng, const float* __restrict__ bnb,
    const float* __restrict__ l1w, const float* __restrict__ l1b,
    const float* __restrict__ l2w, const float* __restrict__ l2b,
    float* __restrict__ out, int out_size) {
    __shared__ float Mc[25];
    __shared__ float invdc[5];
    __shared__ float neigh[5 * 500];
    __shared__ float pre[5 * 500];
    __shared__ float h1[5 * 250];
    __shared__ float lg[5];
    int tid = threadIdx.x;
    if (tid == 0) {
        float mean = 0.f;
        for (int q = 0; q < 25; q++) mean += g_Ac[q];
        mean *= (1.f / 25.f);
        for (int q = 0; q < 25; q++)
            Mc[q] = (g_Ac[q] >= mean && g_Ac[q] > 0.f) ? 1.f : 0.f;
        for (int i = 0; i < 5; i++) {
            float d = 0.f;
            for (int j = 0; j < 5; j++) d += Mc[i * 5 + j];
            invdc[i] = 1.f / fmaxf(d, 1.f);
        }
    }
    __syncthreads();
    for (int idx = tid; idx < 2500; idx += 512) {
        int i = idx / 500, f = idx % 500;
        float a = 0.f;
#pragma unroll
        for (int j = 0; j < 5; j++) a += Mc[i * 5 + j] * g_coar[j * LP + f];
        neigh[idx] = a * invdc[i];
    }
    __syncthreads();
    for (int idx = tid; idx < 2500; idx += 512) {
        int i = idx / 500, f = idx % 500;
        const float* wlr = wl + f * 500;
        const float* wrr = wr + f * 500;
        float a0 = 0.f, a1 = 0.f, a2 = 0.f, a3 = 0.f;
        for (int k = 0; k < 500; k += 4) {
            a0 += neigh[i * 500 + k] * wlr[k] + g_coar[i * LP + k] * wrr[k];
            a1 += neigh[i * 500 + k + 1] * wlr[k + 1] + g_coar[i * LP + k + 1] * wrr[k + 1];
            a2 += neigh[i * 500 + k + 2] * wlr[k + 2] + g_coar[i * LP + k + 2] * wrr[k + 2];
            a3 += neigh[i * 500 + k + 3] * wlr[k + 3] + g_coar[i * LP + k + 3] * wrr[k + 3];
        }
        float acc = bl[f] + ((a0 + a1) + (a2 + a3));
        pre[idx] = (acc >= 0.f) ? acc : 0.01f * acc;
    }
    __syncthreads();
    for (int f = tid; f < 500; f += 512) {
        float m = 0.f;
#pragma unroll
        for (int i = 0; i < 5; i++) m += pre[i * 500 + f];
        m *= 0.2f;
        float v = 0.f;
#pragma unroll
        for (int i = 0; i < 5; i++) { float d = pre[i * 500 + f] - m; v += d * d; }
        v *= 0.2f;
        float sd = sqrtf(v + 1e-5f);
        float gf = bng[f], bf = bnb[f];
#pragma unroll
        for (int i = 0; i < 5; i++)
            pre[i * 500 + f] = (pre[i * 500 + f] - m) / sd * gf + bf;
    }
    __syncthreads();
    for (int idx = tid; idx < 2500; idx += 512) {
        int i = idx / 500, f = idx % 500;
        float mx = -1e30f;
#pragma unroll
        for (int j = 0; j < 5; j++)
            if (Mc[i * 5 + j] > 0.f || j == i) mx = fmaxf(mx, pre[j * 500 + f]);
        neigh[idx] = mx;
    }
    __syncthreads();
    for (int idx = tid; idx < 1250; idx += 512) {
        int i = idx / 250, o = idx % 250;
        const float* w = l1w + o * 500;
        float a0 = 0.f, a1 = 0.f, a2 = 0.f, a3 = 0.f;
        for (int k = 0; k < 500; k += 4) {
            a0 += neigh[i * 500 + k] * w[k];
            a1 += neigh[i * 500 + k + 1] * w[k + 1];
            a2 += neigh[i * 500 + k + 2] * w[k + 2];
            a3 += neigh[i * 500 + k + 3] * w[k + 3];
        }
        float acc = l1b[o] + ((a0 + a1) + (a2 + a3));
        h1[idx] = (acc >= 0.f) ? acc : 0.01f * acc;
    }
    __syncthreads();
    if (tid < 5) {
        float acc = l2b[0];
        for (int k = 0; k < 250; k++) acc += h1[tid * 250 + k] * l2w[k];
        lg[tid] = (acc >= 0.f) ? acc : 0.01f * acc;
    }
    __syncthreads();
    if (tid == 0) {
        float m = lg[0];
        for (int i = 1; i < 5; i++) m = fmaxf(m, lg[i]);
        float e[5], s = 0.f;
        for (int i = 0; i < 5; i++) { e[i] = expf(lg[i] - m); s += e[i]; }
        float p = 0.f;
        for (int i = 0; i < 5; i++) p = fmaxf(p, e[i] / s);
        out[0] = p;
        if (out_size > 1) out[1] = (p >= 0.5f) ? 1.f : 0.f;
    }
}

// ---------------- host launcher ----------------
static float* symaddr(const void* sym) {
    void* p = nullptr;
    cudaGetSymbolAddress(&p, sym);
    return (float*)p;
}

extern "C" void kernel_launch(void* const* d_in, const int* in_sizes, int n_in,
                              void* d_out, int out_size) {
    const float* x    = (const float*)d_in[0];
    const float* c1w  = (const float*)d_in[1];
    const float* c1b  = (const float*)d_in[2];
    const float* c2w  = (const float*)d_in[3];
    const float* c2b  = (const float*)d_in[4];
    const float* fcw  = (const float*)d_in[5];
    const float* fcb  = (const float*)d_in[6];
    const float* swl  = (const float*)d_in[7];
    const float* sbl  = (const float*)d_in[8];
    const float* swr  = (const float*)d_in[9];
    const float* bng  = (const float*)d_in[10];
    const float* bnb  = (const float*)d_in[11];
    const float* cgwo = (const float*)d_in[12];
    const float* cgbo = (const float*)d_in[13];
    const float* cgwr = (const float*)d_in[14];
    const float* l1w  = (const float*)d_in[15];
    const float* l1b  = (const float*)d_in[16];
    const float* l2w  = (const float*)d_in[17];
    const float* l2b  = (const float*)d_in[18];
    float* out = (float*)d_out;

    float* pF   = symaddr(g_F);
    float* pH   = symaddr(g_H);
    float* pAHn = symaddr(g_AHn);
    float* pZp  = symaddr(g_Zp);
    float* pW   = symaddr(g_W);

    const int c2_smem = C2_IMGS * 3840 * (int)sizeof(float);
    cudaFuncSetAttribute(k_conv2, cudaFuncAttributeMaxDynamicSharedMemorySize, c2_smem);

    k_zero<<<1, 64>>>();
    k_packw<<<512, 256>>>(swl, swr);
    k_conv1<<<NNODE, 384>>>(x, c1w, c1b);
    k_conv2<<<(NNODE + C2_IMGS - 1) / C2_IMGS, 512, c2_smem>>>(c2w, c2b);
    {   // fc: H = relu(F @ fcw^T + fcb), split-K 2 (400+400); fused row norms
        dim3 g(4, 32, 2);
        k_gemm_sk<<<g, 256>>>(pF, pF + 400, FEAT, fcw, fcw + 400, FEAT, 400, LL);
        k_comb<<<NNODE, 128>>>(fcb, pH, 1, 1);
    }
    k_gram<<<528, 256>>>();
    k_thr<<<1, 1>>>();
    k_adj<<<NNODE, 256>>>();
    k_gather<<<NNODE, 128>>>();
    {   // SAGE: Zp = leaky(AHn@wl^T + H@wr^T + bl), two slots of packed W
        dim3 g(4, 32, 2);
        k_gemm_sk<<<g, 256>>>(pAHn, pH, LP, pW, pW + 512, 1024, 512, LP);
        k_comb<<<NNODE, 128>>>(sbl, pZp, 2, 0);
    }
    k_bnsum<<<64, 512>>>();
    k_bnfin<<<1, 512>>>();
    k_bnapply<<<64, 512>>>(bng, bnb);
    k_cluster<<<NNODE / 4, 128>>>(cgwo, cgbo, cgwr);
    k_ts<<<NNODE / 8, 256>>>();
    {
        dim3 g(8, 8);
        k_coar<<<g, 256>>>();
        k_coarfin<<<5, 512>>>();
    }
    k_ac<<<1, 256>>>();
    k_final<<<1, 512>>>(swl, sbl, swr, bng, bnb, l1w, l1b, l2w, l2b, out, out_size);
}